// round 1
// baseline (speedup 1.0000x reference)
#include <cuda_runtime.h>
#include <cuda_bf16.h>

#define DIM 1536
#define NHD 12
#define HD  128
#define SL  6400      // query length (100*8*8)
#define LK  3200      // kv length after even-frame subsample (50*64)
#define TPB 256

// ---------------- scratch (static device arrays; no allocs) ----------------
__device__ float g_qraw[SL * DIM];
__device__ float g_kraw[SL * DIM];
__device__ float g_vraw[SL * DIM];
__device__ __nv_bfloat16 g_qb[SL * DIM];
__device__ __nv_bfloat16 g_kb[LK * DIM];
__device__ __nv_bfloat16 g_vb[LK * DIM];
__device__ __nv_bfloat16 g_sc[(size_t)NHD * SL * LK];   // 491.5 MB scores/probs
__device__ float g_ao[SL * DIM];                        // attention output (bf16-rounded values)

// ---------------- fp32 SGEMM: C = A(MxK) @ B(KxN) + bias ----------------
// BM=BN=128, BK=16, 256 threads, 8x8 per thread. All dims divide evenly here.
__global__ void sgemm_f32(const float* __restrict__ A, const float* __restrict__ B,
                          const float* __restrict__ bias, float* __restrict__ C,
                          int M, int N, int K)
{
    __shared__ float As[16][132];
    __shared__ float Bs[16][128];
    const int tid = threadIdx.x;
    const int trow = tid >> 4, tcol = tid & 15;
    const int m0 = blockIdx.y * 128, n0 = blockIdx.x * 128;
    float acc[8][8] = {};

    for (int k0 = 0; k0 < K; k0 += 16) {
#pragma unroll
        for (int i = 0; i < 8; i++) {
            int idx = tid + i * 256;
            int r = idx >> 4, c = idx & 15;
            As[c][r] = A[(size_t)(m0 + r) * K + k0 + c];
            int rb = idx >> 7, cb = idx & 127;
            Bs[rb][cb] = B[(size_t)(k0 + rb) * N + n0 + cb];
        }
        __syncthreads();
#pragma unroll
        for (int kk = 0; kk < 16; kk++) {
            float a[8], b[8];
#pragma unroll
            for (int i = 0; i < 8; i++) a[i] = As[kk][trow * 8 + i];
#pragma unroll
            for (int j = 0; j < 8; j++) b[j] = Bs[kk][tcol * 8 + j];
#pragma unroll
            for (int i = 0; i < 8; i++)
#pragma unroll
                for (int j = 0; j < 8; j++)
                    acc[i][j] += a[i] * b[j];
        }
        __syncthreads();
    }
#pragma unroll
    for (int i = 0; i < 8; i++) {
        int m = m0 + trow * 8 + i;
#pragma unroll
        for (int j = 0; j < 8; j++) {
            int n = n0 + tcol * 8 + j;
            C[(size_t)m * N + n] = acc[i][j] + bias[n];
        }
    }
}

// ---------------- RMSNorm + 3D RoPE + bf16 pack + KV subsample ----------------
__global__ void rmsrope_kernel(const float* __restrict__ gq, const float* __restrict__ gk,
                               const float* __restrict__ freqs)
{
    const int l = blockIdx.x;
    const int tid = threadIdx.x;
    const float* qr = g_qraw + (size_t)l * DIM;
    const float* kr = g_kraw + (size_t)l * DIM;
    const float* vr = g_vraw + (size_t)l * DIM;

    float sq = 0.f, sk = 0.f;
    for (int i = tid; i < DIM; i += TPB) {
        float a = qr[i]; sq += a * a;
        float b = kr[i]; sk += b * b;
    }
    __shared__ float rq[8], rk[8];
#pragma unroll
    for (int off = 16; off; off >>= 1) {
        sq += __shfl_xor_sync(0xffffffffu, sq, off);
        sk += __shfl_xor_sync(0xffffffffu, sk, off);
    }
    if ((tid & 31) == 0) { rq[tid >> 5] = sq; rk[tid >> 5] = sk; }
    __syncthreads();
    if (tid == 0) {
        float tq = 0.f, tk = 0.f;
        for (int i = 0; i < 8; i++) { tq += rq[i]; tk += rk[i]; }
        rq[0] = rsqrtf(tq / DIM + 1e-6f);
        rk[0] = rsqrtf(tk / DIM + 1e-6f);
    }
    __syncthreads();
    const float invq = rq[0], invk = rk[0];

    const int fi = l >> 6;           // frame
    const int rem = l & 63;          // position in frame
    const int hi = rem >> 3, wi = rem & 7;
    const bool keep = (fi & 1) == 0;
    const int kc = (fi >> 1) * 64 + rem;

    // 12 heads x 64 complex pairs = 768 items
    for (int e = tid; e < NHD * 64; e += TPB) {
        const int n = e >> 6;        // head
        const int p = e & 63;        // pair index within head
        float ang;
        if (p < 22)      ang = freqs[fi * 64 + p];
        else if (p < 43) ang = freqs[hi * 64 + p];
        else             ang = freqs[wi * 64 + p];
        float s, c;
        sincosf(ang, &s, &c);
        const int j0 = n * HD + 2 * p;

        float q0 = qr[j0] * invq * gq[j0];
        float q1 = qr[j0 + 1] * invq * gq[j0 + 1];
        g_qb[(size_t)l * DIM + j0]     = __float2bfloat16(q0 * c - q1 * s);
        g_qb[(size_t)l * DIM + j0 + 1] = __float2bfloat16(q0 * s + q1 * c);

        if (keep) {
            float k0v = kr[j0] * invk * gk[j0];
            float k1v = kr[j0 + 1] * invk * gk[j0 + 1];
            g_kb[(size_t)kc * DIM + j0]     = __float2bfloat16(k0v * c - k1v * s);
            g_kb[(size_t)kc * DIM + j0 + 1] = __float2bfloat16(k0v * s + k1v * c);
        }
    }
    if (keep) {
        for (int i = tid; i < DIM; i += TPB)
            g_vb[(size_t)kc * DIM + i] = __float2bfloat16(vr[i]);
    }
}

// ---------------- scores: S[h,m,n] = sum_k Q[m,h,k] * K[n,h,k] (bf16 in, bf16 out) ----------------
__global__ void score_gemm(void)
{
    __shared__ float As[16][132];
    __shared__ float Bs[16][132];
    const int h = blockIdx.z;
    const int m0 = blockIdx.y * 128, n0 = blockIdx.x * 128;
    const int tid = threadIdx.x;
    const int trow = tid >> 4, tcol = tid & 15;
    const __nv_bfloat16* Q  = g_qb + h * HD;
    const __nv_bfloat16* Kb = g_kb + h * HD;
    float acc[8][8] = {};

    for (int k0 = 0; k0 < HD; k0 += 16) {
#pragma unroll
        for (int i = 0; i < 8; i++) {
            int idx = tid + i * 256;
            int r = idx >> 4, c = idx & 15;
            As[c][r] = __bfloat162float(Q [(size_t)(m0 + r) * DIM + k0 + c]);
            Bs[c][r] = __bfloat162float(Kb[(size_t)(n0 + r) * DIM + k0 + c]);
        }
        __syncthreads();
#pragma unroll
        for (int kk = 0; kk < 16; kk++) {
            float a[8], b[8];
#pragma unroll
            for (int i = 0; i < 8; i++) a[i] = As[kk][trow * 8 + i];
#pragma unroll
            for (int j = 0; j < 8; j++) b[j] = Bs[kk][tcol * 8 + j];
#pragma unroll
            for (int i = 0; i < 8; i++)
#pragma unroll
                for (int j = 0; j < 8; j++)
                    acc[i][j] += a[i] * b[j];
        }
        __syncthreads();
    }
    __nv_bfloat16* S = g_sc + (size_t)h * SL * LK;
#pragma unroll
    for (int i = 0; i < 8; i++) {
        int m = m0 + trow * 8 + i;
#pragma unroll
        for (int j = 0; j < 8; j++)
            S[(size_t)m * LK + n0 + tcol * 8 + j] = __float2bfloat16(acc[i][j]); // bf16 rounding like reference einsum
    }
}

// ---------------- softmax over last axis (3200), in-place, probs rounded to bf16 ----------------
__global__ void softmax_kernel(void)
{
    __nv_bfloat16* S = g_sc + (size_t)blockIdx.x * LK;
    const int tid = threadIdx.x;
    const float scale = 0.088388347648318447f; // 1/sqrt(128)

    float v[13];
    int cnt = 0;
    float m = -1e30f;
    for (int i = tid; i < LK; i += TPB) {
        float x = __bfloat162float(S[i]) * scale;
        v[cnt++] = x;
        m = fmaxf(m, x);
    }
    __shared__ float smax[8], ssum[8];
#pragma unroll
    for (int off = 16; off; off >>= 1) m = fmaxf(m, __shfl_xor_sync(0xffffffffu, m, off));
    if ((tid & 31) == 0) smax[tid >> 5] = m;
    __syncthreads();
    if (tid == 0) {
        float t = smax[0];
        for (int i = 1; i < 8; i++) t = fmaxf(t, smax[i]);
        smax[0] = t;
    }
    __syncthreads();
    m = smax[0];

    float z = 0.f;
    for (int c2 = 0; c2 < cnt; c2++) { v[c2] = expf(v[c2] - m); z += v[c2]; }
#pragma unroll
    for (int off = 16; off; off >>= 1) z += __shfl_xor_sync(0xffffffffu, z, off);
    if ((tid & 31) == 0) ssum[tid >> 5] = z;
    __syncthreads();
    if (tid == 0) {
        float t = 0.f;
        for (int i = 0; i < 8; i++) t += ssum[i];
        ssum[0] = t;
    }
    __syncthreads();
    const float inv = 1.f / ssum[0];

    cnt = 0;
    for (int i = tid; i < LK; i += TPB)
        S[i] = __float2bfloat16(v[cnt++] * inv);   // probs rounded to bf16 like reference
}

// ---------------- PV: O[m, h*128+n] = sum_k P[h,m,k] * V[k, h*128+n] ----------------
__global__ void pv_gemm(void)
{
    __shared__ float As[16][132];
    __shared__ float Bs[16][128];
    const int h = blockIdx.z;
    const int m0 = blockIdx.y * 128;   // N=128 exactly one tile
    const int tid = threadIdx.x;
    const int trow = tid >> 4, tcol = tid & 15;
    const __nv_bfloat16* P = g_sc + (size_t)h * SL * LK;
    const __nv_bfloat16* V = g_vb + h * HD;
    float acc[8][8] = {};

    for (int k0 = 0; k0 < LK; k0 += 16) {
#pragma unroll
        for (int i = 0; i < 8; i++) {
            int idx = tid + i * 256;
            int r = idx >> 4, c = idx & 15;
            As[c][r] = __bfloat162float(P[(size_t)(m0 + r) * LK + k0 + c]);
            int rb = idx >> 7, cb = idx & 127;
            Bs[rb][cb] = __bfloat162float(V[(size_t)(k0 + rb) * DIM + cb]);
        }
        __syncthreads();
#pragma unroll
        for (int kk = 0; kk < 16; kk++) {
            float a[8], b[8];
#pragma unroll
            for (int i = 0; i < 8; i++) a[i] = As[kk][trow * 8 + i];
#pragma unroll
            for (int j = 0; j < 8; j++) b[j] = Bs[kk][tcol * 8 + j];
#pragma unroll
            for (int i = 0; i < 8; i++)
#pragma unroll
                for (int j = 0; j < 8; j++)
                    acc[i][j] += a[i] * b[j];
        }
        __syncthreads();
    }
#pragma unroll
    for (int i = 0; i < 8; i++) {
        int m = m0 + trow * 8 + i;
#pragma unroll
        for (int j = 0; j < 8; j++) {
            // reference rounds attention output to bf16 before Wo
            float r = __bfloat162float(__float2bfloat16(acc[i][j]));
            g_ao[(size_t)m * DIM + h * HD + tcol * 8 + j] = r;
        }
    }
}

// ---------------- launch ----------------
extern "C" void kernel_launch(void* const* d_in, const int* in_sizes, int n_in,
                              void* d_out, int out_size)
{
    const float* x     = (const float*)d_in[0];
    const float* freqs = (const float*)d_in[1];
    const float* Wq    = (const float*)d_in[2];
    const float* bq    = (const float*)d_in[3];
    const float* Wk    = (const float*)d_in[4];
    const float* bk    = (const float*)d_in[5];
    const float* Wv    = (const float*)d_in[6];
    const float* bv    = (const float*)d_in[7];
    const float* Wo    = (const float*)d_in[8];
    const float* bo    = (const float*)d_in[9];
    const float* gq    = (const float*)d_in[10];
    const float* gk    = (const float*)d_in[11];
    float* out = (float*)d_out;

    float *qraw, *kraw, *vraw, *ao;
    cudaGetSymbolAddress((void**)&qraw, g_qraw);
    cudaGetSymbolAddress((void**)&kraw, g_kraw);
    cudaGetSymbolAddress((void**)&vraw, g_vraw);
    cudaGetSymbolAddress((void**)&ao,   g_ao);

    dim3 blk(TPB);
    dim3 gProj(DIM / 128, SL / 128);          // (12, 50)
    sgemm_f32<<<gProj, blk>>>(x, Wq, bq, qraw, SL, DIM, DIM);
    sgemm_f32<<<gProj, blk>>>(x, Wk, bk, kraw, SL, DIM, DIM);
    sgemm_f32<<<gProj, blk>>>(x, Wv, bv, vraw, SL, DIM, DIM);

    rmsrope_kernel<<<SL, blk>>>(gq, gk, freqs);

    dim3 gScore(LK / 128, SL / 128, NHD);     // (25, 50, 12)
    score_gemm<<<gScore, blk>>>();

    softmax_kernel<<<NHD * SL, blk>>>();      // 76800 rows

    dim3 gPV(1, SL / 128, NHD);
    pv_gemm<<<gPV, blk>>>();

    sgemm_f32<<<gProj, blk>>>(ao, Wo, bo, out, SL, DIM, DIM);
}

// round 2
// speedup vs baseline: 1.6410x; 1.6410x over previous
#include <cuda_runtime.h>
#include <cuda_bf16.h>

#define DIM 1536
#define NHD 12
#define HD  128
#define SL  6400      // query length (100*8*8)
#define LK  3200      // kv length after even-frame subsample (50*64)
#define TPB 256

// ---------------- scratch (static device arrays; no allocs) ----------------
__device__ float g_qraw[SL * DIM];
__device__ float g_kraw[SL * DIM];
__device__ float g_vraw[SL * DIM];
__device__ __nv_bfloat16 g_qb[SL * DIM];
__device__ __nv_bfloat16 g_kb[LK * DIM];
__device__ __nv_bfloat16 g_vb[LK * DIM];
__device__ __nv_bfloat16 g_sc[(size_t)NHD * SL * LK];   // 491.5 MB scores/probs
__device__ float g_ao[SL * DIM];                        // attention output (bf16-rounded values)

// ---------------- warp-level bf16 MMA helper ----------------
__device__ __forceinline__ void mma_bf16(float* d, const unsigned* a, const unsigned* b)
{
    asm volatile(
        "mma.sync.aligned.m16n8k16.row.col.f32.bf16.bf16.f32 "
        "{%0,%1,%2,%3}, {%4,%5,%6,%7}, {%8,%9}, {%0,%1,%2,%3};\n"
        : "+f"(d[0]), "+f"(d[1]), "+f"(d[2]), "+f"(d[3])
        : "r"(a[0]), "r"(a[1]), "r"(a[2]), "r"(a[3]), "r"(b[0]), "r"(b[1]));
}

// ---------------- fp32 SGEMM: C = A(MxK) @ B(KxN) + bias ----------------
__global__ void sgemm_f32(const float* __restrict__ A, const float* __restrict__ B,
                          const float* __restrict__ bias, float* __restrict__ C,
                          int M, int N, int K)
{
    __shared__ float As[16][132];
    __shared__ float Bs[16][128];
    const int tid = threadIdx.x;
    const int trow = tid >> 4, tcol = tid & 15;
    const int m0 = blockIdx.y * 128, n0 = blockIdx.x * 128;
    float acc[8][8] = {};

    for (int k0 = 0; k0 < K; k0 += 16) {
#pragma unroll
        for (int i = 0; i < 8; i++) {
            int idx = tid + i * 256;
            int r = idx >> 4, c = idx & 15;
            As[c][r] = A[(size_t)(m0 + r) * K + k0 + c];
            int rb = idx >> 7, cb = idx & 127;
            Bs[rb][cb] = B[(size_t)(k0 + rb) * N + n0 + cb];
        }
        __syncthreads();
#pragma unroll
        for (int kk = 0; kk < 16; kk++) {
            float a[8], b[8];
#pragma unroll
            for (int i = 0; i < 8; i++) a[i] = As[kk][trow * 8 + i];
#pragma unroll
            for (int j = 0; j < 8; j++) b[j] = Bs[kk][tcol * 8 + j];
#pragma unroll
            for (int i = 0; i < 8; i++)
#pragma unroll
                for (int j = 0; j < 8; j++)
                    acc[i][j] += a[i] * b[j];
        }
        __syncthreads();
    }
#pragma unroll
    for (int i = 0; i < 8; i++) {
        int m = m0 + trow * 8 + i;
#pragma unroll
        for (int j = 0; j < 8; j++) {
            int n = n0 + tcol * 8 + j;
            C[(size_t)m * N + n] = acc[i][j] + bias[n];
        }
    }
}

// ---------------- RMSNorm + 3D RoPE + bf16 pack + KV subsample ----------------
__global__ void rmsrope_kernel(const float* __restrict__ gq, const float* __restrict__ gk,
                               const float* __restrict__ freqs)
{
    const int l = blockIdx.x;
    const int tid = threadIdx.x;
    const float* qr = g_qraw + (size_t)l * DIM;
    const float* kr = g_kraw + (size_t)l * DIM;
    const float* vr = g_vraw + (size_t)l * DIM;

    float sq = 0.f, sk = 0.f;
    for (int i = tid; i < DIM; i += TPB) {
        float a = qr[i]; sq += a * a;
        float b = kr[i]; sk += b * b;
    }
    __shared__ float rq[8], rk[8];
#pragma unroll
    for (int off = 16; off; off >>= 1) {
        sq += __shfl_xor_sync(0xffffffffu, sq, off);
        sk += __shfl_xor_sync(0xffffffffu, sk, off);
    }
    if ((tid & 31) == 0) { rq[tid >> 5] = sq; rk[tid >> 5] = sk; }
    __syncthreads();
    if (tid == 0) {
        float tq = 0.f, tk = 0.f;
        for (int i = 0; i < 8; i++) { tq += rq[i]; tk += rk[i]; }
        rq[0] = rsqrtf(tq / DIM + 1e-6f);
        rk[0] = rsqrtf(tk / DIM + 1e-6f);
    }
    __syncthreads();
    const float invq = rq[0], invk = rk[0];

    const int fi = l >> 6;           // frame
    const int rem = l & 63;          // position in frame
    const int hi = rem >> 3, wi = rem & 7;
    const bool keep = (fi & 1) == 0;
    const int kc = (fi >> 1) * 64 + rem;

    for (int e = tid; e < NHD * 64; e += TPB) {
        const int n = e >> 6;        // head
        const int p = e & 63;        // pair index within head
        float ang;
        if (p < 22)      ang = freqs[fi * 64 + p];
        else if (p < 43) ang = freqs[hi * 64 + p];
        else             ang = freqs[wi * 64 + p];
        float s, c;
        sincosf(ang, &s, &c);
        const int j0 = n * HD + 2 * p;

        float q0 = qr[j0] * invq * gq[j0];
        float q1 = qr[j0 + 1] * invq * gq[j0 + 1];
        g_qb[(size_t)l * DIM + j0]     = __float2bfloat16(q0 * c - q1 * s);
        g_qb[(size_t)l * DIM + j0 + 1] = __float2bfloat16(q0 * s + q1 * c);

        if (keep) {
            float k0v = kr[j0] * invk * gk[j0];
            float k1v = kr[j0 + 1] * invk * gk[j0 + 1];
            g_kb[(size_t)kc * DIM + j0]     = __float2bfloat16(k0v * c - k1v * s);
            g_kb[(size_t)kc * DIM + j0 + 1] = __float2bfloat16(k0v * s + k1v * c);
        }
    }
    if (keep) {
        for (int i = tid; i < DIM; i += TPB)
            g_vb[(size_t)kc * DIM + i] = __float2bfloat16(vr[i]);
    }
}

// ---------------- scores via HMMA: S[h,m,n] = sum_k Q[m,h,k]*K[n,h,k], bf16 out ----
// block tile 128(m) x 128(n), k-chunks of 64 (2 chunks for HD=128), 8 warps of 32m x 64n
__global__ void __launch_bounds__(256) score_gemm_mma(void)
{
    __shared__ __nv_bfloat16 Qs[128][72];
    __shared__ __nv_bfloat16 Ks[128][72];
    const int h = blockIdx.z;
    const int m0 = blockIdx.y * 128, n0 = blockIdx.x * 128;
    const int tid = threadIdx.x;
    const int warp = tid >> 5, lane = tid & 31;
    const int wm = warp >> 1, wn = warp & 1;
    const int group = lane >> 2, tig = lane & 3;

    const __nv_bfloat16* Q  = g_qb + h * HD;
    const __nv_bfloat16* Kb = g_kb + h * HD;

    float acc[2][8][4] = {};

    for (int k0 = 0; k0 < HD; k0 += 64) {
#pragma unroll
        for (int i = 0; i < 4; i++) {
            int idx = tid + i * 256;
            int r = idx >> 3, c = (idx & 7) * 8;
            *(uint4*)&Qs[r][c] = *(const uint4*)&Q [(size_t)(m0 + r) * DIM + k0 + c];
            *(uint4*)&Ks[r][c] = *(const uint4*)&Kb[(size_t)(n0 + r) * DIM + k0 + c];
        }
        __syncthreads();
#pragma unroll
        for (int kk = 0; kk < 64; kk += 16) {
            unsigned a[2][4], b[8][2];
#pragma unroll
            for (int mt = 0; mt < 2; mt++) {
                const int r = wm * 32 + mt * 16 + group;
                a[mt][0] = *(const unsigned*)&Qs[r][kk + tig * 2];
                a[mt][1] = *(const unsigned*)&Qs[r + 8][kk + tig * 2];
                a[mt][2] = *(const unsigned*)&Qs[r][kk + 8 + tig * 2];
                a[mt][3] = *(const unsigned*)&Qs[r + 8][kk + 8 + tig * 2];
            }
#pragma unroll
            for (int nt = 0; nt < 8; nt++) {
                const int r = wn * 64 + nt * 8 + group;
                b[nt][0] = *(const unsigned*)&Ks[r][kk + tig * 2];
                b[nt][1] = *(const unsigned*)&Ks[r][kk + 8 + tig * 2];
            }
#pragma unroll
            for (int mt = 0; mt < 2; mt++)
#pragma unroll
                for (int nt = 0; nt < 8; nt++)
                    mma_bf16(acc[mt][nt], a[mt], b[nt]);
        }
        __syncthreads();
    }

    __nv_bfloat16* S = g_sc + (size_t)h * SL * LK;
#pragma unroll
    for (int mt = 0; mt < 2; mt++) {
        const int row = m0 + wm * 32 + mt * 16 + group;
#pragma unroll
        for (int nt = 0; nt < 8; nt++) {
            const int col = n0 + wn * 64 + nt * 8 + tig * 2;
            *(__nv_bfloat162*)&S[(size_t)row * LK + col] =
                __floats2bfloat162_rn(acc[mt][nt][0], acc[mt][nt][1]);
            *(__nv_bfloat162*)&S[(size_t)(row + 8) * LK + col] =
                __floats2bfloat162_rn(acc[mt][nt][2], acc[mt][nt][3]);
        }
    }
}

// ---------------- softmax over last axis (3200), in-place, probs rounded to bf16 ----------------
__global__ void softmax_kernel(void)
{
    __nv_bfloat16* S = g_sc + (size_t)blockIdx.x * LK;
    const int tid = threadIdx.x;
    const float scale = 0.088388347648318447f; // 1/sqrt(128)

    float v[13];
    int cnt = 0;
    float m = -1e30f;
    for (int i = tid; i < LK; i += TPB) {
        float x = __bfloat162float(S[i]) * scale;
        v[cnt++] = x;
        m = fmaxf(m, x);
    }
    __shared__ float smax[8], ssum[8];
#pragma unroll
    for (int off = 16; off; off >>= 1) m = fmaxf(m, __shfl_xor_sync(0xffffffffu, m, off));
    if ((tid & 31) == 0) smax[tid >> 5] = m;
    __syncthreads();
    if (tid == 0) {
        float t = smax[0];
        for (int i = 1; i < 8; i++) t = fmaxf(t, smax[i]);
        smax[0] = t;
    }
    __syncthreads();
    m = smax[0];

    float z = 0.f;
    for (int c2 = 0; c2 < cnt; c2++) { v[c2] = expf(v[c2] - m); z += v[c2]; }
#pragma unroll
    for (int off = 16; off; off >>= 1) z += __shfl_xor_sync(0xffffffffu, z, off);
    if ((tid & 31) == 0) ssum[tid >> 5] = z;
    __syncthreads();
    if (tid == 0) {
        float t = 0.f;
        for (int i = 0; i < 8; i++) t += ssum[i];
        ssum[0] = t;
    }
    __syncthreads();
    const float inv = 1.f / ssum[0];

    cnt = 0;
    for (int i = tid; i < LK; i += TPB)
        S[i] = __float2bfloat16(v[cnt++] * inv);
}

// ---------------- PV via HMMA: O[m, h*128+n] = sum_k P[h,m,k] * V[k, h*128+n] ----
// block tile 128(m) x 128(n = full head), k-chunks of 64, 8 warps of 32m x 64n.
// V repacked in smem as uint32 pairs {V[2k+1][n], V[2k][n]} so B frags are 1 LDS.32.
__global__ void __launch_bounds__(256) pv_gemm_mma(void)
{
    __shared__ __nv_bfloat16 Ps[128][72];
    __shared__ unsigned Vp[32][132];          // [k/2][n] packed bf16 pairs
    const int h = blockIdx.z;
    const int m0 = blockIdx.y * 128;
    const int tid = threadIdx.x;
    const int warp = tid >> 5, lane = tid & 31;
    const int wm = warp >> 1, wn = warp & 1;
    const int group = lane >> 2, tig = lane & 3;

    const __nv_bfloat16* P = g_sc + (size_t)h * SL * LK;
    const __nv_bfloat16* V = g_vb + h * HD;

    float acc[2][8][4] = {};

    for (int k0 = 0; k0 < LK; k0 += 64) {
        // load P tile 128 x 64
#pragma unroll
        for (int i = 0; i < 4; i++) {
            int idx = tid + i * 256;
            int r = idx >> 3, c = (idx & 7) * 8;
            *(uint4*)&Ps[r][c] = *(const uint4*)&P[(size_t)(m0 + r) * LK + k0 + c];
        }
        // load + pack V tile: 64 k-rows x 128 n  ->  Vp[32][128]
#pragma unroll
        for (int i = 0; i < 2; i++) {
            int idx = tid + i * 256;
            int kp = idx >> 4, c = (idx & 15) * 8;
            uint4 a4 = *(const uint4*)&V[(size_t)(k0 + 2 * kp) * DIM + c];
            uint4 b4 = *(const uint4*)&V[(size_t)(k0 + 2 * kp + 1) * DIM + c];
            uint4 p0, p1;
            p0.x = __byte_perm(a4.x, b4.x, 0x5410); p0.y = __byte_perm(a4.x, b4.x, 0x7632);
            p0.z = __byte_perm(a4.y, b4.y, 0x5410); p0.w = __byte_perm(a4.y, b4.y, 0x7632);
            p1.x = __byte_perm(a4.z, b4.z, 0x5410); p1.y = __byte_perm(a4.z, b4.z, 0x7632);
            p1.z = __byte_perm(a4.w, b4.w, 0x5410); p1.w = __byte_perm(a4.w, b4.w, 0x7632);
            *(uint4*)&Vp[kp][c]     = p0;
            *(uint4*)&Vp[kp][c + 4] = p1;
        }
        __syncthreads();
#pragma unroll
        for (int kk = 0; kk < 64; kk += 16) {
            unsigned a[2][4], b[8][2];
#pragma unroll
            for (int mt = 0; mt < 2; mt++) {
                const int r = wm * 32 + mt * 16 + group;
                a[mt][0] = *(const unsigned*)&Ps[r][kk + tig * 2];
                a[mt][1] = *(const unsigned*)&Ps[r + 8][kk + tig * 2];
                a[mt][2] = *(const unsigned*)&Ps[r][kk + 8 + tig * 2];
                a[mt][3] = *(const unsigned*)&Ps[r + 8][kk + 8 + tig * 2];
            }
#pragma unroll
            for (int nt = 0; nt < 8; nt++) {
                const int n = wn * 64 + nt * 8 + group;
                b[nt][0] = Vp[kk / 2 + tig][n];
                b[nt][1] = Vp[kk / 2 + 4 + tig][n];
            }
#pragma unroll
            for (int mt = 0; mt < 2; mt++)
#pragma unroll
                for (int nt = 0; nt < 8; nt++)
                    mma_bf16(acc[mt][nt], a[mt], b[nt]);
        }
        __syncthreads();
    }

#pragma unroll
    for (int mt = 0; mt < 2; mt++) {
        const int row = m0 + wm * 32 + mt * 16 + group;
#pragma unroll
        for (int nt = 0; nt < 8; nt++) {
            const int col = h * HD + wn * 64 + nt * 8 + tig * 2;
            // reference rounds attention output to bf16 before Wo
            g_ao[(size_t)row * DIM + col]           = __bfloat162float(__float2bfloat16(acc[mt][nt][0]));
            g_ao[(size_t)row * DIM + col + 1]       = __bfloat162float(__float2bfloat16(acc[mt][nt][1]));
            g_ao[(size_t)(row + 8) * DIM + col]     = __bfloat162float(__float2bfloat16(acc[mt][nt][2]));
            g_ao[(size_t)(row + 8) * DIM + col + 1] = __bfloat162float(__float2bfloat16(acc[mt][nt][3]));
        }
    }
}

// ---------------- launch ----------------
extern "C" void kernel_launch(void* const* d_in, const int* in_sizes, int n_in,
                              void* d_out, int out_size)
{
    const float* x     = (const float*)d_in[0];
    const float* freqs = (const float*)d_in[1];
    const float* Wq    = (const float*)d_in[2];
    const float* bq    = (const float*)d_in[3];
    const float* Wk    = (const float*)d_in[4];
    const float* bk    = (const float*)d_in[5];
    const float* Wv    = (const float*)d_in[6];
    const float* bv    = (const float*)d_in[7];
    const float* Wo    = (const float*)d_in[8];
    const float* bo    = (const float*)d_in[9];
    const float* gq    = (const float*)d_in[10];
    const float* gk    = (const float*)d_in[11];
    float* out = (float*)d_out;

    float *qraw, *kraw, *vraw, *ao;
    cudaGetSymbolAddress((void**)&qraw, g_qraw);
    cudaGetSymbolAddress((void**)&kraw, g_kraw);
    cudaGetSymbolAddress((void**)&vraw, g_vraw);
    cudaGetSymbolAddress((void**)&ao,   g_ao);

    dim3 blk(TPB);
    dim3 gProj(DIM / 128, SL / 128);          // (12, 50)
    sgemm_f32<<<gProj, blk>>>(x, Wq, bq, qraw, SL, DIM, DIM);
    sgemm_f32<<<gProj, blk>>>(x, Wk, bk, kraw, SL, DIM, DIM);
    sgemm_f32<<<gProj, blk>>>(x, Wv, bv, vraw, SL, DIM, DIM);

    rmsrope_kernel<<<SL, blk>>>(gq, gk, freqs);

    dim3 gScore(LK / 128, SL / 128, NHD);     // (25, 50, 12)
    score_gemm_mma<<<gScore, blk>>>();

    softmax_kernel<<<NHD * SL, blk>>>();      // 76800 rows

    dim3 gPV(1, SL / 128, NHD);
    pv_gemm_mma<<<gPV, blk>>>();

    sgemm_f32<<<gProj, blk>>>(ao, Wo, bo, out, SL, DIM, DIM);
}

// round 5
// speedup vs baseline: 2.2713x; 1.3841x over previous
#include <cuda_runtime.h>
#include <cuda_bf16.h>

#define DIM 1536
#define NHD 12
#define HD  128
#define SL  6400      // query length (100*8*8)
#define LK  3200      // kv length after even-frame subsample (50*64)
#define TPB 256

// ---------------- scratch (static device arrays; no allocs) ----------------
__device__ float g_qraw[SL * DIM];
__device__ float g_kraw[SL * DIM];
__device__ float g_vraw[SL * DIM];
__device__ __nv_bfloat16 g_xs[3][SL * DIM];            // x 3-way split
__device__ __nv_bfloat16 g_ws[9][DIM * DIM];           // Wq,Wk,Wv 3-way splits
__device__ __nv_bfloat16 g_wo2[2][DIM * DIM];          // Wo 2-way split
__device__ __nv_bfloat16 g_qb[SL * DIM];
__device__ __nv_bfloat16 g_kb[LK * DIM];
__device__ __nv_bfloat16 g_vb[LK * DIM];
__device__ __nv_bfloat16 g_sc[(size_t)NHD * SL * LK];  // 491.5 MB scores/probs
__device__ __nv_bfloat16 g_aob[SL * DIM];              // attention output, bf16 (exact per reference)

// ---------------- warp-level bf16 MMA helper ----------------
__device__ __forceinline__ void mma_bf16(float* d, const unsigned* a, const unsigned* b)
{
    asm volatile(
        "mma.sync.aligned.m16n8k16.row.col.f32.bf16.bf16.f32 "
        "{%0,%1,%2,%3}, {%4,%5,%6,%7}, {%8,%9}, {%0,%1,%2,%3};\n"
        : "+f"(d[0]), "+f"(d[1]), "+f"(d[2]), "+f"(d[3])
        : "r"(a[0]), "r"(a[1]), "r"(a[2]), "r"(a[3]), "r"(b[0]), "r"(b[1]));
}

// ---------------- split fp32 -> 3 bf16 components ----------------
__global__ void split3_kernel(const float* __restrict__ src,
                              __nv_bfloat16* __restrict__ h0,
                              __nv_bfloat16* __restrict__ h1,
                              __nv_bfloat16* __restrict__ h2, int n)
{
    int i = blockIdx.x * blockDim.x + threadIdx.x;
    if (i < n) {
        float f = src[i];
        __nv_bfloat16 a = __float2bfloat16(f);
        float r = f - __bfloat162float(a);
        __nv_bfloat16 b = __float2bfloat16(r);
        float r2 = r - __bfloat162float(b);
        h0[i] = a; h1[i] = b; h2[i] = __float2bfloat16(r2);
    }
}

__global__ void split2_kernel(const float* __restrict__ src,
                              __nv_bfloat16* __restrict__ h0,
                              __nv_bfloat16* __restrict__ h1, int n)
{
    int i = blockIdx.x * blockDim.x + threadIdx.x;
    if (i < n) {
        float f = src[i];
        __nv_bfloat16 a = __float2bfloat16(f);
        h0[i] = a;
        h1[i] = __float2bfloat16(f - __bfloat162float(a));
    }
}

// ---------------- multi-term split GEMM with RN flush ----------------
// C = sum_{i+j<=TMAX} A_i @ B_j + bias.
// Each k-chunk's terms go into a ZERO-initialized mma accumulator (short RZ
// chain), then are folded into the persistent accumulator with FADD (RN),
// avoiding the tensor-core truncating-accumulation bias over long chains.
// tile 128m x 128n, k-chunk 32, 8 warps of 32m x 64n. Register-prefetch
// pipelining for the global tile loads.
template <int NA, int NB, int TMAX>
__global__ void __launch_bounds__(256) gemm_terms(
    const __nv_bfloat16* __restrict__ A0, const __nv_bfloat16* __restrict__ A1,
    const __nv_bfloat16* __restrict__ A2,
    const __nv_bfloat16* __restrict__ B0, const __nv_bfloat16* __restrict__ B1,
    const __nv_bfloat16* __restrict__ B2,
    const float* __restrict__ bias, float* __restrict__ C, int M, int N, int K)
{
    extern __shared__ char sm_raw[];
    typedef __nv_bfloat16 ARow[40];
    typedef unsigned BRow[132];
    ARow* As = (ARow*)sm_raw;                                   // NA*128 rows
    BRow* Bs = (BRow*)(sm_raw + (size_t)NA * 128 * 40 * 2);     // NB*16 rows

    const int tid = threadIdx.x;
    const int warp = tid >> 5, lane = tid & 31;
    const int wm = warp >> 1, wn = warp & 1;
    const int group = lane >> 2, tig = lane & 3;
    const int m0 = blockIdx.y * 128, n0 = blockIdx.x * 128;

    const __nv_bfloat16* Ap[3] = {A0, A1, A2};
    const __nv_bfloat16* Bp[3] = {B0, B1, B2};

    // load/store index precompute
    const int kpB = tid >> 4;            // 0..15  (k-pair row within 32-k chunk)
    const int cgB = (tid & 15) * 8;      // 0..120 (n column group of 8)

    float acc[2][8][4] = {};
    uint4 pa[NA][2];
    uint4 pb0[NB], pb1[NB];

    // ---- prefetch helpers ----
    auto load_tiles = [&](int k0) {
#pragma unroll
        for (int p = 0; p < NA; p++)
#pragma unroll
            for (int i = 0; i < 2; i++) {
                int idx = tid + i * 256;
                int r = idx >> 2, c = (idx & 3) * 8;
                pa[p][i] = *(const uint4*)&Ap[p][(size_t)(m0 + r) * K + k0 + c];
            }
#pragma unroll
        for (int p = 0; p < NB; p++) {
            pb0[p] = *(const uint4*)&Bp[p][(size_t)(k0 + 2 * kpB) * N + n0 + cgB];
            pb1[p] = *(const uint4*)&Bp[p][(size_t)(k0 + 2 * kpB + 1) * N + n0 + cgB];
        }
    };
    auto store_tiles = [&]() {
#pragma unroll
        for (int p = 0; p < NA; p++)
#pragma unroll
            for (int i = 0; i < 2; i++) {
                int idx = tid + i * 256;
                int r = idx >> 2, c = (idx & 3) * 8;
                *(uint4*)&As[p * 128 + r][c] = pa[p][i];
            }
#pragma unroll
        for (int p = 0; p < NB; p++) {
            uint4 a4 = pb0[p], b4 = pb1[p];
            uint4 q0, q1;
            q0.x = __byte_perm(a4.x, b4.x, 0x5410); q0.y = __byte_perm(a4.x, b4.x, 0x7632);
            q0.z = __byte_perm(a4.y, b4.y, 0x5410); q0.w = __byte_perm(a4.y, b4.y, 0x7632);
            q1.x = __byte_perm(a4.z, b4.z, 0x5410); q1.y = __byte_perm(a4.z, b4.z, 0x7632);
            q1.z = __byte_perm(a4.w, b4.w, 0x5410); q1.w = __byte_perm(a4.w, b4.w, 0x7632);
            *(uint4*)&Bs[p * 16 + kpB][cgB]     = q0;
            *(uint4*)&Bs[p * 16 + kpB][cgB + 4] = q1;
        }
    };

    load_tiles(0);
    store_tiles();
    __syncthreads();

    for (int k0 = 0; k0 < K; k0 += 32) {
        const bool more = (k0 + 32 < K);
        if (more) load_tiles(k0 + 32);   // global loads overlap with compute below

#pragma unroll
        for (int kk = 0; kk < 32; kk += 16) {
            unsigned a[NA][2][4];
#pragma unroll
            for (int p = 0; p < NA; p++)
#pragma unroll
                for (int mt = 0; mt < 2; mt++) {
                    const int r = wm * 32 + mt * 16 + group;
                    a[p][mt][0] = *(const unsigned*)&As[p * 128 + r][kk + tig * 2];
                    a[p][mt][1] = *(const unsigned*)&As[p * 128 + r + 8][kk + tig * 2];
                    a[p][mt][2] = *(const unsigned*)&As[p * 128 + r][kk + 8 + tig * 2];
                    a[p][mt][3] = *(const unsigned*)&As[p * 128 + r + 8][kk + 8 + tig * 2];
                }
#pragma unroll
            for (int nt = 0; nt < 8; nt++) {
                const int n = wn * 64 + nt * 8 + group;
                unsigned b[NB][2];
#pragma unroll
                for (int p = 0; p < NB; p++) {
                    b[p][0] = Bs[p * 16 + kk / 2 + tig][n];
                    b[p][1] = Bs[p * 16 + kk / 2 + 4 + tig][n];
                }
#pragma unroll
                for (int mt = 0; mt < 2; mt++) {
                    float d[4] = {0.f, 0.f, 0.f, 0.f};   // fresh chunk accumulator
#pragma unroll
                    for (int i = 0; i < NA; i++)
#pragma unroll
                        for (int j = 0; j < NB; j++)
                            if (i + j <= TMAX)
                                mma_bf16(d, a[i][mt], b[j]);
                    // RN fold into persistent accumulator
                    acc[mt][nt][0] += d[0];
                    acc[mt][nt][1] += d[1];
                    acc[mt][nt][2] += d[2];
                    acc[mt][nt][3] += d[3];
                }
            }
        }
        __syncthreads();                  // all warps done reading smem
        if (more) {
            store_tiles();
            __syncthreads();
        }
    }

#pragma unroll
    for (int mt = 0; mt < 2; mt++) {
        const int row = m0 + wm * 32 + mt * 16 + group;
#pragma unroll
        for (int nt = 0; nt < 8; nt++) {
            const int col = n0 + wn * 64 + nt * 8 + tig * 2;
            float b0 = bias[col], b1 = bias[col + 1];
            C[(size_t)row * N + col]           = acc[mt][nt][0] + b0;
            C[(size_t)row * N + col + 1]       = acc[mt][nt][1] + b1;
            C[(size_t)(row + 8) * N + col]     = acc[mt][nt][2] + b0;
            C[(size_t)(row + 8) * N + col + 1] = acc[mt][nt][3] + b1;
        }
    }
}

// ---------------- RMSNorm + 3D RoPE + bf16 pack + KV subsample ----------------
__global__ void rmsrope_kernel(const float* __restrict__ gq, const float* __restrict__ gk,
                               const float* __restrict__ freqs)
{
    const int l = blockIdx.x;
    const int tid = threadIdx.x;
    const float* qr = g_qraw + (size_t)l * DIM;
    const float* kr = g_kraw + (size_t)l * DIM;
    const float* vr = g_vraw + (size_t)l * DIM;

    float sq = 0.f, sk = 0.f;
    for (int i = tid; i < DIM; i += TPB) {
        float a = qr[i]; sq += a * a;
        float b = kr[i]; sk += b * b;
    }
    __shared__ float rq[8], rk[8];
#pragma unroll
    for (int off = 16; off; off >>= 1) {
        sq += __shfl_xor_sync(0xffffffffu, sq, off);
        sk += __shfl_xor_sync(0xffffffffu, sk, off);
    }
    if ((tid & 31) == 0) { rq[tid >> 5] = sq; rk[tid >> 5] = sk; }
    __syncthreads();
    if (tid == 0) {
        float tq = 0.f, tk = 0.f;
        for (int i = 0; i < 8; i++) { tq += rq[i]; tk += rk[i]; }
        rq[0] = rsqrtf(tq / DIM + 1e-6f);
        rk[0] = rsqrtf(tk / DIM + 1e-6f);
    }
    __syncthreads();
    const float invq = rq[0], invk = rk[0];

    const int fi = l >> 6;
    const int rem = l & 63;
    const int hi = rem >> 3, wi = rem & 7;
    const bool keep = (fi & 1) == 0;
    const int kc = (fi >> 1) * 64 + rem;

    for (int e = tid; e < NHD * 64; e += TPB) {
        const int n = e >> 6;
        const int p = e & 63;
        float ang;
        if (p < 22)      ang = freqs[fi * 64 + p];
        else if (p < 43) ang = freqs[hi * 64 + p];
        else             ang = freqs[wi * 64 + p];
        float s, c;
        sincosf(ang, &s, &c);
        const int j0 = n * HD + 2 * p;

        float q0 = qr[j0] * invq * gq[j0];
        float q1 = qr[j0 + 1] * invq * gq[j0 + 1];
        g_qb[(size_t)l * DIM + j0]     = __float2bfloat16(q0 * c - q1 * s);
        g_qb[(size_t)l * DIM + j0 + 1] = __float2bfloat16(q0 * s + q1 * c);

        if (keep) {
            float k0v = kr[j0] * invk * gk[j0];
            float k1v = kr[j0 + 1] * invk * gk[j0 + 1];
            g_kb[(size_t)kc * DIM + j0]     = __float2bfloat16(k0v * c - k1v * s);
            g_kb[(size_t)kc * DIM + j0 + 1] = __float2bfloat16(k0v * s + k1v * c);
        }
    }
    if (keep) {
        for (int i = tid; i < DIM; i += TPB)
            g_vb[(size_t)kc * DIM + i] = __float2bfloat16(vr[i]);
    }
}

// ---------------- scores via HMMA ----------------
__global__ void __launch_bounds__(256) score_gemm_mma(void)
{
    __shared__ __nv_bfloat16 Qs[128][72];
    __shared__ __nv_bfloat16 Ks[128][72];
    const int h = blockIdx.z;
    const int m0 = blockIdx.y * 128, n0 = blockIdx.x * 128;
    const int tid = threadIdx.x;
    const int warp = tid >> 5, lane = tid & 31;
    const int wm = warp >> 1, wn = warp & 1;
    const int group = lane >> 2, tig = lane & 3;

    const __nv_bfloat16* Q  = g_qb + h * HD;
    const __nv_bfloat16* Kb = g_kb + h * HD;

    float acc[2][8][4] = {};

    for (int k0 = 0; k0 < HD; k0 += 64) {
#pragma unroll
        for (int i = 0; i < 4; i++) {
            int idx = tid + i * 256;
            int r = idx >> 3, c = (idx & 7) * 8;
            *(uint4*)&Qs[r][c] = *(const uint4*)&Q [(size_t)(m0 + r) * DIM + k0 + c];
            *(uint4*)&Ks[r][c] = *(const uint4*)&Kb[(size_t)(n0 + r) * DIM + k0 + c];
        }
        __syncthreads();
#pragma unroll
        for (int kk = 0; kk < 64; kk += 16) {
            unsigned a[2][4], b[8][2];
#pragma unroll
            for (int mt = 0; mt < 2; mt++) {
                const int r = wm * 32 + mt * 16 + group;
                a[mt][0] = *(const unsigned*)&Qs[r][kk + tig * 2];
                a[mt][1] = *(const unsigned*)&Qs[r + 8][kk + tig * 2];
                a[mt][2] = *(const unsigned*)&Qs[r][kk + 8 + tig * 2];
                a[mt][3] = *(const unsigned*)&Qs[r + 8][kk + 8 + tig * 2];
            }
#pragma unroll
            for (int nt = 0; nt < 8; nt++) {
                const int r = wn * 64 + nt * 8 + group;
                b[nt][0] = *(const unsigned*)&Ks[r][kk + tig * 2];
                b[nt][1] = *(const unsigned*)&Ks[r][kk + 8 + tig * 2];
            }
#pragma unroll
            for (int mt = 0; mt < 2; mt++)
#pragma unroll
                for (int nt = 0; nt < 8; nt++)
                    mma_bf16(acc[mt][nt], a[mt], b[nt]);
        }
        __syncthreads();
    }

    __nv_bfloat16* S = g_sc + (size_t)h * SL * LK;
#pragma unroll
    for (int mt = 0; mt < 2; mt++) {
        const int row = m0 + wm * 32 + mt * 16 + group;
#pragma unroll
        for (int nt = 0; nt < 8; nt++) {
            const int col = n0 + wn * 64 + nt * 8 + tig * 2;
            *(__nv_bfloat162*)&S[(size_t)row * LK + col] =
                __floats2bfloat162_rn(acc[mt][nt][0], acc[mt][nt][1]);
            *(__nv_bfloat162*)&S[(size_t)(row + 8) * LK + col] =
                __floats2bfloat162_rn(acc[mt][nt][2], acc[mt][nt][3]);
        }
    }
}

// ---------------- softmax over last axis (3200), in-place, bf16 probs ----------------
__global__ void softmax_kernel(void)
{
    __nv_bfloat16* S = g_sc + (size_t)blockIdx.x * LK;
    const int tid = threadIdx.x;
    const float scale = 0.088388347648318447f; // 1/sqrt(128)

    float v[13];
    int cnt = 0;
    float m = -1e30f;
    for (int i = tid; i < LK; i += TPB) {
        float x = __bfloat162float(S[i]) * scale;
        v[cnt++] = x;
        m = fmaxf(m, x);
    }
    __shared__ float smax[8], ssum[8];
#pragma unroll
    for (int off = 16; off; off >>= 1) m = fmaxf(m, __shfl_xor_sync(0xffffffffu, m, off));
    if ((tid & 31) == 0) smax[tid >> 5] = m;
    __syncthreads();
    if (tid == 0) {
        float t = smax[0];
        for (int i = 1; i < 8; i++) t = fmaxf(t, smax[i]);
        smax[0] = t;
    }
    __syncthreads();
    m = smax[0];

    float z = 0.f;
    for (int c2 = 0; c2 < cnt; c2++) { v[c2] = expf(v[c2] - m); z += v[c2]; }
#pragma unroll
    for (int off = 16; off; off >>= 1) z += __shfl_xor_sync(0xffffffffu, z, off);
    if ((tid & 31) == 0) ssum[tid >> 5] = z;
    __syncthreads();
    if (tid == 0) {
        float t = 0.f;
        for (int i = 0; i < 8; i++) t += ssum[i];
        ssum[0] = t;
    }
    __syncthreads();
    const float inv = 1.f / ssum[0];

    cnt = 0;
    for (int i = tid; i < LK; i += TPB)
        S[i] = __float2bfloat16(v[cnt++] * inv);
}

// ---------------- PV via HMMA, bf16 output ----------------
__global__ void __launch_bounds__(256) pv_gemm_mma(void)
{
    __shared__ __nv_bfloat16 Ps[128][72];
    __shared__ unsigned Vp[32][132];
    const int h = blockIdx.z;
    const int m0 = blockIdx.y * 128;
    const int tid = threadIdx.x;
    const int warp = tid >> 5, lane = tid & 31;
    const int wm = warp >> 1, wn = warp & 1;
    const int group = lane >> 2, tig = lane & 3;

    const __nv_bfloat16* P = g_sc + (size_t)h * SL * LK;
    const __nv_bfloat16* V = g_vb + h * HD;

    float acc[2][8][4] = {};

    for (int k0 = 0; k0 < LK; k0 += 64) {
#pragma unroll
        for (int i = 0; i < 4; i++) {
            int idx = tid + i * 256;
            int r = idx >> 3, c = (idx & 7) * 8;
            *(uint4*)&Ps[r][c] = *(const uint4*)&P[(size_t)(m0 + r) * LK + k0 + c];
        }
#pragma unroll
        for (int i = 0; i < 2; i++) {
            int idx = tid + i * 256;
            int kp = idx >> 4, c = (idx & 15) * 8;
            uint4 a4 = *(const uint4*)&V[(size_t)(k0 + 2 * kp) * DIM + c];
            uint4 b4 = *(const uint4*)&V[(size_t)(k0 + 2 * kp + 1) * DIM + c];
            uint4 p0, p1;
            p0.x = __byte_perm(a4.x, b4.x, 0x5410); p0.y = __byte_perm(a4.x, b4.x, 0x7632);
            p0.z = __byte_perm(a4.y, b4.y, 0x5410); p0.w = __byte_perm(a4.y, b4.y, 0x7632);
            p1.x = __byte_perm(a4.z, b4.z, 0x5410); p1.y = __byte_perm(a4.z, b4.z, 0x7632);
            p1.z = __byte_perm(a4.w, b4.w, 0x5410); p1.w = __byte_perm(a4.w, b4.w, 0x7632);
            *(uint4*)&Vp[kp][c]     = p0;
            *(uint4*)&Vp[kp][c + 4] = p1;
        }
        __syncthreads();
#pragma unroll
        for (int kk = 0; kk < 64; kk += 16) {
            unsigned a[2][4], b[8][2];
#pragma unroll
            for (int mt = 0; mt < 2; mt++) {
                const int r = wm * 32 + mt * 16 + group;
                a[mt][0] = *(const unsigned*)&Ps[r][kk + tig * 2];
                a[mt][1] = *(const unsigned*)&Ps[r + 8][kk + tig * 2];
                a[mt][2] = *(const unsigned*)&Ps[r][kk + 8 + tig * 2];
                a[mt][3] = *(const unsigned*)&Ps[r + 8][kk + 8 + tig * 2];
            }
#pragma unroll
            for (int nt = 0; nt < 8; nt++) {
                const int n = wn * 64 + nt * 8 + group;
                b[nt][0] = Vp[kk / 2 + tig][n];
                b[nt][1] = Vp[kk / 2 + 4 + tig][n];
            }
#pragma unroll
            for (int mt = 0; mt < 2; mt++)
#pragma unroll
                for (int nt = 0; nt < 8; nt++)
                    mma_bf16(acc[mt][nt], a[mt], b[nt]);
        }
        __syncthreads();
    }

#pragma unroll
    for (int mt = 0; mt < 2; mt++) {
        const int row = m0 + wm * 32 + mt * 16 + group;
#pragma unroll
        for (int nt = 0; nt < 8; nt++) {
            const int col = h * HD + wn * 64 + nt * 8 + tig * 2;
            *(__nv_bfloat162*)&g_aob[(size_t)row * DIM + col] =
                __floats2bfloat162_rn(acc[mt][nt][0], acc[mt][nt][1]);
            *(__nv_bfloat162*)&g_aob[(size_t)(row + 8) * DIM + col] =
                __floats2bfloat162_rn(acc[mt][nt][2], acc[mt][nt][3]);
        }
    }
}

// ---------------- launch ----------------
extern "C" void kernel_launch(void* const* d_in, const int* in_sizes, int n_in,
                              void* d_out, int out_size)
{
    const float* x     = (const float*)d_in[0];
    const float* freqs = (const float*)d_in[1];
    const float* Wq    = (const float*)d_in[2];
    const float* bq    = (const float*)d_in[3];
    const float* Wk    = (const float*)d_in[4];
    const float* bk    = (const float*)d_in[5];
    const float* Wv    = (const float*)d_in[6];
    const float* bv    = (const float*)d_in[7];
    const float* Wo    = (const float*)d_in[8];
    const float* bo    = (const float*)d_in[9];
    const float* gq    = (const float*)d_in[10];
    const float* gk    = (const float*)d_in[11];
    float* out = (float*)d_out;

    float *qraw, *kraw, *vraw;
    __nv_bfloat16 *xs, *ws, *wo2, *aob;
    cudaGetSymbolAddress((void**)&qraw, g_qraw);
    cudaGetSymbolAddress((void**)&kraw, g_kraw);
    cudaGetSymbolAddress((void**)&vraw, g_vraw);
    cudaGetSymbolAddress((void**)&xs,   g_xs);
    cudaGetSymbolAddress((void**)&ws,   g_ws);
    cudaGetSymbolAddress((void**)&wo2,  g_wo2);
    cudaGetSymbolAddress((void**)&aob,  g_aob);

    __nv_bfloat16* xsp[3];
    for (int i = 0; i < 3; i++) xsp[i] = xs + (size_t)i * SL * DIM;
    __nv_bfloat16* wsp[9];
    for (int i = 0; i < 9; i++) wsp[i] = ws + (size_t)i * DIM * DIM;
    __nv_bfloat16* wop[2];
    for (int i = 0; i < 2; i++) wop[i] = wo2 + (size_t)i * DIM * DIM;

    const int SM33 = 3 * 128 * 40 * 2 + 3 * 16 * 132 * 4;  // 56064
    const int SM12 = 1 * 128 * 40 * 2 + 2 * 16 * 132 * 4;  // 27136
    cudaFuncSetAttribute(gemm_terms<3, 3, 2>, cudaFuncAttributeMaxDynamicSharedMemorySize, SM33);
    cudaFuncSetAttribute(gemm_terms<1, 2, 1>, cudaFuncAttributeMaxDynamicSharedMemorySize, SM12);

    dim3 blk(TPB);

    split3_kernel<<<(SL * DIM + TPB - 1) / TPB, blk>>>(x, xsp[0], xsp[1], xsp[2], SL * DIM);
    split3_kernel<<<(DIM * DIM + TPB - 1) / TPB, blk>>>(Wq, wsp[0], wsp[1], wsp[2], DIM * DIM);
    split3_kernel<<<(DIM * DIM + TPB - 1) / TPB, blk>>>(Wk, wsp[3], wsp[4], wsp[5], DIM * DIM);
    split3_kernel<<<(DIM * DIM + TPB - 1) / TPB, blk>>>(Wv, wsp[6], wsp[7], wsp[8], DIM * DIM);
    split2_kernel<<<(DIM * DIM + TPB - 1) / TPB, blk>>>(Wo, wop[0], wop[1], DIM * DIM);

    dim3 gProj(DIM / 128, SL / 128);          // (12, 50)
    gemm_terms<3, 3, 2><<<gProj, blk, SM33>>>(xsp[0], xsp[1], xsp[2], wsp[0], wsp[1], wsp[2],
                                              bq, qraw, SL, DIM, DIM);
    gemm_terms<3, 3, 2><<<gProj, blk, SM33>>>(xsp[0], xsp[1], xsp[2], wsp[3], wsp[4], wsp[5],
                                              bk, kraw, SL, DIM, DIM);
    gemm_terms<3, 3, 2><<<gProj, blk, SM33>>>(xsp[0], xsp[1], xsp[2], wsp[6], wsp[7], wsp[8],
                                              bv, vraw, SL, DIM, DIM);

    rmsrope_kernel<<<SL, blk>>>(gq, gk, freqs);

    dim3 gScore(LK / 128, SL / 128, NHD);     // (25, 50, 12)
    score_gemm_mma<<<gScore, blk>>>();

    softmax_kernel<<<NHD * SL, blk>>>();      // 76800 rows

    dim3 gPV(1, SL / 128, NHD);
    pv_gemm_mma<<<gPV, blk>>>();

    gemm_terms<1, 2, 1><<<gProj, blk, SM12>>>(aob, aob, aob, wop[0], wop[1], wop[1],
                                              bo, out, SL, DIM, DIM);
}

// round 6
// speedup vs baseline: 2.9846x; 1.3140x over previous
#include <cuda_runtime.h>
#include <cuda_bf16.h>
#include <cuda_fp16.h>

#define DIM 1536
#define NHD 12
#define HD  128
#define SL  6400      // query length (100*8*8)
#define LK  3200      // kv length after even-frame subsample (50*64)
#define TPB 256

#define LOSCALE 2048.0f
#define INV_LOSCALE 4.8828125e-4f   // 1/2048

// ---------------- scratch (static device arrays; no allocs) ----------------
__device__ float g_qraw[SL * DIM];
__device__ float g_kraw[SL * DIM];
__device__ float g_vraw[SL * DIM];
__device__ __half g_xh[2][SL * DIM];                   // x fp16 2-split (lo scaled)
__device__ __half g_wh[6][DIM * DIM];                  // Wq,Wk,Wv fp16 2-splits
__device__ __nv_bfloat16 g_wo2[2][DIM * DIM];          // Wo 2-way bf16 split
__device__ __nv_bfloat16 g_qb[SL * DIM];
__device__ __nv_bfloat16 g_kb[LK * DIM];
__device__ __nv_bfloat16 g_vb[LK * DIM];
__device__ __nv_bfloat16 g_sc[(size_t)NHD * SL * LK];  // 491.5 MB scores/probs
__device__ __nv_bfloat16 g_aob[SL * DIM];              // attention output, bf16 (exact per reference)

// ---------------- warp-level MMA helpers ----------------
__device__ __forceinline__ void mma_bf16(float* d, const unsigned* a, const unsigned* b)
{
    asm volatile(
        "mma.sync.aligned.m16n8k16.row.col.f32.bf16.bf16.f32 "
        "{%0,%1,%2,%3}, {%4,%5,%6,%7}, {%8,%9}, {%0,%1,%2,%3};\n"
        : "+f"(d[0]), "+f"(d[1]), "+f"(d[2]), "+f"(d[3])
        : "r"(a[0]), "r"(a[1]), "r"(a[2]), "r"(a[3]), "r"(b[0]), "r"(b[1]));
}

__device__ __forceinline__ void mma_f16(float* d, const unsigned* a, const unsigned* b)
{
    asm volatile(
        "mma.sync.aligned.m16n8k16.row.col.f32.f16.f16.f32 "
        "{%0,%1,%2,%3}, {%4,%5,%6,%7}, {%8,%9}, {%0,%1,%2,%3};\n"
        : "+f"(d[0]), "+f"(d[1]), "+f"(d[2]), "+f"(d[3])
        : "r"(a[0]), "r"(a[1]), "r"(a[2]), "r"(a[3]), "r"(b[0]), "r"(b[1]));
}

// ---------------- splits ----------------
// fp16 2-split with scaled lo (avoids fp16 subnormals for small W entries)
__global__ void split2h_kernel(const float* __restrict__ src,
                               __half* __restrict__ h0,
                               __half* __restrict__ h1, int n)
{
    int i = blockIdx.x * blockDim.x + threadIdx.x;
    if (i < n) {
        float f = src[i];
        __half a = __float2half_rn(f);
        float r = f - __half2float(a);
        h0[i] = a;
        h1[i] = __float2half_rn(r * LOSCALE);
    }
}

__global__ void split2_kernel(const float* __restrict__ src,
                              __nv_bfloat16* __restrict__ h0,
                              __nv_bfloat16* __restrict__ h1, int n)
{
    int i = blockIdx.x * blockDim.x + threadIdx.x;
    if (i < n) {
        float f = src[i];
        __nv_bfloat16 a = __float2bfloat16(f);
        h0[i] = a;
        h1[i] = __float2bfloat16(f - __bfloat162float(a));
    }
}

// ---------------- fp16 3-term split GEMM with RN flush ----------------
// C = (A0 + A1/S) @ (B0 + B1/S) + bias, dropping the A1B1/S^2 term (2^-22).
// Per 16-k step: d0 = A0B0 (fresh), d1 = A0B1 + A1B0 (fresh, scale S),
// acc += d0 + d1/S  (RN adds; RZ chains length<=2).
// tile 128m x 128n, k-chunk 32, 8 warps of 32m x 64n, register-prefetch pipeline.
__global__ void __launch_bounds__(256) gemm_f16_split(
    const __half* __restrict__ A0, const __half* __restrict__ A1,
    const __half* __restrict__ B0, const __half* __restrict__ B1,
    const float* __restrict__ bias, float* __restrict__ C, int M, int N, int K)
{
    __shared__ __half As[2][128][40];
    __shared__ unsigned Bs[2][16][132];   // packed {B[2k][n], B[2k+1][n]}

    const int tid = threadIdx.x;
    const int warp = tid >> 5, lane = tid & 31;
    const int wm = warp >> 1, wn = warp & 1;
    const int group = lane >> 2, tig = lane & 3;
    const int m0 = blockIdx.y * 128, n0 = blockIdx.x * 128;

    const __half* Ap[2] = {A0, A1};
    const __half* Bp[2] = {B0, B1};

    const int kpB = tid >> 4;            // 0..15
    const int cgB = (tid & 15) * 8;      // 0..120

    float acc[2][8][4] = {};
    uint4 pa[2][2];
    uint4 pb0[2], pb1[2];

    auto load_tiles = [&](int k0) {
#pragma unroll
        for (int p = 0; p < 2; p++)
#pragma unroll
            for (int i = 0; i < 2; i++) {
                int idx = tid + i * 256;
                int r = idx >> 2, c = (idx & 3) * 8;
                pa[p][i] = *(const uint4*)&Ap[p][(size_t)(m0 + r) * K + k0 + c];
            }
#pragma unroll
        for (int p = 0; p < 2; p++) {
            pb0[p] = *(const uint4*)&Bp[p][(size_t)(k0 + 2 * kpB) * N + n0 + cgB];
            pb1[p] = *(const uint4*)&Bp[p][(size_t)(k0 + 2 * kpB + 1) * N + n0 + cgB];
        }
    };
    auto store_tiles = [&]() {
#pragma unroll
        for (int p = 0; p < 2; p++)
#pragma unroll
            for (int i = 0; i < 2; i++) {
                int idx = tid + i * 256;
                int r = idx >> 2, c = (idx & 3) * 8;
                *(uint4*)&As[p][r][c] = pa[p][i];
            }
#pragma unroll
        for (int p = 0; p < 2; p++) {
            uint4 a4 = pb0[p], b4 = pb1[p];
            uint4 q0, q1;
            q0.x = __byte_perm(a4.x, b4.x, 0x5410); q0.y = __byte_perm(a4.x, b4.x, 0x7632);
            q0.z = __byte_perm(a4.y, b4.y, 0x5410); q0.w = __byte_perm(a4.y, b4.y, 0x7632);
            q1.x = __byte_perm(a4.z, b4.z, 0x5410); q1.y = __byte_perm(a4.z, b4.z, 0x7632);
            q1.z = __byte_perm(a4.w, b4.w, 0x5410); q1.w = __byte_perm(a4.w, b4.w, 0x7632);
            *(uint4*)&Bs[p][kpB][cgB]     = q0;
            *(uint4*)&Bs[p][kpB][cgB + 4] = q1;
        }
    };

    load_tiles(0);
    store_tiles();
    __syncthreads();

    for (int k0 = 0; k0 < K; k0 += 32) {
        const bool more = (k0 + 32 < K);
        if (more) load_tiles(k0 + 32);

#pragma unroll
        for (int kk = 0; kk < 32; kk += 16) {
            unsigned a[2][2][4];
#pragma unroll
            for (int p = 0; p < 2; p++)
#pragma unroll
                for (int mt = 0; mt < 2; mt++) {
                    const int r = wm * 32 + mt * 16 + group;
                    a[p][mt][0] = *(const unsigned*)&As[p][r][kk + tig * 2];
                    a[p][mt][1] = *(const unsigned*)&As[p][r + 8][kk + tig * 2];
                    a[p][mt][2] = *(const unsigned*)&As[p][r][kk + 8 + tig * 2];
                    a[p][mt][3] = *(const unsigned*)&As[p][r + 8][kk + 8 + tig * 2];
                }
#pragma unroll
            for (int nt = 0; nt < 8; nt++) {
                const int n = wn * 64 + nt * 8 + group;
                unsigned b[2][2];
#pragma unroll
                for (int p = 0; p < 2; p++) {
                    b[p][0] = Bs[p][kk / 2 + tig][n];
                    b[p][1] = Bs[p][kk / 2 + 4 + tig][n];
                }
#pragma unroll
                for (int mt = 0; mt < 2; mt++) {
                    float d0[4] = {0.f, 0.f, 0.f, 0.f};
                    float d1[4] = {0.f, 0.f, 0.f, 0.f};
                    mma_f16(d0, a[0][mt], b[0]);     // hi*hi
                    mma_f16(d1, a[0][mt], b[1]);     // hi*lo_s
                    mma_f16(d1, a[1][mt], b[0]);     // lo_s*hi
#pragma unroll
                    for (int c = 0; c < 4; c++)
                        acc[mt][nt][c] += d0[c] + d1[c] * INV_LOSCALE;
                }
            }
        }
        __syncthreads();
        if (more) {
            store_tiles();
            __syncthreads();
        }
    }

#pragma unroll
    for (int mt = 0; mt < 2; mt++) {
        const int row = m0 + wm * 32 + mt * 16 + group;
#pragma unroll
        for (int nt = 0; nt < 8; nt++) {
            const int col = n0 + wn * 64 + nt * 8 + tig * 2;
            float b0 = bias[col], b1 = bias[col + 1];
            C[(size_t)row * N + col]           = acc[mt][nt][0] + b0;
            C[(size_t)row * N + col + 1]       = acc[mt][nt][1] + b1;
            C[(size_t)(row + 8) * N + col]     = acc[mt][nt][2] + b0;
            C[(size_t)(row + 8) * N + col + 1] = acc[mt][nt][3] + b1;
        }
    }
}

// ---------------- bf16 2-term GEMM for Wo (A exactly bf16) with RN flush ----
__global__ void __launch_bounds__(256) gemm_wo(
    const __nv_bfloat16* __restrict__ A0,
    const __nv_bfloat16* __restrict__ B0, const __nv_bfloat16* __restrict__ B1,
    const float* __restrict__ bias, float* __restrict__ C, int M, int N, int K)
{
    __shared__ __nv_bfloat16 As[128][40];
    __shared__ unsigned Bs[2][16][132];

    const int tid = threadIdx.x;
    const int warp = tid >> 5, lane = tid & 31;
    const int wm = warp >> 1, wn = warp & 1;
    const int group = lane >> 2, tig = lane & 3;
    const int m0 = blockIdx.y * 128, n0 = blockIdx.x * 128;

    const __nv_bfloat16* Bp[2] = {B0, B1};
    const int kpB = tid >> 4;
    const int cgB = (tid & 15) * 8;

    float acc[2][8][4] = {};
    uint4 pa[2];
    uint4 pb0[2], pb1[2];

    auto load_tiles = [&](int k0) {
#pragma unroll
        for (int i = 0; i < 2; i++) {
            int idx = tid + i * 256;
            int r = idx >> 2, c = (idx & 3) * 8;
            pa[i] = *(const uint4*)&A0[(size_t)(m0 + r) * K + k0 + c];
        }
#pragma unroll
        for (int p = 0; p < 2; p++) {
            pb0[p] = *(const uint4*)&Bp[p][(size_t)(k0 + 2 * kpB) * N + n0 + cgB];
            pb1[p] = *(const uint4*)&Bp[p][(size_t)(k0 + 2 * kpB + 1) * N + n0 + cgB];
        }
    };
    auto store_tiles = [&]() {
#pragma unroll
        for (int i = 0; i < 2; i++) {
            int idx = tid + i * 256;
            int r = idx >> 2, c = (idx & 3) * 8;
            *(uint4*)&As[r][c] = pa[i];
        }
#pragma unroll
        for (int p = 0; p < 2; p++) {
            uint4 a4 = pb0[p], b4 = pb1[p];
            uint4 q0, q1;
            q0.x = __byte_perm(a4.x, b4.x, 0x5410); q0.y = __byte_perm(a4.x, b4.x, 0x7632);
            q0.z = __byte_perm(a4.y, b4.y, 0x5410); q0.w = __byte_perm(a4.y, b4.y, 0x7632);
            q1.x = __byte_perm(a4.z, b4.z, 0x5410); q1.y = __byte_perm(a4.z, b4.z, 0x7632);
            q1.z = __byte_perm(a4.w, b4.w, 0x5410); q1.w = __byte_perm(a4.w, b4.w, 0x7632);
            *(uint4*)&Bs[p][kpB][cgB]     = q0;
            *(uint4*)&Bs[p][kpB][cgB + 4] = q1;
        }
    };

    load_tiles(0);
    store_tiles();
    __syncthreads();

    for (int k0 = 0; k0 < K; k0 += 32) {
        const bool more = (k0 + 32 < K);
        if (more) load_tiles(k0 + 32);

#pragma unroll
        for (int kk = 0; kk < 32; kk += 16) {
            unsigned a[2][4];
#pragma unroll
            for (int mt = 0; mt < 2; mt++) {
                const int r = wm * 32 + mt * 16 + group;
                a[mt][0] = *(const unsigned*)&As[r][kk + tig * 2];
                a[mt][1] = *(const unsigned*)&As[r + 8][kk + tig * 2];
                a[mt][2] = *(const unsigned*)&As[r][kk + 8 + tig * 2];
                a[mt][3] = *(const unsigned*)&As[r + 8][kk + 8 + tig * 2];
            }
#pragma unroll
            for (int nt = 0; nt < 8; nt++) {
                const int n = wn * 64 + nt * 8 + group;
                unsigned b[2][2];
#pragma unroll
                for (int p = 0; p < 2; p++) {
                    b[p][0] = Bs[p][kk / 2 + tig][n];
                    b[p][1] = Bs[p][kk / 2 + 4 + tig][n];
                }
#pragma unroll
                for (int mt = 0; mt < 2; mt++) {
                    float d[4] = {0.f, 0.f, 0.f, 0.f};
                    mma_bf16(d, a[mt], b[0]);
                    mma_bf16(d, a[mt], b[1]);
#pragma unroll
                    for (int c = 0; c < 4; c++) acc[mt][nt][c] += d[c];
                }
            }
        }
        __syncthreads();
        if (more) {
            store_tiles();
            __syncthreads();
        }
    }

#pragma unroll
    for (int mt = 0; mt < 2; mt++) {
        const int row = m0 + wm * 32 + mt * 16 + group;
#pragma unroll
        for (int nt = 0; nt < 8; nt++) {
            const int col = n0 + wn * 64 + nt * 8 + tig * 2;
            float b0 = bias[col], b1 = bias[col + 1];
            C[(size_t)row * N + col]           = acc[mt][nt][0] + b0;
            C[(size_t)row * N + col + 1]       = acc[mt][nt][1] + b1;
            C[(size_t)(row + 8) * N + col]     = acc[mt][nt][2] + b0;
            C[(size_t)(row + 8) * N + col + 1] = acc[mt][nt][3] + b1;
        }
    }
}

// ---------------- RMSNorm + 3D RoPE + bf16 pack + KV subsample ----------------
__global__ void rmsrope_kernel(const float* __restrict__ gq, const float* __restrict__ gk,
                               const float* __restrict__ freqs)
{
    const int l = blockIdx.x;
    const int tid = threadIdx.x;
    const float* qr = g_qraw + (size_t)l * DIM;
    const float* kr = g_kraw + (size_t)l * DIM;
    const float* vr = g_vraw + (size_t)l * DIM;

    float sq = 0.f, sk = 0.f;
    for (int i = tid; i < DIM; i += TPB) {
        float a = qr[i]; sq += a * a;
        float b = kr[i]; sk += b * b;
    }
    __shared__ float rq[8], rk[8];
#pragma unroll
    for (int off = 16; off; off >>= 1) {
        sq += __shfl_xor_sync(0xffffffffu, sq, off);
        sk += __shfl_xor_sync(0xffffffffu, sk, off);
    }
    if ((tid & 31) == 0) { rq[tid >> 5] = sq; rk[tid >> 5] = sk; }
    __syncthreads();
    if (tid == 0) {
        float tq = 0.f, tk = 0.f;
        for (int i = 0; i < 8; i++) { tq += rq[i]; tk += rk[i]; }
        rq[0] = rsqrtf(tq / DIM + 1e-6f);
        rk[0] = rsqrtf(tk / DIM + 1e-6f);
    }
    __syncthreads();
    const float invq = rq[0], invk = rk[0];

    const int fi = l >> 6;
    const int rem = l & 63;
    const int hi = rem >> 3, wi = rem & 7;
    const bool keep = (fi & 1) == 0;
    const int kc = (fi >> 1) * 64 + rem;

    for (int e = tid; e < NHD * 64; e += TPB) {
        const int n = e >> 6;
        const int p = e & 63;
        float ang;
        if (p < 22)      ang = freqs[fi * 64 + p];
        else if (p < 43) ang = freqs[hi * 64 + p];
        else             ang = freqs[wi * 64 + p];
        float s, c;
        sincosf(ang, &s, &c);
        const int j0 = n * HD + 2 * p;

        float q0 = qr[j0] * invq * gq[j0];
        float q1 = qr[j0 + 1] * invq * gq[j0 + 1];
        g_qb[(size_t)l * DIM + j0]     = __float2bfloat16(q0 * c - q1 * s);
        g_qb[(size_t)l * DIM + j0 + 1] = __float2bfloat16(q0 * s + q1 * c);

        if (keep) {
            float k0v = kr[j0] * invk * gk[j0];
            float k1v = kr[j0 + 1] * invk * gk[j0 + 1];
            g_kb[(size_t)kc * DIM + j0]     = __float2bfloat16(k0v * c - k1v * s);
            g_kb[(size_t)kc * DIM + j0 + 1] = __float2bfloat16(k0v * s + k1v * c);
        }
    }
    if (keep) {
        for (int i = tid; i < DIM; i += TPB)
            g_vb[(size_t)kc * DIM + i] = __float2bfloat16(vr[i]);
    }
}

// ---------------- scores via HMMA ----------------
__global__ void __launch_bounds__(256) score_gemm_mma(void)
{
    __shared__ __nv_bfloat16 Qs[128][72];
    __shared__ __nv_bfloat16 Ks[128][72];
    const int h = blockIdx.z;
    const int m0 = blockIdx.y * 128, n0 = blockIdx.x * 128;
    const int tid = threadIdx.x;
    const int warp = tid >> 5, lane = tid & 31;
    const int wm = warp >> 1, wn = warp & 1;
    const int group = lane >> 2, tig = lane & 3;

    const __nv_bfloat16* Q  = g_qb + h * HD;
    const __nv_bfloat16* Kb = g_kb + h * HD;

    float acc[2][8][4] = {};

    for (int k0 = 0; k0 < HD; k0 += 64) {
#pragma unroll
        for (int i = 0; i < 4; i++) {
            int idx = tid + i * 256;
            int r = idx >> 3, c = (idx & 7) * 8;
            *(uint4*)&Qs[r][c] = *(const uint4*)&Q [(size_t)(m0 + r) * DIM + k0 + c];
            *(uint4*)&Ks[r][c] = *(const uint4*)&Kb[(size_t)(n0 + r) * DIM + k0 + c];
        }
        __syncthreads();
#pragma unroll
        for (int kk = 0; kk < 64; kk += 16) {
            unsigned a[2][4], b[8][2];
#pragma unroll
            for (int mt = 0; mt < 2; mt++) {
                const int r = wm * 32 + mt * 16 + group;
                a[mt][0] = *(const unsigned*)&Qs[r][kk + tig * 2];
                a[mt][1] = *(const unsigned*)&Qs[r + 8][kk + tig * 2];
                a[mt][2] = *(const unsigned*)&Qs[r][kk + 8 + tig * 2];
                a[mt][3] = *(const unsigned*)&Qs[r + 8][kk + 8 + tig * 2];
            }
#pragma unroll
            for (int nt = 0; nt < 8; nt++) {
                const int r = wn * 64 + nt * 8 + group;
                b[nt][0] = *(const unsigned*)&Ks[r][kk + tig * 2];
                b[nt][1] = *(const unsigned*)&Ks[r][kk + 8 + tig * 2];
            }
#pragma unroll
            for (int mt = 0; mt < 2; mt++)
#pragma unroll
                for (int nt = 0; nt < 8; nt++)
                    mma_bf16(acc[mt][nt], a[mt], b[nt]);
        }
        __syncthreads();
    }

    __nv_bfloat16* S = g_sc + (size_t)h * SL * LK;
#pragma unroll
    for (int mt = 0; mt < 2; mt++) {
        const int row = m0 + wm * 32 + mt * 16 + group;
#pragma unroll
        for (int nt = 0; nt < 8; nt++) {
            const int col = n0 + wn * 64 + nt * 8 + tig * 2;
            *(__nv_bfloat162*)&S[(size_t)row * LK + col] =
                __floats2bfloat162_rn(acc[mt][nt][0], acc[mt][nt][1]);
            *(__nv_bfloat162*)&S[(size_t)(row + 8) * LK + col] =
                __floats2bfloat162_rn(acc[mt][nt][2], acc[mt][nt][3]);
        }
    }
}

// ---------------- softmax over last axis (3200), in-place, bf16 probs ----------------
__global__ void softmax_kernel(void)
{
    __nv_bfloat16* S = g_sc + (size_t)blockIdx.x * LK;
    const int tid = threadIdx.x;
    const float scale = 0.088388347648318447f; // 1/sqrt(128)

    float v[13];
    int cnt = 0;
    float m = -1e30f;
    for (int i = tid; i < LK; i += TPB) {
        float x = __bfloat162float(S[i]) * scale;
        v[cnt++] = x;
        m = fmaxf(m, x);
    }
    __shared__ float smax[8], ssum[8];
#pragma unroll
    for (int off = 16; off; off >>= 1) m = fmaxf(m, __shfl_xor_sync(0xffffffffu, m, off));
    if ((tid & 31) == 0) smax[tid >> 5] = m;
    __syncthreads();
    if (tid == 0) {
        float t = smax[0];
        for (int i = 1; i < 8; i++) t = fmaxf(t, smax[i]);
        smax[0] = t;
    }
    __syncthreads();
    m = smax[0];

    float z = 0.f;
    for (int c2 = 0; c2 < cnt; c2++) { v[c2] = expf(v[c2] - m); z += v[c2]; }
#pragma unroll
    for (int off = 16; off; off >>= 1) z += __shfl_xor_sync(0xffffffffu, z, off);
    if ((tid & 31) == 0) ssum[tid >> 5] = z;
    __syncthreads();
    if (tid == 0) {
        float t = 0.f;
        for (int i = 0; i < 8; i++) t += ssum[i];
        ssum[0] = t;
    }
    __syncthreads();
    const float inv = 1.f / ssum[0];

    cnt = 0;
    for (int i = tid; i < LK; i += TPB)
        S[i] = __float2bfloat16(v[cnt++] * inv);
}

// ---------------- PV via HMMA, bf16 output ----------------
__global__ void __launch_bounds__(256) pv_gemm_mma(void)
{
    __shared__ __nv_bfloat16 Ps[128][72];
    __shared__ unsigned Vp[32][132];
    const int h = blockIdx.z;
    const int m0 = blockIdx.y * 128;
    const int tid = threadIdx.x;
    const int warp = tid >> 5, lane = tid & 31;
    const int wm = warp >> 1, wn = warp & 1;
    const int group = lane >> 2, tig = lane & 3;

    const __nv_bfloat16* P = g_sc + (size_t)h * SL * LK;
    const __nv_bfloat16* V = g_vb + h * HD;

    float acc[2][8][4] = {};

    for (int k0 = 0; k0 < LK; k0 += 64) {
#pragma unroll
        for (int i = 0; i < 4; i++) {
            int idx = tid + i * 256;
            int r = idx >> 3, c = (idx & 7) * 8;
            *(uint4*)&Ps[r][c] = *(const uint4*)&P[(size_t)(m0 + r) * LK + k0 + c];
        }
#pragma unroll
        for (int i = 0; i < 2; i++) {
            int idx = tid + i * 256;
            int kp = idx >> 4, c = (idx & 15) * 8;
            uint4 a4 = *(const uint4*)&V[(size_t)(k0 + 2 * kp) * DIM + c];
            uint4 b4 = *(const uint4*)&V[(size_t)(k0 + 2 * kp + 1) * DIM + c];
            uint4 p0, p1;
            p0.x = __byte_perm(a4.x, b4.x, 0x5410); p0.y = __byte_perm(a4.x, b4.x, 0x7632);
            p0.z = __byte_perm(a4.y, b4.y, 0x5410); p0.w = __byte_perm(a4.y, b4.y, 0x7632);
            p1.x = __byte_perm(a4.z, b4.z, 0x5410); p1.y = __byte_perm(a4.z, b4.z, 0x7632);
            p1.z = __byte_perm(a4.w, b4.w, 0x5410); p1.w = __byte_perm(a4.w, b4.w, 0x7632);
            *(uint4*)&Vp[kp][c]     = p0;
            *(uint4*)&Vp[kp][c + 4] = p1;
        }
        __syncthreads();
#pragma unroll
        for (int kk = 0; kk < 64; kk += 16) {
            unsigned a[2][4], b[8][2];
#pragma unroll
            for (int mt = 0; mt < 2; mt++) {
                const int r = wm * 32 + mt * 16 + group;
                a[mt][0] = *(const unsigned*)&Ps[r][kk + tig * 2];
                a[mt][1] = *(const unsigned*)&Ps[r + 8][kk + tig * 2];
                a[mt][2] = *(const unsigned*)&Ps[r][kk + 8 + tig * 2];
                a[mt][3] = *(const unsigned*)&Ps[r + 8][kk + 8 + tig * 2];
            }
#pragma unroll
            for (int nt = 0; nt < 8; nt++) {
                const int n = wn * 64 + nt * 8 + group;
                b[nt][0] = Vp[kk / 2 + tig][n];
                b[nt][1] = Vp[kk / 2 + 4 + tig][n];
            }
#pragma unroll
            for (int mt = 0; mt < 2; mt++)
#pragma unroll
                for (int nt = 0; nt < 8; nt++)
                    mma_bf16(acc[mt][nt], a[mt], b[nt]);
        }
        __syncthreads();
    }

#pragma unroll
    for (int mt = 0; mt < 2; mt++) {
        const int row = m0 + wm * 32 + mt * 16 + group;
#pragma unroll
        for (int nt = 0; nt < 8; nt++) {
            const int col = h * HD + wn * 64 + nt * 8 + tig * 2;
            *(__nv_bfloat162*)&g_aob[(size_t)row * DIM + col] =
                __floats2bfloat162_rn(acc[mt][nt][0], acc[mt][nt][1]);
            *(__nv_bfloat162*)&g_aob[(size_t)(row + 8) * DIM + col] =
                __floats2bfloat162_rn(acc[mt][nt][2], acc[mt][nt][3]);
        }
    }
}

// ---------------- launch ----------------
extern "C" void kernel_launch(void* const* d_in, const int* in_sizes, int n_in,
                              void* d_out, int out_size)
{
    const float* x     = (const float*)d_in[0];
    const float* freqs = (const float*)d_in[1];
    const float* Wq    = (const float*)d_in[2];
    const float* bq    = (const float*)d_in[3];
    const float* Wk    = (const float*)d_in[4];
    const float* bk    = (const float*)d_in[5];
    const float* Wv    = (const float*)d_in[6];
    const float* bv    = (const float*)d_in[7];
    const float* Wo    = (const float*)d_in[8];
    const float* bo    = (const float*)d_in[9];
    const float* gq    = (const float*)d_in[10];
    const float* gk    = (const float*)d_in[11];
    float* out = (float*)d_out;

    float *qraw, *kraw, *vraw;
    __half *xh, *wh;
    __nv_bfloat16 *wo2, *aob;
    cudaGetSymbolAddress((void**)&qraw, g_qraw);
    cudaGetSymbolAddress((void**)&kraw, g_kraw);
    cudaGetSymbolAddress((void**)&vraw, g_vraw);
    cudaGetSymbolAddress((void**)&xh,   g_xh);
    cudaGetSymbolAddress((void**)&wh,   g_wh);
    cudaGetSymbolAddress((void**)&wo2,  g_wo2);
    cudaGetSymbolAddress((void**)&aob,  g_aob);

    __half* xp[2];
    for (int i = 0; i < 2; i++) xp[i] = xh + (size_t)i * SL * DIM;
    __half* wp[6];
    for (int i = 0; i < 6; i++) wp[i] = wh + (size_t)i * DIM * DIM;
    __nv_bfloat16* wop[2];
    for (int i = 0; i < 2; i++) wop[i] = wo2 + (size_t)i * DIM * DIM;

    dim3 blk(TPB);

    split2h_kernel<<<(SL * DIM + TPB - 1) / TPB, blk>>>(x, xp[0], xp[1], SL * DIM);
    split2h_kernel<<<(DIM * DIM + TPB - 1) / TPB, blk>>>(Wq, wp[0], wp[1], DIM * DIM);
    split2h_kernel<<<(DIM * DIM + TPB - 1) / TPB, blk>>>(Wk, wp[2], wp[3], DIM * DIM);
    split2h_kernel<<<(DIM * DIM + TPB - 1) / TPB, blk>>>(Wv, wp[4], wp[5], DIM * DIM);
    split2_kernel<<<(DIM * DIM + TPB - 1) / TPB, blk>>>(Wo, wop[0], wop[1], DIM * DIM);

    dim3 gProj(DIM / 128, SL / 128);          // (12, 50)
    gemm_f16_split<<<gProj, blk>>>(xp[0], xp[1], wp[0], wp[1], bq, qraw, SL, DIM, DIM);
    gemm_f16_split<<<gProj, blk>>>(xp[0], xp[1], wp[2], wp[3], bk, kraw, SL, DIM, DIM);
    gemm_f16_split<<<gProj, blk>>>(xp[0], xp[1], wp[4], wp[5], bv, vraw, SL, DIM, DIM);

    rmsrope_kernel<<<SL, blk>>>(gq, gk, freqs);

    dim3 gScore(LK / 128, SL / 128, NHD);     // (25, 50, 12)
    score_gemm_mma<<<gScore, blk>>>();

    softmax_kernel<<<NHD * SL, blk>>>();      // 76800 rows

    dim3 gPV(1, SL / 128, NHD);
    pv_gemm_mma<<<gPV, blk>>>();

    gemm_wo<<<gProj, blk>>>(aob, wop[0], wop[1], bo, out, SL, DIM, DIM);
}

// round 7
// speedup vs baseline: 3.1428x; 1.0530x over previous
#include <cuda_runtime.h>
#include <cuda_bf16.h>
#include <cuda_fp16.h>

#define DIM 1536
#define NHD 12
#define HD  128
#define SL  6400      // query length (100*8*8)
#define LK  3200      // kv length after even-frame subsample (50*64)
#define TPB 256

#define LOSCALE 2048.0f
#define INV_LOSCALE 4.8828125e-4f   // 1/2048

// ---------------- scratch (static device arrays; no allocs) ----------------
__device__ float g_qraw[SL * DIM];
__device__ float g_kraw[SL * DIM];
__device__ float g_vraw[SL * DIM];
__device__ __half g_xh[2][SL * DIM];                   // x fp16 2-split (lo scaled)
__device__ unsigned g_whp[6][(DIM / 2) * DIM];         // Wq,Wk,Wv fp16 2-splits, k-pair packed
__device__ unsigned g_wop[2][(DIM / 2) * DIM];         // Wo bf16 2-split, k-pair packed
__device__ __nv_bfloat16 g_qb[SL * DIM];
__device__ __nv_bfloat16 g_kb[LK * DIM];
__device__ __nv_bfloat16 g_vb[LK * DIM];
__device__ __nv_bfloat16 g_sc[(size_t)NHD * SL * LK];  // 491.5 MB scores/probs
__device__ __nv_bfloat16 g_aob[SL * DIM];              // attention output, bf16 (exact per reference)

// ---------------- warp-level MMA helpers ----------------
__device__ __forceinline__ void mma_bf16(float* d, const unsigned* a, const unsigned* b)
{
    asm volatile(
        "mma.sync.aligned.m16n8k16.row.col.f32.bf16.bf16.f32 "
        "{%0,%1,%2,%3}, {%4,%5,%6,%7}, {%8,%9}, {%0,%1,%2,%3};\n"
        : "+f"(d[0]), "+f"(d[1]), "+f"(d[2]), "+f"(d[3])
        : "r"(a[0]), "r"(a[1]), "r"(a[2]), "r"(a[3]), "r"(b[0]), "r"(b[1]));
}

__device__ __forceinline__ void mma_f16(float* d, const unsigned* a, const unsigned* b)
{
    asm volatile(
        "mma.sync.aligned.m16n8k16.row.col.f32.f16.f16.f32 "
        "{%0,%1,%2,%3}, {%4,%5,%6,%7}, {%8,%9}, {%0,%1,%2,%3};\n"
        : "+f"(d[0]), "+f"(d[1]), "+f"(d[2]), "+f"(d[3])
        : "r"(a[0]), "r"(a[1]), "r"(a[2]), "r"(a[3]), "r"(b[0]), "r"(b[1]));
}

__device__ __forceinline__ void cp16(void* dst_smem, const void* src)
{
    unsigned d = (unsigned)__cvta_generic_to_shared(dst_smem);
    asm volatile("cp.async.cg.shared.global [%0], [%1], 16;\n" :: "r"(d), "l"(src));
}
#define CP_COMMIT() asm volatile("cp.async.commit_group;\n")
#define CP_WAIT0()  asm volatile("cp.async.wait_group 0;\n")

// ---------------- splits ----------------
// x: fp16 2-split with scaled lo (A operand, row-major halves)
__global__ void split2h_kernel(const float* __restrict__ src,
                               __half* __restrict__ h0,
                               __half* __restrict__ h1, int n)
{
    int i = blockIdx.x * blockDim.x + threadIdx.x;
    if (i < n) {
        float f = src[i];
        __half a = __float2half_rn(f);
        float r = f - __half2float(a);
        h0[i] = a;
        h1[i] = __float2half_rn(r * LOSCALE);
    }
}

// W: fp16 2-split, directly stored k-pair packed: p[kp*N+n] = {W[2kp][n], W[2kp+1][n]}
__global__ void splitpack_h_kernel(const float* __restrict__ src,
                                   unsigned* __restrict__ p0,
                                   unsigned* __restrict__ p1, int K, int N)
{
    int i = blockIdx.x * blockDim.x + threadIdx.x;
    int total = (K / 2) * N;
    if (i < total) {
        int kp = i / N, n = i - kp * N;
        float f0 = src[(size_t)(2 * kp) * N + n];
        float f1 = src[(size_t)(2 * kp + 1) * N + n];
        __half h0 = __float2half_rn(f0), h1 = __float2half_rn(f1);
        __half l0 = __float2half_rn((f0 - __half2float(h0)) * LOSCALE);
        __half l1 = __float2half_rn((f1 - __half2float(h1)) * LOSCALE);
        __half2 ph = __halves2half2(h0, h1);
        __half2 pl = __halves2half2(l0, l1);
        p0[i] = *(unsigned*)&ph;
        p1[i] = *(unsigned*)&pl;
    }
}

// Wo: bf16 2-split, k-pair packed
__global__ void splitpack_b_kernel(const float* __restrict__ src,
                                   unsigned* __restrict__ p0,
                                   unsigned* __restrict__ p1, int K, int N)
{
    int i = blockIdx.x * blockDim.x + threadIdx.x;
    int total = (K / 2) * N;
    if (i < total) {
        int kp = i / N, n = i - kp * N;
        float f0 = src[(size_t)(2 * kp) * N + n];
        float f1 = src[(size_t)(2 * kp + 1) * N + n];
        __nv_bfloat16 h0 = __float2bfloat16(f0), h1 = __float2bfloat16(f1);
        __nv_bfloat16 l0 = __float2bfloat16(f0 - __bfloat162float(h0));
        __nv_bfloat16 l1 = __float2bfloat16(f1 - __bfloat162float(h1));
        __nv_bfloat162 ph = __halves2bfloat162(h0, h1);
        __nv_bfloat162 pl = __halves2bfloat162(l0, l1);
        p0[i] = *(unsigned*)&ph;
        p1[i] = *(unsigned*)&pl;
    }
}

// ---------------- fp16 3-term split GEMM, cp.async double-buffered ----------------
// C = (A0 + A1/S) @ (B0 + B1/S) + bias, dropping A1B1/S^2 (2^-22).
// Per 16-k step: d0 = A0B0 (fresh), d1 = A0B1 + A1B0 (fresh), acc += d0 + d1/S (RN).
// tile 128m x 128n, k-chunk 32, 8 warps of 32m x 64n.
#define SMF (2*2*128*40*2 + 2*2*16*132*4)   // 74752
__global__ void __launch_bounds__(256) gemm_f16_split(
    const __half* __restrict__ A0, const __half* __restrict__ A1,
    const unsigned* __restrict__ B0p, const unsigned* __restrict__ B1p,
    const float* __restrict__ bias, float* __restrict__ C, int M, int N, int K)
{
    extern __shared__ char sm[];
    typedef __half ATile[2][128][40];      // [part][r][c]
    typedef unsigned BTile[2][16][132];    // [part][kp][n]
    ATile* As = (ATile*)sm;                            // [2 buf]
    BTile* Bs = (BTile*)(sm + 2 * 2 * 128 * 40 * 2);   // [2 buf]

    const int tid = threadIdx.x;
    const int warp = tid >> 5, lane = tid & 31;
    const int wm = warp >> 1, wn = warp & 1;
    const int group = lane >> 2, tig = lane & 3;
    const int m0 = blockIdx.y * 128, n0 = blockIdx.x * 128;

    const __half* Ap[2] = {A0, A1};
    const unsigned* Bp[2] = {B0p, B1p};

    const int rA = tid >> 2;             // 0..63 (+64 second half)
    const int cA = (tid & 3) * 8;
    const int kpB = tid >> 5;            // 0..7 (+8)
    const int nqB = (tid & 31) * 4;

    auto issue = [&](int k0, int buf) {
#pragma unroll
        for (int p = 0; p < 2; p++) {
#pragma unroll
            for (int i = 0; i < 2; i++) {
                int r = rA + i * 64;
                cp16(&As[buf][p][r][cA], &Ap[p][(size_t)(m0 + r) * K + k0 + cA]);
            }
#pragma unroll
            for (int i = 0; i < 2; i++) {
                int kp = kpB + i * 8;
                cp16(&Bs[buf][p][kp][nqB], &Bp[p][(size_t)(k0 / 2 + kp) * N + n0 + nqB]);
            }
        }
    };

    float acc[2][8][4] = {};

    issue(0, 0);
    CP_COMMIT();
    int buf = 0;

    for (int k0 = 0; k0 < K; k0 += 32) {
        CP_WAIT0();
        __syncthreads();
        if (k0 + 32 < K) {
            issue(k0 + 32, buf ^ 1);
            CP_COMMIT();
        }
#pragma unroll
        for (int kk = 0; kk < 32; kk += 16) {
            unsigned a[2][2][4];
#pragma unroll
            for (int p = 0; p < 2; p++)
#pragma unroll
                for (int mt = 0; mt < 2; mt++) {
                    const int r = wm * 32 + mt * 16 + group;
                    a[p][mt][0] = *(const unsigned*)&As[buf][p][r][kk + tig * 2];
                    a[p][mt][1] = *(const unsigned*)&As[buf][p][r + 8][kk + tig * 2];
                    a[p][mt][2] = *(const unsigned*)&As[buf][p][r][kk + 8 + tig * 2];
                    a[p][mt][3] = *(const unsigned*)&As[buf][p][r + 8][kk + 8 + tig * 2];
                }
#pragma unroll
            for (int nt = 0; nt < 8; nt++) {
                const int n = wn * 64 + nt * 8 + group;
                unsigned b[2][2];
#pragma unroll
                for (int p = 0; p < 2; p++) {
                    b[p][0] = Bs[buf][p][kk / 2 + tig][n];
                    b[p][1] = Bs[buf][p][kk / 2 + 4 + tig][n];
                }
#pragma unroll
                for (int mt = 0; mt < 2; mt++) {
                    float d0[4] = {0.f, 0.f, 0.f, 0.f};
                    float d1[4] = {0.f, 0.f, 0.f, 0.f};
                    mma_f16(d0, a[0][mt], b[0]);     // hi*hi
                    mma_f16(d1, a[0][mt], b[1]);     // hi*lo_s
                    mma_f16(d1, a[1][mt], b[0]);     // lo_s*hi
#pragma unroll
                    for (int c = 0; c < 4; c++)
                        acc[mt][nt][c] += d0[c] + d1[c] * INV_LOSCALE;
                }
            }
        }
        buf ^= 1;
    }

#pragma unroll
    for (int mt = 0; mt < 2; mt++) {
        const int row = m0 + wm * 32 + mt * 16 + group;
#pragma unroll
        for (int nt = 0; nt < 8; nt++) {
            const int col = n0 + wn * 64 + nt * 8 + tig * 2;
            float b0 = bias[col], b1 = bias[col + 1];
            C[(size_t)row * N + col]           = acc[mt][nt][0] + b0;
            C[(size_t)row * N + col + 1]       = acc[mt][nt][1] + b1;
            C[(size_t)(row + 8) * N + col]     = acc[mt][nt][2] + b0;
            C[(size_t)(row + 8) * N + col + 1] = acc[mt][nt][3] + b1;
        }
    }
}

// ---------------- bf16 2-term GEMM for Wo, cp.async double-buffered ----------------
#define SMW (2*128*40*2 + 2*2*16*132*4)     // 54272
__global__ void __launch_bounds__(256) gemm_wo(
    const __nv_bfloat16* __restrict__ A0,
    const unsigned* __restrict__ B0p, const unsigned* __restrict__ B1p,
    const float* __restrict__ bias, float* __restrict__ C, int M, int N, int K)
{
    extern __shared__ char sm[];
    typedef __nv_bfloat16 ATile[128][40];
    typedef unsigned BTile[2][16][132];
    ATile* As = (ATile*)sm;                        // [2 buf]
    BTile* Bs = (BTile*)(sm + 2 * 128 * 40 * 2);   // [2 buf]

    const int tid = threadIdx.x;
    const int warp = tid >> 5, lane = tid & 31;
    const int wm = warp >> 1, wn = warp & 1;
    const int group = lane >> 2, tig = lane & 3;
    const int m0 = blockIdx.y * 128, n0 = blockIdx.x * 128;

    const unsigned* Bp[2] = {B0p, B1p};
    const int rA = tid >> 2;
    const int cA = (tid & 3) * 8;
    const int kpB = tid >> 5;
    const int nqB = (tid & 31) * 4;

    auto issue = [&](int k0, int buf) {
#pragma unroll
        for (int i = 0; i < 2; i++) {
            int r = rA + i * 64;
            cp16(&As[buf][r][cA], &A0[(size_t)(m0 + r) * K + k0 + cA]);
        }
#pragma unroll
        for (int p = 0; p < 2; p++)
#pragma unroll
            for (int i = 0; i < 2; i++) {
                int kp = kpB + i * 8;
                cp16(&Bs[buf][p][kp][nqB], &Bp[p][(size_t)(k0 / 2 + kp) * N + n0 + nqB]);
            }
    };

    float acc[2][8][4] = {};
    issue(0, 0);
    CP_COMMIT();
    int buf = 0;

    for (int k0 = 0; k0 < K; k0 += 32) {
        CP_WAIT0();
        __syncthreads();
        if (k0 + 32 < K) {
            issue(k0 + 32, buf ^ 1);
            CP_COMMIT();
        }
#pragma unroll
        for (int kk = 0; kk < 32; kk += 16) {
            unsigned a[2][4];
#pragma unroll
            for (int mt = 0; mt < 2; mt++) {
                const int r = wm * 32 + mt * 16 + group;
                a[mt][0] = *(const unsigned*)&As[buf][r][kk + tig * 2];
                a[mt][1] = *(const unsigned*)&As[buf][r + 8][kk + tig * 2];
                a[mt][2] = *(const unsigned*)&As[buf][r][kk + 8 + tig * 2];
                a[mt][3] = *(const unsigned*)&As[buf][r + 8][kk + 8 + tig * 2];
            }
#pragma unroll
            for (int nt = 0; nt < 8; nt++) {
                const int n = wn * 64 + nt * 8 + group;
                unsigned b[2][2];
#pragma unroll
                for (int p = 0; p < 2; p++) {
                    b[p][0] = Bs[buf][p][kk / 2 + tig][n];
                    b[p][1] = Bs[buf][p][kk / 2 + 4 + tig][n];
                }
#pragma unroll
                for (int mt = 0; mt < 2; mt++) {
                    float d[4] = {0.f, 0.f, 0.f, 0.f};
                    mma_bf16(d, a[mt], b[0]);
                    mma_bf16(d, a[mt], b[1]);
#pragma unroll
                    for (int c = 0; c < 4; c++) acc[mt][nt][c] += d[c];
                }
            }
        }
        buf ^= 1;
    }

#pragma unroll
    for (int mt = 0; mt < 2; mt++) {
        const int row = m0 + wm * 32 + mt * 16 + group;
#pragma unroll
        for (int nt = 0; nt < 8; nt++) {
            const int col = n0 + wn * 64 + nt * 8 + tig * 2;
            float b0 = bias[col], b1 = bias[col + 1];
            C[(size_t)row * N + col]           = acc[mt][nt][0] + b0;
            C[(size_t)row * N + col + 1]       = acc[mt][nt][1] + b1;
            C[(size_t)(row + 8) * N + col]     = acc[mt][nt][2] + b0;
            C[(size_t)(row + 8) * N + col + 1] = acc[mt][nt][3] + b1;
        }
    }
}

// ---------------- RMSNorm + 3D RoPE + bf16 pack + KV subsample ----------------
__global__ void rmsrope_kernel(const float* __restrict__ gq, const float* __restrict__ gk,
                               const float* __restrict__ freqs)
{
    const int l = blockIdx.x;
    const int tid = threadIdx.x;
    const float* qr = g_qraw + (size_t)l * DIM;
    const float* kr = g_kraw + (size_t)l * DIM;
    const float* vr = g_vraw + (size_t)l * DIM;

    float sq = 0.f, sk = 0.f;
    for (int i = tid; i < DIM; i += TPB) {
        float a = qr[i]; sq += a * a;
        float b = kr[i]; sk += b * b;
    }
    __shared__ float rq[8], rk[8];
#pragma unroll
    for (int off = 16; off; off >>= 1) {
        sq += __shfl_xor_sync(0xffffffffu, sq, off);
        sk += __shfl_xor_sync(0xffffffffu, sk, off);
    }
    if ((tid & 31) == 0) { rq[tid >> 5] = sq; rk[tid >> 5] = sk; }
    __syncthreads();
    if (tid == 0) {
        float tq = 0.f, tk = 0.f;
        for (int i = 0; i < 8; i++) { tq += rq[i]; tk += rk[i]; }
        rq[0] = rsqrtf(tq / DIM + 1e-6f);
        rk[0] = rsqrtf(tk / DIM + 1e-6f);
    }
    __syncthreads();
    const float invq = rq[0], invk = rk[0];

    const int fi = l >> 6;
    const int rem = l & 63;
    const int hi = rem >> 3, wi = rem & 7;
    const bool keep = (fi & 1) == 0;
    const int kc = (fi >> 1) * 64 + rem;

    for (int e = tid; e < NHD * 64; e += TPB) {
        const int n = e >> 6;
        const int p = e & 63;
        float ang;
        if (p < 22)      ang = freqs[fi * 64 + p];
        else if (p < 43) ang = freqs[hi * 64 + p];
        else             ang = freqs[wi * 64 + p];
        float s, c;
        sincosf(ang, &s, &c);
        const int j0 = n * HD + 2 * p;

        float q0 = qr[j0] * invq * gq[j0];
        float q1 = qr[j0 + 1] * invq * gq[j0 + 1];
        g_qb[(size_t)l * DIM + j0]     = __float2bfloat16(q0 * c - q1 * s);
        g_qb[(size_t)l * DIM + j0 + 1] = __float2bfloat16(q0 * s + q1 * c);

        if (keep) {
            float k0v = kr[j0] * invk * gk[j0];
            float k1v = kr[j0 + 1] * invk * gk[j0 + 1];
            g_kb[(size_t)kc * DIM + j0]     = __float2bfloat16(k0v * c - k1v * s);
            g_kb[(size_t)kc * DIM + j0 + 1] = __float2bfloat16(k0v * s + k1v * c);
        }
    }
    if (keep) {
        for (int i = tid; i < DIM; i += TPB)
            g_vb[(size_t)kc * DIM + i] = __float2bfloat16(vr[i]);
    }
}

// ---------------- scores via HMMA ----------------
__global__ void __launch_bounds__(256) score_gemm_mma(void)
{
    __shared__ __nv_bfloat16 Qs[128][72];
    __shared__ __nv_bfloat16 Ks[128][72];
    const int h = blockIdx.z;
    const int m0 = blockIdx.y * 128, n0 = blockIdx.x * 128;
    const int tid = threadIdx.x;
    const int warp = tid >> 5, lane = tid & 31;
    const int wm = warp >> 1, wn = warp & 1;
    const int group = lane >> 2, tig = lane & 3;

    const __nv_bfloat16* Q  = g_qb + h * HD;
    const __nv_bfloat16* Kb = g_kb + h * HD;

    float acc[2][8][4] = {};

    for (int k0 = 0; k0 < HD; k0 += 64) {
#pragma unroll
        for (int i = 0; i < 4; i++) {
            int idx = tid + i * 256;
            int r = idx >> 3, c = (idx & 7) * 8;
            *(uint4*)&Qs[r][c] = *(const uint4*)&Q [(size_t)(m0 + r) * DIM + k0 + c];
            *(uint4*)&Ks[r][c] = *(const uint4*)&Kb[(size_t)(n0 + r) * DIM + k0 + c];
        }
        __syncthreads();
#pragma unroll
        for (int kk = 0; kk < 64; kk += 16) {
            unsigned a[2][4], b[8][2];
#pragma unroll
            for (int mt = 0; mt < 2; mt++) {
                const int r = wm * 32 + mt * 16 + group;
                a[mt][0] = *(const unsigned*)&Qs[r][kk + tig * 2];
                a[mt][1] = *(const unsigned*)&Qs[r + 8][kk + tig * 2];
                a[mt][2] = *(const unsigned*)&Qs[r][kk + 8 + tig * 2];
                a[mt][3] = *(const unsigned*)&Qs[r + 8][kk + 8 + tig * 2];
            }
#pragma unroll
            for (int nt = 0; nt < 8; nt++) {
                const int r = wn * 64 + nt * 8 + group;
                b[nt][0] = *(const unsigned*)&Ks[r][kk + tig * 2];
                b[nt][1] = *(const unsigned*)&Ks[r][kk + 8 + tig * 2];
            }
#pragma unroll
            for (int mt = 0; mt < 2; mt++)
#pragma unroll
                for (int nt = 0; nt < 8; nt++)
                    mma_bf16(acc[mt][nt], a[mt], b[nt]);
        }
        __syncthreads();
    }

    __nv_bfloat16* S = g_sc + (size_t)h * SL * LK;
#pragma unroll
    for (int mt = 0; mt < 2; mt++) {
        const int row = m0 + wm * 32 + mt * 16 + group;
#pragma unroll
        for (int nt = 0; nt < 8; nt++) {
            const int col = n0 + wn * 64 + nt * 8 + tig * 2;
            *(__nv_bfloat162*)&S[(size_t)row * LK + col] =
                __floats2bfloat162_rn(acc[mt][nt][0], acc[mt][nt][1]);
            *(__nv_bfloat162*)&S[(size_t)(row + 8) * LK + col] =
                __floats2bfloat162_rn(acc[mt][nt][2], acc[mt][nt][3]);
        }
    }
}

// ---------------- softmax, vectorized uint4 (8 bf16 per transaction) ----------------
__global__ void __launch_bounds__(256) softmax_kernel(void)
{
    uint4* S4 = (uint4*)(g_sc + (size_t)blockIdx.x * LK);   // 400 uint4 per row
    const int tid = threadIdx.x;
    const float scale = 0.088388347648318447f; // 1/sqrt(128)

    float v[16];
    int cnt = 0;
    float m = -1e30f;
    for (int i = tid; i < LK / 8; i += TPB) {
        uint4 r = S4[i];
        unsigned w[4] = {r.x, r.y, r.z, r.w};
#pragma unroll
        for (int j = 0; j < 4; j++) {
            float2 f = __bfloat1622float2(*(__nv_bfloat162*)&w[j]);
            float f0 = f.x * scale, f1 = f.y * scale;
            v[cnt++] = f0; v[cnt++] = f1;
            m = fmaxf(m, fmaxf(f0, f1));
        }
    }
    __shared__ float smax[8], ssum[8];
#pragma unroll
    for (int off = 16; off; off >>= 1) m = fmaxf(m, __shfl_xor_sync(0xffffffffu, m, off));
    if ((tid & 31) == 0) smax[tid >> 5] = m;
    __syncthreads();
    if (tid == 0) {
        float t = smax[0];
        for (int i = 1; i < 8; i++) t = fmaxf(t, smax[i]);
        smax[0] = t;
    }
    __syncthreads();
    m = smax[0];

    float z = 0.f;
    for (int c = 0; c < cnt; c++) { v[c] = expf(v[c] - m); z += v[c]; }
#pragma unroll
    for (int off = 16; off; off >>= 1) z += __shfl_xor_sync(0xffffffffu, z, off);
    if ((tid & 31) == 0) ssum[tid >> 5] = z;
    __syncthreads();
    if (tid == 0) {
        float t = 0.f;
        for (int i = 0; i < 8; i++) t += ssum[i];
        ssum[0] = t;
    }
    __syncthreads();
    const float inv = 1.f / ssum[0];

    cnt = 0;
    for (int i = tid; i < LK / 8; i += TPB) {
        uint4 o;
        unsigned* ow = &o.x;
#pragma unroll
        for (int j = 0; j < 4; j++) {
            __nv_bfloat162 b2 = __floats2bfloat162_rn(v[cnt] * inv, v[cnt + 1] * inv);
            ow[j] = *(unsigned*)&b2;
            cnt += 2;
        }
        S4[i] = o;
    }
}

// ---------------- PV via HMMA, bf16 output ----------------
__global__ void __launch_bounds__(256) pv_gemm_mma(void)
{
    __shared__ __nv_bfloat16 Ps[128][72];
    __shared__ unsigned Vp[32][132];
    const int h = blockIdx.z;
    const int m0 = blockIdx.y * 128;
    const int tid = threadIdx.x;
    const int warp = tid >> 5, lane = tid & 31;
    const int wm = warp >> 1, wn = warp & 1;
    const int group = lane >> 2, tig = lane & 3;

    const __nv_bfloat16* P = g_sc + (size_t)h * SL * LK;
    const __nv_bfloat16* V = g_vb + h * HD;

    float acc[2][8][4] = {};

    for (int k0 = 0; k0 < LK; k0 += 64) {
#pragma unroll
        for (int i = 0; i < 4; i++) {
            int idx = tid + i * 256;
            int r = idx >> 3, c = (idx & 7) * 8;
            *(uint4*)&Ps[r][c] = *(const uint4*)&P[(size_t)(m0 + r) * LK + k0 + c];
        }
#pragma unroll
        for (int i = 0; i < 2; i++) {
            int idx = tid + i * 256;
            int kp = idx >> 4, c = (idx & 15) * 8;
            uint4 a4 = *(const uint4*)&V[(size_t)(k0 + 2 * kp) * DIM + c];
            uint4 b4 = *(const uint4*)&V[(size_t)(k0 + 2 * kp + 1) * DIM + c];
            uint4 p0, p1;
            p0.x = __byte_perm(a4.x, b4.x, 0x5410); p0.y = __byte_perm(a4.x, b4.x, 0x7632);
            p0.z = __byte_perm(a4.y, b4.y, 0x5410); p0.w = __byte_perm(a4.y, b4.y, 0x7632);
            p1.x = __byte_perm(a4.z, b4.z, 0x5410); p1.y = __byte_perm(a4.z, b4.z, 0x7632);
            p1.z = __byte_perm(a4.w, b4.w, 0x5410); p1.w = __byte_perm(a4.w, b4.w, 0x7632);
            *(uint4*)&Vp[kp][c]     = p0;
            *(uint4*)&Vp[kp][c + 4] = p1;
        }
        __syncthreads();
#pragma unroll
        for (int kk = 0; kk < 64; kk += 16) {
            unsigned a[2][4], b[8][2];
#pragma unroll
            for (int mt = 0; mt < 2; mt++) {
                const int r = wm * 32 + mt * 16 + group;
                a[mt][0] = *(const unsigned*)&Ps[r][kk + tig * 2];
                a[mt][1] = *(const unsigned*)&Ps[r + 8][kk + tig * 2];
                a[mt][2] = *(const unsigned*)&Ps[r][kk + 8 + tig * 2];
                a[mt][3] = *(const unsigned*)&Ps[r + 8][kk + 8 + tig * 2];
            }
#pragma unroll
            for (int nt = 0; nt < 8; nt++) {
                const int n = wn * 64 + nt * 8 + group;
                b[nt][0] = Vp[kk / 2 + tig][n];
                b[nt][1] = Vp[kk / 2 + 4 + tig][n];
            }
#pragma unroll
            for (int mt = 0; mt < 2; mt++)
#pragma unroll
                for (int nt = 0; nt < 8; nt++)
                    mma_bf16(acc[mt][nt], a[mt], b[nt]);
        }
        __syncthreads();
    }

#pragma unroll
    for (int mt = 0; mt < 2; mt++) {
        const int row = m0 + wm * 32 + mt * 16 + group;
#pragma unroll
        for (int nt = 0; nt < 8; nt++) {
            const int col = h * HD + wn * 64 + nt * 8 + tig * 2;
            *(__nv_bfloat162*)&g_aob[(size_t)row * DIM + col] =
                __floats2bfloat162_rn(acc[mt][nt][0], acc[mt][nt][1]);
            *(__nv_bfloat162*)&g_aob[(size_t)(row + 8) * DIM + col] =
                __floats2bfloat162_rn(acc[mt][nt][2], acc[mt][nt][3]);
        }
    }
}

// ---------------- launch ----------------
extern "C" void kernel_launch(void* const* d_in, const int* in_sizes, int n_in,
                              void* d_out, int out_size)
{
    const float* x     = (const float*)d_in[0];
    const float* freqs = (const float*)d_in[1];
    const float* Wq    = (const float*)d_in[2];
    const float* bq    = (const float*)d_in[3];
    const float* Wk    = (const float*)d_in[4];
    const float* bk    = (const float*)d_in[5];
    const float* Wv    = (const float*)d_in[6];
    const float* bv    = (const float*)d_in[7];
    const float* Wo    = (const float*)d_in[8];
    const float* bo    = (const float*)d_in[9];
    const float* gq    = (const float*)d_in[10];
    const float* gk    = (const float*)d_in[11];
    float* out = (float*)d_out;

    float *qraw, *kraw, *vraw;
    __half *xh;
    unsigned *whp, *wop;
    __nv_bfloat16 *aob;
    cudaGetSymbolAddress((void**)&qraw, g_qraw);
    cudaGetSymbolAddress((void**)&kraw, g_kraw);
    cudaGetSymbolAddress((void**)&vraw, g_vraw);
    cudaGetSymbolAddress((void**)&xh,   g_xh);
    cudaGetSymbolAddress((void**)&whp,  g_whp);
    cudaGetSymbolAddress((void**)&wop,  g_wop);
    cudaGetSymbolAddress((void**)&aob,  g_aob);

    const size_t WPS = (size_t)(DIM / 2) * DIM;   // packed words per split part
    __half* xp[2];
    for (int i = 0; i < 2; i++) xp[i] = xh + (size_t)i * SL * DIM;
    unsigned* wp[6];
    for (int i = 0; i < 6; i++) wp[i] = whp + (size_t)i * WPS;
    unsigned* wo[2];
    for (int i = 0; i < 2; i++) wo[i] = wop + (size_t)i * WPS;

    cudaFuncSetAttribute(gemm_f16_split, cudaFuncAttributeMaxDynamicSharedMemorySize, SMF);
    cudaFuncSetAttribute(gemm_wo, cudaFuncAttributeMaxDynamicSharedMemorySize, SMW);

    dim3 blk(TPB);
    const int nw = (DIM / 2) * DIM;               // packed elements per W

    split2h_kernel<<<(SL * DIM + TPB - 1) / TPB, blk>>>(x, xp[0], xp[1], SL * DIM);
    splitpack_h_kernel<<<(nw + TPB - 1) / TPB, blk>>>(Wq, wp[0], wp[1], DIM, DIM);
    splitpack_h_kernel<<<(nw + TPB - 1) / TPB, blk>>>(Wk, wp[2], wp[3], DIM, DIM);
    splitpack_h_kernel<<<(nw + TPB - 1) / TPB, blk>>>(Wv, wp[4], wp[5], DIM, DIM);
    splitpack_b_kernel<<<(nw + TPB - 1) / TPB, blk>>>(Wo, wo[0], wo[1], DIM, DIM);

    dim3 gProj(DIM / 128, SL / 128);          // (12, 50)
    gemm_f16_split<<<gProj, blk, SMF>>>(xp[0], xp[1], wp[0], wp[1], bq, qraw, SL, DIM, DIM);
    gemm_f16_split<<<gProj, blk, SMF>>>(xp[0], xp[1], wp[2], wp[3], bk, kraw, SL, DIM, DIM);
    gemm_f16_split<<<gProj, blk, SMF>>>(xp[0], xp[1], wp[4], wp[5], bv, vraw, SL, DIM, DIM);

    rmsrope_kernel<<<SL, blk>>>(gq, gk, freqs);

    dim3 gScore(LK / 128, SL / 128, NHD);     // (25, 50, 12)
    score_gemm_mma<<<gScore, blk>>>();

    softmax_kernel<<<NHD * SL, blk>>>();      // 76800 rows

    dim3 gPV(1, SL / 128, NHD);
    pv_gemm_mma<<<gPV, blk>>>();

    gemm_wo<<<gProj, blk, SMW>>>(aob, wo[0], wo[1], bo, out, SL, DIM, DIM);
}

// round 8
// speedup vs baseline: 3.4020x; 1.0825x over previous
#include <cuda_runtime.h>
#include <cuda_bf16.h>
#include <cuda_fp16.h>

#define DIM 1536
#define NHD 12
#define HD  128
#define SL  6400      // query length (100*8*8)
#define LK  3200      // kv length after even-frame subsample (50*64)
#define TPB 256

#define LOSCALE 2048.0f
#define INV_LOSCALE 4.8828125e-4f   // 1/2048

// ---------------- scratch (static device arrays; no allocs) ----------------
__device__ float g_qraw[SL * DIM];
__device__ float g_kraw[SL * DIM];
__device__ float g_vraw[SL * DIM];
__device__ __half g_xh[2][SL * DIM];                   // x fp16 2-split (lo scaled)
__device__ unsigned g_whp[6][(DIM / 2) * DIM];         // Wq,Wk,Wv fp16 2-splits, k-pair packed
__device__ unsigned g_wop[2][(DIM / 2) * DIM];         // Wo bf16 2-split, k-pair packed
__device__ __nv_bfloat16 g_qb[SL * DIM];
__device__ __nv_bfloat16 g_kb[LK * DIM];
__device__ __nv_bfloat16 g_vb[LK * DIM];
__device__ __nv_bfloat16 g_sc[(size_t)NHD * SL * LK];  // 491.5 MB scores/probs
__device__ __nv_bfloat16 g_aob[SL * DIM];              // attention output, bf16 (exact per reference)

// ---------------- warp-level MMA helpers ----------------
__device__ __forceinline__ void mma_bf16(float* d, const unsigned* a, const unsigned* b)
{
    asm volatile(
        "mma.sync.aligned.m16n8k16.row.col.f32.bf16.bf16.f32 "
        "{%0,%1,%2,%3}, {%4,%5,%6,%7}, {%8,%9}, {%0,%1,%2,%3};\n"
        : "+f"(d[0]), "+f"(d[1]), "+f"(d[2]), "+f"(d[3])
        : "r"(a[0]), "r"(a[1]), "r"(a[2]), "r"(a[3]), "r"(b[0]), "r"(b[1]));
}

__device__ __forceinline__ void mma_f16(float* d, const unsigned* a, const unsigned* b)
{
    asm volatile(
        "mma.sync.aligned.m16n8k16.row.col.f32.f16.f16.f32 "
        "{%0,%1,%2,%3}, {%4,%5,%6,%7}, {%8,%9}, {%0,%1,%2,%3};\n"
        : "+f"(d[0]), "+f"(d[1]), "+f"(d[2]), "+f"(d[3])
        : "r"(a[0]), "r"(a[1]), "r"(a[2]), "r"(a[3]), "r"(b[0]), "r"(b[1]));
}

__device__ __forceinline__ void ldsm_x4(unsigned* a, const void* p)
{
    unsigned addr = (unsigned)__cvta_generic_to_shared(p);
    asm volatile("ldmatrix.sync.aligned.m8n8.x4.shared.b16 {%0,%1,%2,%3}, [%4];"
                 : "=r"(a[0]), "=r"(a[1]), "=r"(a[2]), "=r"(a[3]) : "r"(addr));
}

__device__ __forceinline__ void cp16(void* dst_smem, const void* src)
{
    unsigned d = (unsigned)__cvta_generic_to_shared(dst_smem);
    asm volatile("cp.async.cg.shared.global [%0], [%1], 16;\n" :: "r"(d), "l"(src));
}
#define CP_COMMIT() asm volatile("cp.async.commit_group;\n")
#define CP_WAIT0()  asm volatile("cp.async.wait_group 0;\n")

// ---------------- splits ----------------
__global__ void split2h_kernel(const float* __restrict__ src,
                               __half* __restrict__ h0,
                               __half* __restrict__ h1, int n)
{
    int i = blockIdx.x * blockDim.x + threadIdx.x;
    if (i < n) {
        float f = src[i];
        __half a = __float2half_rn(f);
        float r = f - __half2float(a);
        h0[i] = a;
        h1[i] = __float2half_rn(r * LOSCALE);
    }
}

__global__ void splitpack_h_kernel(const float* __restrict__ src,
                                   unsigned* __restrict__ p0,
                                   unsigned* __restrict__ p1, int K, int N)
{
    int i = blockIdx.x * blockDim.x + threadIdx.x;
    int total = (K / 2) * N;
    if (i < total) {
        int kp = i / N, n = i - kp * N;
        float f0 = src[(size_t)(2 * kp) * N + n];
        float f1 = src[(size_t)(2 * kp + 1) * N + n];
        __half h0 = __float2half_rn(f0), h1 = __float2half_rn(f1);
        __half l0 = __float2half_rn((f0 - __half2float(h0)) * LOSCALE);
        __half l1 = __float2half_rn((f1 - __half2float(h1)) * LOSCALE);
        __half2 ph = __halves2half2(h0, h1);
        __half2 pl = __halves2half2(l0, l1);
        p0[i] = *(unsigned*)&ph;
        p1[i] = *(unsigned*)&pl;
    }
}

__global__ void splitpack_b_kernel(const float* __restrict__ src,
                                   unsigned* __restrict__ p0,
                                   unsigned* __restrict__ p1, int K, int N)
{
    int i = blockIdx.x * blockDim.x + threadIdx.x;
    int total = (K / 2) * N;
    if (i < total) {
        int kp = i / N, n = i - kp * N;
        float f0 = src[(size_t)(2 * kp) * N + n];
        float f1 = src[(size_t)(2 * kp + 1) * N + n];
        __nv_bfloat16 h0 = __float2bfloat16(f0), h1 = __float2bfloat16(f1);
        __nv_bfloat16 l0 = __float2bfloat16(f0 - __bfloat162float(h0));
        __nv_bfloat16 l1 = __float2bfloat16(f1 - __bfloat162float(h1));
        __nv_bfloat162 ph = __halves2bfloat162(h0, h1);
        __nv_bfloat162 pl = __halves2bfloat162(l0, l1);
        p0[i] = *(unsigned*)&ph;
        p1[i] = *(unsigned*)&pl;
    }
}

// ---------------- fp16 3-term split GEMM, cp.async + ldmatrix + chunk-fold ----------
// C = (A0 + A1/S) @ (B0 + B1/S) + bias, dropping A1B1/S^2 (2^-22).
// Per 32-k chunk: d0 = A0B0 (RZ chain 2), d1 = A0B1 + A1B0 (RZ chain 4),
// acc += d0 + d1/S (RN). tile 128m x 128n, 8 warps of 32m x 64n.
#define SMF (2*2*128*40*2 + 2*2*16*132*4)   // 74752
__global__ void __launch_bounds__(256) gemm_f16_split(
    const __half* __restrict__ A0, const __half* __restrict__ A1,
    const unsigned* __restrict__ B0p, const unsigned* __restrict__ B1p,
    const float* __restrict__ bias, float* __restrict__ C, int M, int N, int K)
{
    extern __shared__ char sm[];
    typedef __half ATile[2][128][40];      // [part][r][c]
    typedef unsigned BTile[2][16][132];    // [part][kp][n]
    ATile* As = (ATile*)sm;                            // [2 buf]
    BTile* Bs = (BTile*)(sm + 2 * 2 * 128 * 40 * 2);   // [2 buf]

    const int tid = threadIdx.x;
    const int warp = tid >> 5, lane = tid & 31;
    const int wm = warp >> 1, wn = warp & 1;
    const int group = lane >> 2, tig = lane & 3;
    const int m0 = blockIdx.y * 128, n0 = blockIdx.x * 128;

    // ldmatrix per-lane source offsets (matrix id = lane>>3)
    const int lrow = (lane & 7) + ((lane >> 3) & 1) * 8;
    const int lcol = (lane >> 4) * 8;

    const __half* Ap[2] = {A0, A1};
    const unsigned* Bp[2] = {B0p, B1p};

    const int rA = tid >> 2;             // 0..63 (+64 second half)
    const int cA = (tid & 3) * 8;
    const int kpB = tid >> 5;            // 0..7 (+8)
    const int nqB = (tid & 31) * 4;

    auto issue = [&](int k0, int buf) {
#pragma unroll
        for (int p = 0; p < 2; p++) {
#pragma unroll
            for (int i = 0; i < 2; i++) {
                int r = rA + i * 64;
                cp16(&As[buf][p][r][cA], &Ap[p][(size_t)(m0 + r) * K + k0 + cA]);
            }
#pragma unroll
            for (int i = 0; i < 2; i++) {
                int kp = kpB + i * 8;
                cp16(&Bs[buf][p][kp][nqB], &Bp[p][(size_t)(k0 / 2 + kp) * N + n0 + nqB]);
            }
        }
    };

    float acc[2][8][4] = {};

    issue(0, 0);
    CP_COMMIT();
    int buf = 0;

    for (int k0 = 0; k0 < K; k0 += 32) {
        CP_WAIT0();
        __syncthreads();
        if (k0 + 32 < K) {
            issue(k0 + 32, buf ^ 1);
            CP_COMMIT();
        }

        // load all A fragments for this chunk via ldmatrix (both 16-k steps)
        unsigned a[2][2][2][4];   // [part][mt][kk2]
#pragma unroll
        for (int p = 0; p < 2; p++)
#pragma unroll
            for (int mt = 0; mt < 2; mt++)
#pragma unroll
                for (int kk2 = 0; kk2 < 2; kk2++)
                    ldsm_x4(a[p][mt][kk2],
                            &As[buf][p][wm * 32 + mt * 16 + lrow][kk2 * 16 + lcol]);

#pragma unroll
        for (int nt = 0; nt < 8; nt++) {
            const int n = wn * 64 + nt * 8 + group;
            float d0[2][4] = {};
            float d1[2][4] = {};
#pragma unroll
            for (int kk2 = 0; kk2 < 2; kk2++) {
                unsigned b0[2], b1[2];
                b0[0] = Bs[buf][0][kk2 * 8 + tig][n];
                b0[1] = Bs[buf][0][kk2 * 8 + 4 + tig][n];
                b1[0] = Bs[buf][1][kk2 * 8 + tig][n];
                b1[1] = Bs[buf][1][kk2 * 8 + 4 + tig][n];
#pragma unroll
                for (int mt = 0; mt < 2; mt++) {
                    mma_f16(d0[mt], a[0][mt][kk2], b0);   // hi*hi
                    mma_f16(d1[mt], a[0][mt][kk2], b1);   // hi*lo_s
                    mma_f16(d1[mt], a[1][mt][kk2], b0);   // lo_s*hi
                }
            }
#pragma unroll
            for (int mt = 0; mt < 2; mt++)
#pragma unroll
                for (int c = 0; c < 4; c++)
                    acc[mt][nt][c] += d0[mt][c] + d1[mt][c] * INV_LOSCALE;
        }
        buf ^= 1;
    }

#pragma unroll
    for (int mt = 0; mt < 2; mt++) {
        const int row = m0 + wm * 32 + mt * 16 + group;
#pragma unroll
        for (int nt = 0; nt < 8; nt++) {
            const int col = n0 + wn * 64 + nt * 8 + tig * 2;
            float b0 = bias[col], b1 = bias[col + 1];
            C[(size_t)row * N + col]           = acc[mt][nt][0] + b0;
            C[(size_t)row * N + col + 1]       = acc[mt][nt][1] + b1;
            C[(size_t)(row + 8) * N + col]     = acc[mt][nt][2] + b0;
            C[(size_t)(row + 8) * N + col + 1] = acc[mt][nt][3] + b1;
        }
    }
}

// ---------------- bf16 2-term GEMM for Wo, cp.async + ldmatrix + chunk-fold ----------
#define SMW (2*128*40*2 + 2*2*16*132*4)     // 54272
__global__ void __launch_bounds__(256) gemm_wo(
    const __nv_bfloat16* __restrict__ A0,
    const unsigned* __restrict__ B0p, const unsigned* __restrict__ B1p,
    const float* __restrict__ bias, float* __restrict__ C, int M, int N, int K)
{
    extern __shared__ char sm[];
    typedef __nv_bfloat16 ATile[128][40];
    typedef unsigned BTile[2][16][132];
    ATile* As = (ATile*)sm;                        // [2 buf]
    BTile* Bs = (BTile*)(sm + 2 * 128 * 40 * 2);   // [2 buf]

    const int tid = threadIdx.x;
    const int warp = tid >> 5, lane = tid & 31;
    const int wm = warp >> 1, wn = warp & 1;
    const int group = lane >> 2, tig = lane & 3;
    const int m0 = blockIdx.y * 128, n0 = blockIdx.x * 128;

    const int lrow = (lane & 7) + ((lane >> 3) & 1) * 8;
    const int lcol = (lane >> 4) * 8;

    const unsigned* Bp[2] = {B0p, B1p};
    const int rA = tid >> 2;
    const int cA = (tid & 3) * 8;
    const int kpB = tid >> 5;
    const int nqB = (tid & 31) * 4;

    auto issue = [&](int k0, int buf) {
#pragma unroll
        for (int i = 0; i < 2; i++) {
            int r = rA + i * 64;
            cp16(&As[buf][r][cA], &A0[(size_t)(m0 + r) * K + k0 + cA]);
        }
#pragma unroll
        for (int p = 0; p < 2; p++)
#pragma unroll
            for (int i = 0; i < 2; i++) {
                int kp = kpB + i * 8;
                cp16(&Bs[buf][p][kp][nqB], &Bp[p][(size_t)(k0 / 2 + kp) * N + n0 + nqB]);
            }
    };

    float acc[2][8][4] = {};
    issue(0, 0);
    CP_COMMIT();
    int buf = 0;

    for (int k0 = 0; k0 < K; k0 += 32) {
        CP_WAIT0();
        __syncthreads();
        if (k0 + 32 < K) {
            issue(k0 + 32, buf ^ 1);
            CP_COMMIT();
        }

        unsigned a[2][2][4];   // [mt][kk2]
#pragma unroll
        for (int mt = 0; mt < 2; mt++)
#pragma unroll
            for (int kk2 = 0; kk2 < 2; kk2++)
                ldsm_x4(a[mt][kk2], &As[buf][wm * 32 + mt * 16 + lrow][kk2 * 16 + lcol]);

#pragma unroll
        for (int nt = 0; nt < 8; nt++) {
            const int n = wn * 64 + nt * 8 + group;
            float d[2][4] = {};
#pragma unroll
            for (int kk2 = 0; kk2 < 2; kk2++) {
                unsigned b0[2], b1[2];
                b0[0] = Bs[buf][0][kk2 * 8 + tig][n];
                b0[1] = Bs[buf][0][kk2 * 8 + 4 + tig][n];
                b1[0] = Bs[buf][1][kk2 * 8 + tig][n];
                b1[1] = Bs[buf][1][kk2 * 8 + 4 + tig][n];
#pragma unroll
                for (int mt = 0; mt < 2; mt++) {
                    mma_bf16(d[mt], a[mt][kk2], b0);
                    mma_bf16(d[mt], a[mt][kk2], b1);
                }
            }
#pragma unroll
            for (int mt = 0; mt < 2; mt++)
#pragma unroll
                for (int c = 0; c < 4; c++)
                    acc[mt][nt][c] += d[mt][c];
        }
        buf ^= 1;
    }

#pragma unroll
    for (int mt = 0; mt < 2; mt++) {
        const int row = m0 + wm * 32 + mt * 16 + group;
#pragma unroll
        for (int nt = 0; nt < 8; nt++) {
            const int col = n0 + wn * 64 + nt * 8 + tig * 2;
            float b0 = bias[col], b1 = bias[col + 1];
            C[(size_t)row * N + col]           = acc[mt][nt][0] + b0;
            C[(size_t)row * N + col + 1]       = acc[mt][nt][1] + b1;
            C[(size_t)(row + 8) * N + col]     = acc[mt][nt][2] + b0;
            C[(size_t)(row + 8) * N + col + 1] = acc[mt][nt][3] + b1;
        }
    }
}

// ---------------- RMSNorm + 3D RoPE + bf16 pack + KV subsample ----------------
__global__ void rmsrope_kernel(const float* __restrict__ gq, const float* __restrict__ gk,
                               const float* __restrict__ freqs)
{
    const int l = blockIdx.x;
    const int tid = threadIdx.x;
    const float* qr = g_qraw + (size_t)l * DIM;
    const float* kr = g_kraw + (size_t)l * DIM;
    const float* vr = g_vraw + (size_t)l * DIM;

    float sq = 0.f, sk = 0.f;
    for (int i = tid; i < DIM; i += TPB) {
        float a = qr[i]; sq += a * a;
        float b = kr[i]; sk += b * b;
    }
    __shared__ float rq[8], rk[8];
#pragma unroll
    for (int off = 16; off; off >>= 1) {
        sq += __shfl_xor_sync(0xffffffffu, sq, off);
        sk += __shfl_xor_sync(0xffffffffu, sk, off);
    }
    if ((tid & 31) == 0) { rq[tid >> 5] = sq; rk[tid >> 5] = sk; }
    __syncthreads();
    if (tid == 0) {
        float tq = 0.f, tk = 0.f;
        for (int i = 0; i < 8; i++) { tq += rq[i]; tk += rk[i]; }
        rq[0] = rsqrtf(tq / DIM + 1e-6f);
        rk[0] = rsqrtf(tk / DIM + 1e-6f);
    }
    __syncthreads();
    const float invq = rq[0], invk = rk[0];

    const int fi = l >> 6;
    const int rem = l & 63;
    const int hi = rem >> 3, wi = rem & 7;
    const bool keep = (fi & 1) == 0;
    const int kc = (fi >> 1) * 64 + rem;

    for (int e = tid; e < NHD * 64; e += TPB) {
        const int n = e >> 6;
        const int p = e & 63;
        float ang;
        if (p < 22)      ang = freqs[fi * 64 + p];
        else if (p < 43) ang = freqs[hi * 64 + p];
        else             ang = freqs[wi * 64 + p];
        float s, c;
        sincosf(ang, &s, &c);
        const int j0 = n * HD + 2 * p;

        float q0 = qr[j0] * invq * gq[j0];
        float q1 = qr[j0 + 1] * invq * gq[j0 + 1];
        g_qb[(size_t)l * DIM + j0]     = __float2bfloat16(q0 * c - q1 * s);
        g_qb[(size_t)l * DIM + j0 + 1] = __float2bfloat16(q0 * s + q1 * c);

        if (keep) {
            float k0v = kr[j0] * invk * gk[j0];
            float k1v = kr[j0 + 1] * invk * gk[j0 + 1];
            g_kb[(size_t)kc * DIM + j0]     = __float2bfloat16(k0v * c - k1v * s);
            g_kb[(size_t)kc * DIM + j0 + 1] = __float2bfloat16(k0v * s + k1v * c);
        }
    }
    if (keep) {
        for (int i = tid; i < DIM; i += TPB)
            g_vb[(size_t)kc * DIM + i] = __float2bfloat16(vr[i]);
    }
}

// ---------------- scores via HMMA ----------------
__global__ void __launch_bounds__(256) score_gemm_mma(void)
{
    __shared__ __nv_bfloat16 Qs[128][72];
    __shared__ __nv_bfloat16 Ks[128][72];
    const int h = blockIdx.z;
    const int m0 = blockIdx.y * 128, n0 = blockIdx.x * 128;
    const int tid = threadIdx.x;
    const int warp = tid >> 5, lane = tid & 31;
    const int wm = warp >> 1, wn = warp & 1;
    const int group = lane >> 2, tig = lane & 3;

    const __nv_bfloat16* Q  = g_qb + h * HD;
    const __nv_bfloat16* Kb = g_kb + h * HD;

    float acc[2][8][4] = {};

    for (int k0 = 0; k0 < HD; k0 += 64) {
#pragma unroll
        for (int i = 0; i < 4; i++) {
            int idx = tid + i * 256;
            int r = idx >> 3, c = (idx & 7) * 8;
            *(uint4*)&Qs[r][c] = *(const uint4*)&Q [(size_t)(m0 + r) * DIM + k0 + c];
            *(uint4*)&Ks[r][c] = *(const uint4*)&Kb[(size_t)(n0 + r) * DIM + k0 + c];
        }
        __syncthreads();
#pragma unroll
        for (int kk = 0; kk < 64; kk += 16) {
            unsigned a[2][4], b[8][2];
#pragma unroll
            for (int mt = 0; mt < 2; mt++) {
                const int r = wm * 32 + mt * 16 + group;
                a[mt][0] = *(const unsigned*)&Qs[r][kk + tig * 2];
                a[mt][1] = *(const unsigned*)&Qs[r + 8][kk + tig * 2];
                a[mt][2] = *(const unsigned*)&Qs[r][kk + 8 + tig * 2];
                a[mt][3] = *(const unsigned*)&Qs[r + 8][kk + 8 + tig * 2];
            }
#pragma unroll
            for (int nt = 0; nt < 8; nt++) {
                const int r = wn * 64 + nt * 8 + group;
                b[nt][0] = *(const unsigned*)&Ks[r][kk + tig * 2];
                b[nt][1] = *(const unsigned*)&Ks[r][kk + 8 + tig * 2];
            }
#pragma unroll
            for (int mt = 0; mt < 2; mt++)
#pragma unroll
                for (int nt = 0; nt < 8; nt++)
                    mma_bf16(acc[mt][nt], a[mt], b[nt]);
        }
        __syncthreads();
    }

    __nv_bfloat16* S = g_sc + (size_t)h * SL * LK;
#pragma unroll
    for (int mt = 0; mt < 2; mt++) {
        const int row = m0 + wm * 32 + mt * 16 + group;
#pragma unroll
        for (int nt = 0; nt < 8; nt++) {
            const int col = n0 + wn * 64 + nt * 8 + tig * 2;
            *(__nv_bfloat162*)&S[(size_t)row * LK + col] =
                __floats2bfloat162_rn(acc[mt][nt][0], acc[mt][nt][1]);
            *(__nv_bfloat162*)&S[(size_t)(row + 8) * LK + col] =
                __floats2bfloat162_rn(acc[mt][nt][2], acc[mt][nt][3]);
        }
    }
}

// ---------------- softmax, vectorized uint4 (8 bf16 per transaction) ----------------
__global__ void __launch_bounds__(256) softmax_kernel(void)
{
    uint4* S4 = (uint4*)(g_sc + (size_t)blockIdx.x * LK);   // 400 uint4 per row
    const int tid = threadIdx.x;
    const float scale = 0.088388347648318447f; // 1/sqrt(128)

    float v[16];
    int cnt = 0;
    float m = -1e30f;
    for (int i = tid; i < LK / 8; i += TPB) {
        uint4 r = S4[i];
        unsigned w[4] = {r.x, r.y, r.z, r.w};
#pragma unroll
        for (int j = 0; j < 4; j++) {
            float2 f = __bfloat1622float2(*(__nv_bfloat162*)&w[j]);
            float f0 = f.x * scale, f1 = f.y * scale;
            v[cnt++] = f0; v[cnt++] = f1;
            m = fmaxf(m, fmaxf(f0, f1));
        }
    }
    __shared__ float smax[8], ssum[8];
#pragma unroll
    for (int off = 16; off; off >>= 1) m = fmaxf(m, __shfl_xor_sync(0xffffffffu, m, off));
    if ((tid & 31) == 0) smax[tid >> 5] = m;
    __syncthreads();
    if (tid == 0) {
        float t = smax[0];
        for (int i = 1; i < 8; i++) t = fmaxf(t, smax[i]);
        smax[0] = t;
    }
    __syncthreads();
    m = smax[0];

    float z = 0.f;
    for (int c = 0; c < cnt; c++) { v[c] = expf(v[c] - m); z += v[c]; }
#pragma unroll
    for (int off = 16; off; off >>= 1) z += __shfl_xor_sync(0xffffffffu, z, off);
    if ((tid & 31) == 0) ssum[tid >> 5] = z;
    __syncthreads();
    if (tid == 0) {
        float t = 0.f;
        for (int i = 0; i < 8; i++) t += ssum[i];
        ssum[0] = t;
    }
    __syncthreads();
    const float inv = 1.f / ssum[0];

    cnt = 0;
    for (int i = tid; i < LK / 8; i += TPB) {
        uint4 o;
        unsigned* ow = &o.x;
#pragma unroll
        for (int j = 0; j < 4; j++) {
            __nv_bfloat162 b2 = __floats2bfloat162_rn(v[cnt] * inv, v[cnt + 1] * inv);
            ow[j] = *(unsigned*)&b2;
            cnt += 2;
        }
        S4[i] = o;
    }
}

// ---------------- PV via HMMA, bf16 output ----------------
__global__ void __launch_bounds__(256) pv_gemm_mma(void)
{
    __shared__ __nv_bfloat16 Ps[128][72];
    __shared__ unsigned Vp[32][132];
    const int h = blockIdx.z;
    const int m0 = blockIdx.y * 128;
    const int tid = threadIdx.x;
    const int warp = tid >> 5, lane = tid & 31;
    const int wm = warp >> 1, wn = warp & 1;
    const int group = lane >> 2, tig = lane & 3;

    const __nv_bfloat16* P = g_sc + (size_t)h * SL * LK;
    const __nv_bfloat16* V = g_vb + h * HD;

    float acc[2][8][4] = {};

    for (int k0 = 0; k0 < LK; k0 += 64) {
#pragma unroll
        for (int i = 0; i < 4; i++) {
            int idx = tid + i * 256;
            int r = idx >> 3, c = (idx & 7) * 8;
            *(uint4*)&Ps[r][c] = *(const uint4*)&P[(size_t)(m0 + r) * LK + k0 + c];
        }
#pragma unroll
        for (int i = 0; i < 2; i++) {
            int idx = tid + i * 256;
            int kp = idx >> 4, c = (idx & 15) * 8;
            uint4 a4 = *(const uint4*)&V[(size_t)(k0 + 2 * kp) * DIM + c];
            uint4 b4 = *(const uint4*)&V[(size_t)(k0 + 2 * kp + 1) * DIM + c];
            uint4 p0, p1;
            p0.x = __byte_perm(a4.x, b4.x, 0x5410); p0.y = __byte_perm(a4.x, b4.x, 0x7632);
            p0.z = __byte_perm(a4.y, b4.y, 0x5410); p0.w = __byte_perm(a4.y, b4.y, 0x7632);
            p1.x = __byte_perm(a4.z, b4.z, 0x5410); p1.y = __byte_perm(a4.z, b4.z, 0x7632);
            p1.z = __byte_perm(a4.w, b4.w, 0x5410); p1.w = __byte_perm(a4.w, b4.w, 0x7632);
            *(uint4*)&Vp[kp][c]     = p0;
            *(uint4*)&Vp[kp][c + 4] = p1;
        }
        __syncthreads();
#pragma unroll
        for (int kk = 0; kk < 64; kk += 16) {
            unsigned a[2][4], b[8][2];
#pragma unroll
            for (int mt = 0; mt < 2; mt++) {
                const int r = wm * 32 + mt * 16 + group;
                a[mt][0] = *(const unsigned*)&Ps[r][kk + tig * 2];
                a[mt][1] = *(const unsigned*)&Ps[r + 8][kk + tig * 2];
                a[mt][2] = *(const unsigned*)&Ps[r][kk + 8 + tig * 2];
                a[mt][3] = *(const unsigned*)&Ps[r + 8][kk + 8 + tig * 2];
            }
#pragma unroll
            for (int nt = 0; nt < 8; nt++) {
                const int n = wn * 64 + nt * 8 + group;
                b[nt][0] = Vp[kk / 2 + tig][n];
                b[nt][1] = Vp[kk / 2 + 4 + tig][n];
            }
#pragma unroll
            for (int mt = 0; mt < 2; mt++)
#pragma unroll
                for (int nt = 0; nt < 8; nt++)
                    mma_bf16(acc[mt][nt], a[mt], b[nt]);
        }
        __syncthreads();
    }

#pragma unroll
    for (int mt = 0; mt < 2; mt++) {
        const int row = m0 + wm * 32 + mt * 16 + group;
#pragma unroll
        for (int nt = 0; nt < 8; nt++) {
            const int col = h * HD + wn * 64 + nt * 8 + tig * 2;
            *(__nv_bfloat162*)&g_aob[(size_t)row * DIM + col] =
                __floats2bfloat162_rn(acc[mt][nt][0], acc[mt][nt][1]);
            *(__nv_bfloat162*)&g_aob[(size_t)(row + 8) * DIM + col] =
                __floats2bfloat162_rn(acc[mt][nt][2], acc[mt][nt][3]);
        }
    }
}

// ---------------- launch ----------------
extern "C" void kernel_launch(void* const* d_in, const int* in_sizes, int n_in,
                              void* d_out, int out_size)
{
    const float* x     = (const float*)d_in[0];
    const float* freqs = (const float*)d_in[1];
    const float* Wq    = (const float*)d_in[2];
    const float* bq    = (const float*)d_in[3];
    const float* Wk    = (const float*)d_in[4];
    const float* bk    = (const float*)d_in[5];
    const float* Wv    = (const float*)d_in[6];
    const float* bv    = (const float*)d_in[7];
    const float* Wo    = (const float*)d_in[8];
    const float* bo    = (const float*)d_in[9];
    const float* gq    = (const float*)d_in[10];
    const float* gk    = (const float*)d_in[11];
    float* out = (float*)d_out;

    float *qraw, *kraw, *vraw;
    __half *xh;
    unsigned *whp, *wop;
    __nv_bfloat16 *aob;
    cudaGetSymbolAddress((void**)&qraw, g_qraw);
    cudaGetSymbolAddress((void**)&kraw, g_kraw);
    cudaGetSymbolAddress((void**)&vraw, g_vraw);
    cudaGetSymbolAddress((void**)&xh,   g_xh);
    cudaGetSymbolAddress((void**)&whp,  g_whp);
    cudaGetSymbolAddress((void**)&wop,  g_wop);
    cudaGetSymbolAddress((void**)&aob,  g_aob);

    const size_t WPS = (size_t)(DIM / 2) * DIM;
    __half* xp[2];
    for (int i = 0; i < 2; i++) xp[i] = xh + (size_t)i * SL * DIM;
    unsigned* wp[6];
    for (int i = 0; i < 6; i++) wp[i] = whp + (size_t)i * WPS;
    unsigned* wo[2];
    for (int i = 0; i < 2; i++) wo[i] = wop + (size_t)i * WPS;

    cudaFuncSetAttribute(gemm_f16_split, cudaFuncAttributeMaxDynamicSharedMemorySize, SMF);
    cudaFuncSetAttribute(gemm_wo, cudaFuncAttributeMaxDynamicSharedMemorySize, SMW);

    dim3 blk(TPB);
    const int nw = (DIM / 2) * DIM;

    split2h_kernel<<<(SL * DIM + TPB - 1) / TPB, blk>>>(x, xp[0], xp[1], SL * DIM);
    splitpack_h_kernel<<<(nw + TPB - 1) / TPB, blk>>>(Wq, wp[0], wp[1], DIM, DIM);
    splitpack_h_kernel<<<(nw + TPB - 1) / TPB, blk>>>(Wk, wp[2], wp[3], DIM, DIM);
    splitpack_h_kernel<<<(nw + TPB - 1) / TPB, blk>>>(Wv, wp[4], wp[5], DIM, DIM);
    splitpack_b_kernel<<<(nw + TPB - 1) / TPB, blk>>>(Wo, wo[0], wo[1], DIM, DIM);

    dim3 gProj(DIM / 128, SL / 128);          // (12, 50)
    gemm_f16_split<<<gProj, blk, SMF>>>(xp[0], xp[1], wp[0], wp[1], bq, qraw, SL, DIM, DIM);
    gemm_f16_split<<<gProj, blk, SMF>>>(xp[0], xp[1], wp[2], wp[3], bk, kraw, SL, DIM, DIM);
    gemm_f16_split<<<gProj, blk, SMF>>>(xp[0], xp[1], wp[4], wp[5], bv, vraw, SL, DIM, DIM);

    rmsrope_kernel<<<SL, blk>>>(gq, gk, freqs);

    dim3 gScore(LK / 128, SL / 128, NHD);     // (25, 50, 12)
    score_gemm_mma<<<gScore, blk>>>();

    softmax_kernel<<<NHD * SL, blk>>>();      // 76800 rows

    dim3 gPV(1, SL / 128, NHD);
    pv_gemm_mma<<<gPV, blk>>>();

    gemm_wo<<<gProj, blk, SMW>>>(aob, wo[0], wo[1], bo, out, SL, DIM, DIM);
}

// round 9
// speedup vs baseline: 3.6694x; 1.0786x over previous
#include <cuda_runtime.h>
#include <cuda_bf16.h>
#include <cuda_fp16.h>

#define DIM 1536
#define NHD 12
#define HD  128
#define SL  6400      // query length (100*8*8)
#define LK  3200      // kv length after even-frame subsample (50*64)
#define TPB 256
#define NKB (LK / 128)   // 25 score col-blocks per row

#define LOSCALE 2048.0f
#define INV_LOSCALE 4.8828125e-4f   // 1/2048
#define SM_SCALE 0.088388347648318447f  // 1/sqrt(128)

// ---------------- scratch (static device arrays; no allocs) ----------------
__device__ float g_qraw[SL * DIM];
__device__ float g_kraw[SL * DIM];
__device__ float g_vraw[SL * DIM];
__device__ __half g_xh[2][SL * DIM];                   // x fp16 2-split (lo scaled)
__device__ unsigned g_whp[6][(DIM / 2) * DIM];         // Wq,Wk,Wv fp16 2-splits, k-pair packed
__device__ unsigned g_wop[2][(DIM / 2) * DIM];         // Wo bf16 2-split, k-pair packed
__device__ __nv_bfloat16 g_qb[SL * DIM];
__device__ __nv_bfloat16 g_kb[LK * DIM];
__device__ __nv_bfloat16 g_vb[LK * DIM];
__device__ __nv_bfloat16 g_sc[(size_t)NHD * SL * LK];  // 491.5 MB raw bf16 scores
__device__ float g_pm[NHD * SL * NKB];                 // per-block row max
__device__ float g_ps[NHD * SL * NKB];                 // per-block row sum-exp
__device__ float g_M[NHD * SL];                        // row max (global)
__device__ float g_iz[NHD * SL];                       // 1/Z per row
__device__ __nv_bfloat16 g_aob[SL * DIM];              // attention output, bf16 (per reference)

// ---------------- warp-level MMA helpers ----------------
__device__ __forceinline__ void mma_bf16(float* d, const unsigned* a, const unsigned* b)
{
    asm volatile(
        "mma.sync.aligned.m16n8k16.row.col.f32.bf16.bf16.f32 "
        "{%0,%1,%2,%3}, {%4,%5,%6,%7}, {%8,%9}, {%0,%1,%2,%3};\n"
        : "+f"(d[0]), "+f"(d[1]), "+f"(d[2]), "+f"(d[3])
        : "r"(a[0]), "r"(a[1]), "r"(a[2]), "r"(a[3]), "r"(b[0]), "r"(b[1]));
}

__device__ __forceinline__ void mma_f16(float* d, const unsigned* a, const unsigned* b)
{
    asm volatile(
        "mma.sync.aligned.m16n8k16.row.col.f32.f16.f16.f32 "
        "{%0,%1,%2,%3}, {%4,%5,%6,%7}, {%8,%9}, {%0,%1,%2,%3};\n"
        : "+f"(d[0]), "+f"(d[1]), "+f"(d[2]), "+f"(d[3])
        : "r"(a[0]), "r"(a[1]), "r"(a[2]), "r"(a[3]), "r"(b[0]), "r"(b[1]));
}

__device__ __forceinline__ void ldsm_x4(unsigned* a, const void* p)
{
    unsigned addr = (unsigned)__cvta_generic_to_shared(p);
    asm volatile("ldmatrix.sync.aligned.m8n8.x4.shared.b16 {%0,%1,%2,%3}, [%4];"
                 : "=r"(a[0]), "=r"(a[1]), "=r"(a[2]), "=r"(a[3]) : "r"(addr));
}

__device__ __forceinline__ void cp16(void* dst_smem, const void* src)
{
    unsigned d = (unsigned)__cvta_generic_to_shared(dst_smem);
    asm volatile("cp.async.cg.shared.global [%0], [%1], 16;\n" :: "r"(d), "l"(src));
}
#define CP_COMMIT() asm volatile("cp.async.commit_group;\n")
#define CP_WAIT0()  asm volatile("cp.async.wait_group 0;\n")

// ---------------- splits ----------------
__global__ void split2h_kernel(const float* __restrict__ src,
                               __half* __restrict__ h0,
                               __half* __restrict__ h1, int n)
{
    int i = blockIdx.x * blockDim.x + threadIdx.x;
    if (i < n) {
        float f = src[i];
        __half a = __float2half_rn(f);
        float r = f - __half2float(a);
        h0[i] = a;
        h1[i] = __float2half_rn(r * LOSCALE);
    }
}

__global__ void splitpack_h_kernel(const float* __restrict__ src,
                                   unsigned* __restrict__ p0,
                                   unsigned* __restrict__ p1, int K, int N)
{
    int i = blockIdx.x * blockDim.x + threadIdx.x;
    int total = (K / 2) * N;
    if (i < total) {
        int kp = i / N, n = i - kp * N;
        float f0 = src[(size_t)(2 * kp) * N + n];
        float f1 = src[(size_t)(2 * kp + 1) * N + n];
        __half h0 = __float2half_rn(f0), h1 = __float2half_rn(f1);
        __half l0 = __float2half_rn((f0 - __half2float(h0)) * LOSCALE);
        __half l1 = __float2half_rn((f1 - __half2float(h1)) * LOSCALE);
        __half2 ph = __halves2half2(h0, h1);
        __half2 pl = __halves2half2(l0, l1);
        p0[i] = *(unsigned*)&ph;
        p1[i] = *(unsigned*)&pl;
    }
}

__global__ void splitpack_b_kernel(const float* __restrict__ src,
                                   unsigned* __restrict__ p0,
                                   unsigned* __restrict__ p1, int K, int N)
{
    int i = blockIdx.x * blockDim.x + threadIdx.x;
    int total = (K / 2) * N;
    if (i < total) {
        int kp = i / N, n = i - kp * N;
        float f0 = src[(size_t)(2 * kp) * N + n];
        float f1 = src[(size_t)(2 * kp + 1) * N + n];
        __nv_bfloat16 h0 = __float2bfloat16(f0), h1 = __float2bfloat16(f1);
        __nv_bfloat16 l0 = __float2bfloat16(f0 - __bfloat162float(h0));
        __nv_bfloat16 l1 = __float2bfloat16(f1 - __bfloat162float(h1));
        __nv_bfloat162 ph = __halves2bfloat162(h0, h1);
        __nv_bfloat162 pl = __halves2bfloat162(l0, l1);
        p0[i] = *(unsigned*)&ph;
        p1[i] = *(unsigned*)&pl;
    }
}

// ---------------- fp16 3-term split GEMM, cp.async + ldmatrix + chunk-fold ----------
#define SMF (2*2*128*40*2 + 2*2*16*132*4)   // 74752
__global__ void __launch_bounds__(256) gemm_f16_split(
    const __half* __restrict__ A0, const __half* __restrict__ A1,
    const unsigned* __restrict__ B0p, const unsigned* __restrict__ B1p,
    const float* __restrict__ bias, float* __restrict__ C, int M, int N, int K)
{
    extern __shared__ char sm[];
    typedef __half ATile[2][128][40];
    typedef unsigned BTile[2][16][132];
    ATile* As = (ATile*)sm;
    BTile* Bs = (BTile*)(sm + 2 * 2 * 128 * 40 * 2);

    const int tid = threadIdx.x;
    const int warp = tid >> 5, lane = tid & 31;
    const int wm = warp >> 1, wn = warp & 1;
    const int group = lane >> 2, tig = lane & 3;
    const int m0 = blockIdx.y * 128, n0 = blockIdx.x * 128;

    const int lrow = (lane & 7) + ((lane >> 3) & 1) * 8;
    const int lcol = (lane >> 4) * 8;

    const __half* Ap[2] = {A0, A1};
    const unsigned* Bp[2] = {B0p, B1p};

    const int rA = tid >> 2;
    const int cA = (tid & 3) * 8;
    const int kpB = tid >> 5;
    const int nqB = (tid & 31) * 4;

    auto issue = [&](int k0, int buf) {
#pragma unroll
        for (int p = 0; p < 2; p++) {
#pragma unroll
            for (int i = 0; i < 2; i++) {
                int r = rA + i * 64;
                cp16(&As[buf][p][r][cA], &Ap[p][(size_t)(m0 + r) * K + k0 + cA]);
            }
#pragma unroll
            for (int i = 0; i < 2; i++) {
                int kp = kpB + i * 8;
                cp16(&Bs[buf][p][kp][nqB], &Bp[p][(size_t)(k0 / 2 + kp) * N + n0 + nqB]);
            }
        }
    };

    float acc[2][8][4] = {};

    issue(0, 0);
    CP_COMMIT();
    int buf = 0;

    for (int k0 = 0; k0 < K; k0 += 32) {
        CP_WAIT0();
        __syncthreads();
        if (k0 + 32 < K) {
            issue(k0 + 32, buf ^ 1);
            CP_COMMIT();
        }

        unsigned a[2][2][2][4];   // [part][mt][kk2]
#pragma unroll
        for (int p = 0; p < 2; p++)
#pragma unroll
            for (int mt = 0; mt < 2; mt++)
#pragma unroll
                for (int kk2 = 0; kk2 < 2; kk2++)
                    ldsm_x4(a[p][mt][kk2],
                            &As[buf][p][wm * 32 + mt * 16 + lrow][kk2 * 16 + lcol]);

#pragma unroll
        for (int nt = 0; nt < 8; nt++) {
            const int n = wn * 64 + nt * 8 + group;
            float d0[2][4] = {};
            float d1[2][4] = {};
#pragma unroll
            for (int kk2 = 0; kk2 < 2; kk2++) {
                unsigned b0[2], b1[2];
                b0[0] = Bs[buf][0][kk2 * 8 + tig][n];
                b0[1] = Bs[buf][0][kk2 * 8 + 4 + tig][n];
                b1[0] = Bs[buf][1][kk2 * 8 + tig][n];
                b1[1] = Bs[buf][1][kk2 * 8 + 4 + tig][n];
#pragma unroll
                for (int mt = 0; mt < 2; mt++) {
                    mma_f16(d0[mt], a[0][mt][kk2], b0);
                    mma_f16(d1[mt], a[0][mt][kk2], b1);
                    mma_f16(d1[mt], a[1][mt][kk2], b0);
                }
            }
#pragma unroll
            for (int mt = 0; mt < 2; mt++)
#pragma unroll
                for (int c = 0; c < 4; c++)
                    acc[mt][nt][c] += d0[mt][c] + d1[mt][c] * INV_LOSCALE;
        }
        buf ^= 1;
    }

#pragma unroll
    for (int mt = 0; mt < 2; mt++) {
        const int row = m0 + wm * 32 + mt * 16 + group;
#pragma unroll
        for (int nt = 0; nt < 8; nt++) {
            const int col = n0 + wn * 64 + nt * 8 + tig * 2;
            float b0 = bias[col], b1 = bias[col + 1];
            C[(size_t)row * N + col]           = acc[mt][nt][0] + b0;
            C[(size_t)row * N + col + 1]       = acc[mt][nt][1] + b1;
            C[(size_t)(row + 8) * N + col]     = acc[mt][nt][2] + b0;
            C[(size_t)(row + 8) * N + col + 1] = acc[mt][nt][3] + b1;
        }
    }
}

// ---------------- bf16 2-term GEMM for Wo, cp.async + ldmatrix + chunk-fold ----------
#define SMW (2*128*40*2 + 2*2*16*132*4)     // 54272
__global__ void __launch_bounds__(256) gemm_wo(
    const __nv_bfloat16* __restrict__ A0,
    const unsigned* __restrict__ B0p, const unsigned* __restrict__ B1p,
    const float* __restrict__ bias, float* __restrict__ C, int M, int N, int K)
{
    extern __shared__ char sm[];
    typedef __nv_bfloat16 ATile[128][40];
    typedef unsigned BTile[2][16][132];
    ATile* As = (ATile*)sm;
    BTile* Bs = (BTile*)(sm + 2 * 128 * 40 * 2);

    const int tid = threadIdx.x;
    const int warp = tid >> 5, lane = tid & 31;
    const int wm = warp >> 1, wn = warp & 1;
    const int group = lane >> 2, tig = lane & 3;
    const int m0 = blockIdx.y * 128, n0 = blockIdx.x * 128;

    const int lrow = (lane & 7) + ((lane >> 3) & 1) * 8;
    const int lcol = (lane >> 4) * 8;

    const unsigned* Bp[2] = {B0p, B1p};
    const int rA = tid >> 2;
    const int cA = (tid & 3) * 8;
    const int kpB = tid >> 5;
    const int nqB = (tid & 31) * 4;

    auto issue = [&](int k0, int buf) {
#pragma unroll
        for (int i = 0; i < 2; i++) {
            int r = rA + i * 64;
            cp16(&As[buf][r][cA], &A0[(size_t)(m0 + r) * K + k0 + cA]);
        }
#pragma unroll
        for (int p = 0; p < 2; p++)
#pragma unroll
            for (int i = 0; i < 2; i++) {
                int kp = kpB + i * 8;
                cp16(&Bs[buf][p][kp][nqB], &Bp[p][(size_t)(k0 / 2 + kp) * N + n0 + nqB]);
            }
    };

    float acc[2][8][4] = {};
    issue(0, 0);
    CP_COMMIT();
    int buf = 0;

    for (int k0 = 0; k0 < K; k0 += 32) {
        CP_WAIT0();
        __syncthreads();
        if (k0 + 32 < K) {
            issue(k0 + 32, buf ^ 1);
            CP_COMMIT();
        }

        unsigned a[2][2][4];
#pragma unroll
        for (int mt = 0; mt < 2; mt++)
#pragma unroll
            for (int kk2 = 0; kk2 < 2; kk2++)
                ldsm_x4(a[mt][kk2], &As[buf][wm * 32 + mt * 16 + lrow][kk2 * 16 + lcol]);

#pragma unroll
        for (int nt = 0; nt < 8; nt++) {
            const int n = wn * 64 + nt * 8 + group;
            float d[2][4] = {};
#pragma unroll
            for (int kk2 = 0; kk2 < 2; kk2++) {
                unsigned b0[2], b1[2];
                b0[0] = Bs[buf][0][kk2 * 8 + tig][n];
                b0[1] = Bs[buf][0][kk2 * 8 + 4 + tig][n];
                b1[0] = Bs[buf][1][kk2 * 8 + tig][n];
                b1[1] = Bs[buf][1][kk2 * 8 + 4 + tig][n];
#pragma unroll
                for (int mt = 0; mt < 2; mt++) {
                    mma_bf16(d[mt], a[mt][kk2], b0);
                    mma_bf16(d[mt], a[mt][kk2], b1);
                }
            }
#pragma unroll
            for (int mt = 0; mt < 2; mt++)
#pragma unroll
                for (int c = 0; c < 4; c++)
                    acc[mt][nt][c] += d[mt][c];
        }
        buf ^= 1;
    }

#pragma unroll
    for (int mt = 0; mt < 2; mt++) {
        const int row = m0 + wm * 32 + mt * 16 + group;
#pragma unroll
        for (int nt = 0; nt < 8; nt++) {
            const int col = n0 + wn * 64 + nt * 8 + tig * 2;
            float b0 = bias[col], b1 = bias[col + 1];
            C[(size_t)row * N + col]           = acc[mt][nt][0] + b0;
            C[(size_t)row * N + col + 1]       = acc[mt][nt][1] + b1;
            C[(size_t)(row + 8) * N + col]     = acc[mt][nt][2] + b0;
            C[(size_t)(row + 8) * N + col + 1] = acc[mt][nt][3] + b1;
        }
    }
}

// ---------------- RMSNorm + 3D RoPE + bf16 pack + KV subsample ----------------
__global__ void rmsrope_kernel(const float* __restrict__ gq, const float* __restrict__ gk,
                               const float* __restrict__ freqs)
{
    const int l = blockIdx.x;
    const int tid = threadIdx.x;
    const float* qr = g_qraw + (size_t)l * DIM;
    const float* kr = g_kraw + (size_t)l * DIM;
    const float* vr = g_vraw + (size_t)l * DIM;

    float sq = 0.f, sk = 0.f;
    for (int i = tid; i < DIM; i += TPB) {
        float a = qr[i]; sq += a * a;
        float b = kr[i]; sk += b * b;
    }
    __shared__ float rq[8], rk[8];
#pragma unroll
    for (int off = 16; off; off >>= 1) {
        sq += __shfl_xor_sync(0xffffffffu, sq, off);
        sk += __shfl_xor_sync(0xffffffffu, sk, off);
    }
    if ((tid & 31) == 0) { rq[tid >> 5] = sq; rk[tid >> 5] = sk; }
    __syncthreads();
    if (tid == 0) {
        float tq = 0.f, tk = 0.f;
        for (int i = 0; i < 8; i++) { tq += rq[i]; tk += rk[i]; }
        rq[0] = rsqrtf(tq / DIM + 1e-6f);
        rk[0] = rsqrtf(tk / DIM + 1e-6f);
    }
    __syncthreads();
    const float invq = rq[0], invk = rk[0];

    const int fi = l >> 6;
    const int rem = l & 63;
    const int hi = rem >> 3, wi = rem & 7;
    const bool keep = (fi & 1) == 0;
    const int kc = (fi >> 1) * 64 + rem;

    for (int e = tid; e < NHD * 64; e += TPB) {
        const int n = e >> 6;
        const int p = e & 63;
        float ang;
        if (p < 22)      ang = freqs[fi * 64 + p];
        else if (p < 43) ang = freqs[hi * 64 + p];
        else             ang = freqs[wi * 64 + p];
        float s, c;
        sincosf(ang, &s, &c);
        const int j0 = n * HD + 2 * p;

        float q0 = qr[j0] * invq * gq[j0];
        float q1 = qr[j0 + 1] * invq * gq[j0 + 1];
        g_qb[(size_t)l * DIM + j0]     = __float2bfloat16(q0 * c - q1 * s);
        g_qb[(size_t)l * DIM + j0 + 1] = __float2bfloat16(q0 * s + q1 * c);

        if (keep) {
            float k0v = kr[j0] * invk * gk[j0];
            float k1v = kr[j0 + 1] * invk * gk[j0 + 1];
            g_kb[(size_t)kc * DIM + j0]     = __float2bfloat16(k0v * c - k1v * s);
            g_kb[(size_t)kc * DIM + j0 + 1] = __float2bfloat16(k0v * s + k1v * c);
        }
    }
    if (keep) {
        for (int i = tid; i < DIM; i += TPB)
            g_vb[(size_t)kc * DIM + i] = __float2bfloat16(vr[i]);
    }
}

// ---------------- scores via HMMA + fused per-block softmax stats ----------------
__global__ void __launch_bounds__(256) score_gemm_mma(void)
{
    __shared__ __nv_bfloat16 Qs[128][72];
    __shared__ __nv_bfloat16 Ks[128][72];
    __shared__ float sm_m[128][2], sm_s[128][2];
    const int h = blockIdx.z;
    const int mb0 = blockIdx.y * 128, n0 = blockIdx.x * 128;
    const int tid = threadIdx.x;
    const int warp = tid >> 5, lane = tid & 31;
    const int wm = warp >> 1, wn = warp & 1;
    const int group = lane >> 2, tig = lane & 3;

    const __nv_bfloat16* Q  = g_qb + h * HD;
    const __nv_bfloat16* Kb = g_kb + h * HD;

    float acc[2][8][4] = {};

    for (int k0 = 0; k0 < HD; k0 += 64) {
#pragma unroll
        for (int i = 0; i < 4; i++) {
            int idx = tid + i * 256;
            int r = idx >> 3, c = (idx & 7) * 8;
            *(uint4*)&Qs[r][c] = *(const uint4*)&Q [(size_t)(mb0 + r) * DIM + k0 + c];
            *(uint4*)&Ks[r][c] = *(const uint4*)&Kb[(size_t)(n0 + r) * DIM + k0 + c];
        }
        __syncthreads();
#pragma unroll
        for (int kk = 0; kk < 64; kk += 16) {
            unsigned a[2][4], b[8][2];
#pragma unroll
            for (int mt = 0; mt < 2; mt++) {
                const int r = wm * 32 + mt * 16 + group;
                a[mt][0] = *(const unsigned*)&Qs[r][kk + tig * 2];
                a[mt][1] = *(const unsigned*)&Qs[r + 8][kk + tig * 2];
                a[mt][2] = *(const unsigned*)&Qs[r][kk + 8 + tig * 2];
                a[mt][3] = *(const unsigned*)&Qs[r + 8][kk + 8 + tig * 2];
            }
#pragma unroll
            for (int nt = 0; nt < 8; nt++) {
                const int r = wn * 64 + nt * 8 + group;
                b[nt][0] = *(const unsigned*)&Ks[r][kk + tig * 2];
                b[nt][1] = *(const unsigned*)&Ks[r][kk + 8 + tig * 2];
            }
#pragma unroll
            for (int mt = 0; mt < 2; mt++)
#pragma unroll
                for (int nt = 0; nt < 8; nt++)
                    mma_bf16(acc[mt][nt], a[mt], b[nt]);
        }
        __syncthreads();
    }

    // epilogue: store bf16 scores + compute per-(row, block) max & sum-exp of
    // the bf16-rounded scaled values (exactly what reference softmax consumes)
    __nv_bfloat16* S = g_sc + (size_t)h * SL * LK;
#pragma unroll
    for (int mt = 0; mt < 2; mt++) {
#pragma unroll
        for (int hh = 0; hh < 2; hh++) {                 // hh=0 -> row, hh=1 -> row+8
            const int rr = wm * 32 + mt * 16 + group + hh * 8;
            const int row = mb0 + rr;
            float xv[16];
            float mx = -1e30f;
#pragma unroll
            for (int nt = 0; nt < 8; nt++) {
                const int col = n0 + wn * 64 + nt * 8 + tig * 2;
                __nv_bfloat162 b2 = __floats2bfloat162_rn(acc[mt][nt][hh * 2],
                                                          acc[mt][nt][hh * 2 + 1]);
                *(__nv_bfloat162*)&S[(size_t)row * LK + col] = b2;
                float2 f = __bfloat1622float2(b2);
                xv[2 * nt]     = f.x * SM_SCALE;
                xv[2 * nt + 1] = f.y * SM_SCALE;
                mx = fmaxf(mx, fmaxf(xv[2 * nt], xv[2 * nt + 1]));
            }
            // quad reduce max (lanes tig 0..3 share row)
            mx = fmaxf(mx, __shfl_xor_sync(0xffffffffu, mx, 1));
            mx = fmaxf(mx, __shfl_xor_sync(0xffffffffu, mx, 2));
            float sum = 0.f;
#pragma unroll
            for (int c = 0; c < 16; c++) sum += expf(xv[c] - mx);
            sum += __shfl_xor_sync(0xffffffffu, sum, 1);
            sum += __shfl_xor_sync(0xffffffffu, sum, 2);
            if (tig == 0) { sm_m[rr][wn] = mx; sm_s[rr][wn] = sum; }
        }
    }
    __syncthreads();
    if (tid < 128) {
        float m0v = sm_m[tid][0], m1v = sm_m[tid][1];
        float M = fmaxf(m0v, m1v);
        float Sv = sm_s[tid][0] * expf(m0v - M) + sm_s[tid][1] * expf(m1v - M);
        size_t base = ((size_t)h * SL + mb0 + tid) * NKB + blockIdx.x;
        g_pm[base] = M;
        g_ps[base] = Sv;
    }
}

// ---------------- combine partial stats -> per-row M, 1/Z ----------------
__global__ void combine_kernel(void)
{
    int idx = blockIdx.x * blockDim.x + threadIdx.x;
    if (idx >= NHD * SL) return;
    const float* pm = g_pm + (size_t)idx * NKB;
    const float* ps = g_ps + (size_t)idx * NKB;
    float M = -1e30f;
#pragma unroll
    for (int b = 0; b < NKB; b++) M = fmaxf(M, pm[b]);
    float Z = 0.f;
#pragma unroll
    for (int b = 0; b < NKB; b++) Z += ps[b] * expf(pm[b] - M);
    g_M[idx] = M;
    g_iz[idx] = 1.f / Z;
}

// ---------------- PV via HMMA; probs computed on the fly from raw scores ----------
__global__ void __launch_bounds__(256) pv_gemm_mma(void)
{
    __shared__ __nv_bfloat16 Ps[128][72];
    __shared__ unsigned Vp[32][132];
    __shared__ float sMr[128], sZr[128];
    const int h = blockIdx.z;
    const int m0 = blockIdx.y * 128;
    const int tid = threadIdx.x;
    const int warp = tid >> 5, lane = tid & 31;
    const int wm = warp >> 1, wn = warp & 1;
    const int group = lane >> 2, tig = lane & 3;

    const __nv_bfloat16* P = g_sc + (size_t)h * SL * LK;
    const __nv_bfloat16* V = g_vb + h * HD;

    if (tid < 128) {
        int row = h * SL + m0 + tid;
        sMr[tid] = g_M[row];
        sZr[tid] = g_iz[row];
    }
    __syncthreads();

    float acc[2][8][4] = {};

    for (int k0 = 0; k0 < LK; k0 += 64) {
        // P tile load with on-the-fly softmax: p = bf16(expf(x - M) * invZ)
#pragma unroll
        for (int i = 0; i < 4; i++) {
            int idx = tid + i * 256;
            int r = idx >> 3, c = (idx & 7) * 8;
            uint4 raw = *(const uint4*)&P[(size_t)(m0 + r) * LK + k0 + c];
            float M = sMr[r], iz = sZr[r];
            unsigned* w = &raw.x;
            uint4 o;
            unsigned* ow = &o.x;
#pragma unroll
            for (int j = 0; j < 4; j++) {
                float2 f = __bfloat1622float2(*(__nv_bfloat162*)&w[j]);
                float p0 = expf(f.x * SM_SCALE - M) * iz;
                float p1 = expf(f.y * SM_SCALE - M) * iz;
                __nv_bfloat162 b2 = __floats2bfloat162_rn(p0, p1);
                ow[j] = *(unsigned*)&b2;
            }
            *(uint4*)&Ps[r][c] = o;
        }
#pragma unroll
        for (int i = 0; i < 2; i++) {
            int idx = tid + i * 256;
            int kp = idx >> 4, c = (idx & 15) * 8;
            uint4 a4 = *(const uint4*)&V[(size_t)(k0 + 2 * kp) * DIM + c];
            uint4 b4 = *(const uint4*)&V[(size_t)(k0 + 2 * kp + 1) * DIM + c];
            uint4 p0, p1;
            p0.x = __byte_perm(a4.x, b4.x, 0x5410); p0.y = __byte_perm(a4.x, b4.x, 0x7632);
            p0.z = __byte_perm(a4.y, b4.y, 0x5410); p0.w = __byte_perm(a4.y, b4.y, 0x7632);
            p1.x = __byte_perm(a4.z, b4.z, 0x5410); p1.y = __byte_perm(a4.z, b4.z, 0x7632);
            p1.z = __byte_perm(a4.w, b4.w, 0x5410); p1.w = __byte_perm(a4.w, b4.w, 0x7632);
            *(uint4*)&Vp[kp][c]     = p0;
            *(uint4*)&Vp[kp][c + 4] = p1;
        }
        __syncthreads();
#pragma unroll
        for (int kk = 0; kk < 64; kk += 16) {
            unsigned a[2][4], b[8][2];
#pragma unroll
            for (int mt = 0; mt < 2; mt++) {
                const int r = wm * 32 + mt * 16 + group;
                a[mt][0] = *(const unsigned*)&Ps[r][kk + tig * 2];
                a[mt][1] = *(const unsigned*)&Ps[r + 8][kk + tig * 2];
                a[mt][2] = *(const unsigned*)&Ps[r][kk + 8 + tig * 2];
                a[mt][3] = *(const unsigned*)&Ps[r + 8][kk + 8 + tig * 2];
            }
#pragma unroll
            for (int nt = 0; nt < 8; nt++) {
                const int n = wn * 64 + nt * 8 + group;
                b[nt][0] = Vp[kk / 2 + tig][n];
                b[nt][1] = Vp[kk / 2 + 4 + tig][n];
            }
#pragma unroll
            for (int mt = 0; mt < 2; mt++)
#pragma unroll
                for (int nt = 0; nt < 8; nt++)
                    mma_bf16(acc[mt][nt], a[mt], b[nt]);
        }
        __syncthreads();
    }

#pragma unroll
    for (int mt = 0; mt < 2; mt++) {
        const int row = m0 + wm * 32 + mt * 16 + group;
#pragma unroll
        for (int nt = 0; nt < 8; nt++) {
            const int col = h * HD + wn * 64 + nt * 8 + tig * 2;
            *(__nv_bfloat162*)&g_aob[(size_t)row * DIM + col] =
                __floats2bfloat162_rn(acc[mt][nt][0], acc[mt][nt][1]);
            *(__nv_bfloat162*)&g_aob[(size_t)(row + 8) * DIM + col] =
                __floats2bfloat162_rn(acc[mt][nt][2], acc[mt][nt][3]);
        }
    }
}

// ---------------- launch ----------------
extern "C" void kernel_launch(void* const* d_in, const int* in_sizes, int n_in,
                              void* d_out, int out_size)
{
    const float* x     = (const float*)d_in[0];
    const float* freqs = (const float*)d_in[1];
    const float* Wq    = (const float*)d_in[2];
    const float* bq    = (const float*)d_in[3];
    const float* Wk    = (const float*)d_in[4];
    const float* bk    = (const float*)d_in[5];
    const float* Wv    = (const float*)d_in[6];
    const float* bv    = (const float*)d_in[7];
    const float* Wo    = (const float*)d_in[8];
    const float* bo    = (const float*)d_in[9];
    const float* gq    = (const float*)d_in[10];
    const float* gk    = (const float*)d_in[11];
    float* out = (float*)d_out;

    float *qraw, *kraw, *vraw;
    __half *xh;
    unsigned *whp, *wop;
    __nv_bfloat16 *aob;
    cudaGetSymbolAddress((void**)&qraw, g_qraw);
    cudaGetSymbolAddress((void**)&kraw, g_kraw);
    cudaGetSymbolAddress((void**)&vraw, g_vraw);
    cudaGetSymbolAddress((void**)&xh,   g_xh);
    cudaGetSymbolAddress((void**)&whp,  g_whp);
    cudaGetSymbolAddress((void**)&wop,  g_wop);
    cudaGetSymbolAddress((void**)&aob,  g_aob);

    const size_t WPS = (size_t)(DIM / 2) * DIM;
    __half* xp[2];
    for (int i = 0; i < 2; i++) xp[i] = xh + (size_t)i * SL * DIM;
    unsigned* wp[6];
    for (int i = 0; i < 6; i++) wp[i] = whp + (size_t)i * WPS;
    unsigned* wo[2];
    for (int i = 0; i < 2; i++) wo[i] = wop + (size_t)i * WPS;

    cudaFuncSetAttribute(gemm_f16_split, cudaFuncAttributeMaxDynamicSharedMemorySize, SMF);
    cudaFuncSetAttribute(gemm_wo, cudaFuncAttributeMaxDynamicSharedMemorySize, SMW);

    dim3 blk(TPB);
    const int nw = (DIM / 2) * DIM;

    split2h_kernel<<<(SL * DIM + TPB - 1) / TPB, blk>>>(x, xp[0], xp[1], SL * DIM);
    splitpack_h_kernel<<<(nw + TPB - 1) / TPB, blk>>>(Wq, wp[0], wp[1], DIM, DIM);
    splitpack_h_kernel<<<(nw + TPB - 1) / TPB, blk>>>(Wk, wp[2], wp[3], DIM, DIM);
    splitpack_h_kernel<<<(nw + TPB - 1) / TPB, blk>>>(Wv, wp[4], wp[5], DIM, DIM);
    splitpack_b_kernel<<<(nw + TPB - 1) / TPB, blk>>>(Wo, wo[0], wo[1], DIM, DIM);

    dim3 gProj(DIM / 128, SL / 128);          // (12, 50)
    gemm_f16_split<<<gProj, blk, SMF>>>(xp[0], xp[1], wp[0], wp[1], bq, qraw, SL, DIM, DIM);
    gemm_f16_split<<<gProj, blk, SMF>>>(xp[0], xp[1], wp[2], wp[3], bk, kraw, SL, DIM, DIM);
    gemm_f16_split<<<gProj, blk, SMF>>>(xp[0], xp[1], wp[4], wp[5], bv, vraw, SL, DIM, DIM);

    rmsrope_kernel<<<SL, blk>>>(gq, gk, freqs);

    dim3 gScore(LK / 128, SL / 128, NHD);     // (25, 50, 12)
    score_gemm_mma<<<gScore, blk>>>();

    combine_kernel<<<(NHD * SL + TPB - 1) / TPB, blk>>>();

    dim3 gPV(1, SL / 128, NHD);
    pv_gemm_mma<<<gPV, blk>>>();

    gemm_wo<<<gProj, blk, SMW>>>(aob, wo[0], wo[1], bo, out, SL, DIM, DIM);
}

// round 10
// speedup vs baseline: 4.3336x; 1.1810x over previous
#include <cuda_runtime.h>
#include <cuda_bf16.h>
#include <cuda_fp16.h>

#define DIM 1536
#define NHD 12
#define HD  128
#define SL  6400      // query length (100*8*8)
#define LK  3200      // kv length after even-frame subsample (50*64)
#define TPB 256
#define NKB (LK / 128)   // 25 score col-blocks per row

#define LOSCALE 2048.0f
#define INV_LOSCALE 4.8828125e-4f   // 1/2048
#define SM_SCALE 0.088388347648318447f  // 1/sqrt(128)

// ---------------- scratch (static device arrays; no allocs) ----------------
__device__ float g_qraw[SL * DIM];
__device__ float g_kraw[LK * DIM];                     // only kept rows
__device__ __half g_xh[2][SL * DIM];                   // x fp16 2-split (lo scaled)
__device__ unsigned g_whp[6][(DIM / 2) * DIM];         // Wq,Wk,Wv fp16 2-splits, k-pair packed
__device__ unsigned g_wop[2][(DIM / 2) * DIM];         // Wo bf16 2-split, k-pair packed
__device__ __nv_bfloat16 g_qb[SL * DIM];
__device__ __nv_bfloat16 g_kb[LK * DIM];
__device__ __nv_bfloat16 g_vb[LK * DIM];
__device__ __nv_bfloat16 g_sc[(size_t)NHD * SL * LK];  // 491.5 MB raw bf16 scores
__device__ float g_pm[NHD * SL * NKB];                 // per-block row max
__device__ float g_ps[NHD * SL * NKB];                 // per-block row sum-exp
__device__ float g_M[NHD * SL];                        // row max (global)
__device__ float g_iz[NHD * SL];                       // 1/Z per row
__device__ __nv_bfloat16 g_aob[SL * DIM];              // attention output, bf16 (per reference)

// ---------------- warp-level MMA helpers ----------------
__device__ __forceinline__ void mma_bf16(float* d, const unsigned* a, const unsigned* b)
{
    asm volatile(
        "mma.sync.aligned.m16n8k16.row.col.f32.bf16.bf16.f32 "
        "{%0,%1,%2,%3}, {%4,%5,%6,%7}, {%8,%9}, {%0,%1,%2,%3};\n"
        : "+f"(d[0]), "+f"(d[1]), "+f"(d[2]), "+f"(d[3])
        : "r"(a[0]), "r"(a[1]), "r"(a[2]), "r"(a[3]), "r"(b[0]), "r"(b[1]));
}

__device__ __forceinline__ void mma_f16(float* d, const unsigned* a, const unsigned* b)
{
    asm volatile(
        "mma.sync.aligned.m16n8k16.row.col.f32.f16.f16.f32 "
        "{%0,%1,%2,%3}, {%4,%5,%6,%7}, {%8,%9}, {%0,%1,%2,%3};\n"
        : "+f"(d[0]), "+f"(d[1]), "+f"(d[2]), "+f"(d[3])
        : "r"(a[0]), "r"(a[1]), "r"(a[2]), "r"(a[3]), "r"(b[0]), "r"(b[1]));
}

__device__ __forceinline__ void ldsm_x4(unsigned* a, const void* p)
{
    unsigned addr = (unsigned)__cvta_generic_to_shared(p);
    asm volatile("ldmatrix.sync.aligned.m8n8.x4.shared.b16 {%0,%1,%2,%3}, [%4];"
                 : "=r"(a[0]), "=r"(a[1]), "=r"(a[2]), "=r"(a[3]) : "r"(addr));
}

__device__ __forceinline__ void cp16(void* dst_smem, const void* src)
{
    unsigned d = (unsigned)__cvta_generic_to_shared(dst_smem);
    asm volatile("cp.async.cg.shared.global [%0], [%1], 16;\n" :: "r"(d), "l"(src));
}
#define CP_COMMIT() asm volatile("cp.async.commit_group;\n")
#define CP_WAIT0()  asm volatile("cp.async.wait_group 0;\n")

// expand compact kv row index -> original sequence row (even frames only)
__device__ __forceinline__ int kv_src_row(int kc) { return kc + ((kc >> 6) << 6); }

// ---------------- splits ----------------
__global__ void split2h_kernel(const float* __restrict__ src,
                               __half* __restrict__ h0,
                               __half* __restrict__ h1, int n)
{
    int i = blockIdx.x * blockDim.x + threadIdx.x;
    if (i < n) {
        float f = src[i];
        __half a = __float2half_rn(f);
        float r = f - __half2float(a);
        h0[i] = a;
        h1[i] = __float2half_rn(r * LOSCALE);
    }
}

__global__ void splitpack_h_kernel(const float* __restrict__ src,
                                   unsigned* __restrict__ p0,
                                   unsigned* __restrict__ p1, int K, int N)
{
    int i = blockIdx.x * blockDim.x + threadIdx.x;
    int total = (K / 2) * N;
    if (i < total) {
        int kp = i / N, n = i - kp * N;
        float f0 = src[(size_t)(2 * kp) * N + n];
        float f1 = src[(size_t)(2 * kp + 1) * N + n];
        __half h0 = __float2half_rn(f0), h1 = __float2half_rn(f1);
        __half l0 = __float2half_rn((f0 - __half2float(h0)) * LOSCALE);
        __half l1 = __float2half_rn((f1 - __half2float(h1)) * LOSCALE);
        __half2 ph = __halves2half2(h0, h1);
        __half2 pl = __halves2half2(l0, l1);
        p0[i] = *(unsigned*)&ph;
        p1[i] = *(unsigned*)&pl;
    }
}

__global__ void splitpack_b_kernel(const float* __restrict__ src,
                                   unsigned* __restrict__ p0,
                                   unsigned* __restrict__ p1, int K, int N)
{
    int i = blockIdx.x * blockDim.x + threadIdx.x;
    int total = (K / 2) * N;
    if (i < total) {
        int kp = i / N, n = i - kp * N;
        float f0 = src[(size_t)(2 * kp) * N + n];
        float f1 = src[(size_t)(2 * kp + 1) * N + n];
        __nv_bfloat16 h0 = __float2bfloat16(f0), h1 = __float2bfloat16(f1);
        __nv_bfloat16 l0 = __float2bfloat16(f0 - __bfloat162float(h0));
        __nv_bfloat16 l1 = __float2bfloat16(f1 - __bfloat162float(h1));
        __nv_bfloat162 ph = __halves2bfloat162(h0, h1);
        __nv_bfloat162 pl = __halves2bfloat162(l0, l1);
        p0[i] = *(unsigned*)&ph;
        p1[i] = *(unsigned*)&pl;
    }
}

// ---------------- fp16 3-term split GEMM, cp.async + ldmatrix + chunk-fold ----------
// REMAP: A rows gathered via kv_src_row (compact KV output).
// BF16OUT: write bf16(acc+bias) to Cb instead of fp32 to C.
#define SMF (2*2*128*40*2 + 2*2*16*132*4)   // 74752
template <bool REMAP, bool BF16OUT>
__global__ void __launch_bounds__(256) gemm_f16_split(
    const __half* __restrict__ A0, const __half* __restrict__ A1,
    const unsigned* __restrict__ B0p, const unsigned* __restrict__ B1p,
    const float* __restrict__ bias, float* __restrict__ C,
    __nv_bfloat16* __restrict__ Cb, int M, int N, int K)
{
    extern __shared__ char sm[];
    typedef __half ATile[2][128][40];
    typedef unsigned BTile[2][16][132];
    ATile* As = (ATile*)sm;
    BTile* Bs = (BTile*)(sm + 2 * 2 * 128 * 40 * 2);

    const int tid = threadIdx.x;
    const int warp = tid >> 5, lane = tid & 31;
    const int wm = warp >> 1, wn = warp & 1;
    const int group = lane >> 2, tig = lane & 3;
    const int m0 = blockIdx.y * 128, n0 = blockIdx.x * 128;

    const int lrow = (lane & 7) + ((lane >> 3) & 1) * 8;
    const int lcol = (lane >> 4) * 8;

    const __half* Ap[2] = {A0, A1};
    const unsigned* Bp[2] = {B0p, B1p};

    const int rA = tid >> 2;
    const int cA = (tid & 3) * 8;
    const int kpB = tid >> 5;
    const int nqB = (tid & 31) * 4;

    // source rows for the two A sub-loads (remapped once; K-loop invariant)
    int srcRow[2];
#pragma unroll
    for (int i = 0; i < 2; i++) {
        int o = m0 + rA + i * 64;
        srcRow[i] = REMAP ? kv_src_row(o) : o;
    }

    auto issue = [&](int k0, int buf) {
#pragma unroll
        for (int p = 0; p < 2; p++) {
#pragma unroll
            for (int i = 0; i < 2; i++) {
                int r = rA + i * 64;
                cp16(&As[buf][p][r][cA], &Ap[p][(size_t)srcRow[i] * K + k0 + cA]);
            }
#pragma unroll
            for (int i = 0; i < 2; i++) {
                int kp = kpB + i * 8;
                cp16(&Bs[buf][p][kp][nqB], &Bp[p][(size_t)(k0 / 2 + kp) * N + n0 + nqB]);
            }
        }
    };

    float acc[2][8][4] = {};

    issue(0, 0);
    CP_COMMIT();
    int buf = 0;

    for (int k0 = 0; k0 < K; k0 += 32) {
        CP_WAIT0();
        __syncthreads();
        if (k0 + 32 < K) {
            issue(k0 + 32, buf ^ 1);
            CP_COMMIT();
        }

        unsigned a[2][2][2][4];   // [part][mt][kk2]
#pragma unroll
        for (int p = 0; p < 2; p++)
#pragma unroll
            for (int mt = 0; mt < 2; mt++)
#pragma unroll
                for (int kk2 = 0; kk2 < 2; kk2++)
                    ldsm_x4(a[p][mt][kk2],
                            &As[buf][p][wm * 32 + mt * 16 + lrow][kk2 * 16 + lcol]);

#pragma unroll
        for (int nt = 0; nt < 8; nt++) {
            const int n = wn * 64 + nt * 8 + group;
            float d0[2][4] = {};
            float d1[2][4] = {};
#pragma unroll
            for (int kk2 = 0; kk2 < 2; kk2++) {
                unsigned b0[2], b1[2];
                b0[0] = Bs[buf][0][kk2 * 8 + tig][n];
                b0[1] = Bs[buf][0][kk2 * 8 + 4 + tig][n];
                b1[0] = Bs[buf][1][kk2 * 8 + tig][n];
                b1[1] = Bs[buf][1][kk2 * 8 + 4 + tig][n];
#pragma unroll
                for (int mt = 0; mt < 2; mt++) {
                    mma_f16(d0[mt], a[0][mt][kk2], b0);
                    mma_f16(d1[mt], a[0][mt][kk2], b1);
                    mma_f16(d1[mt], a[1][mt][kk2], b0);
                }
            }
#pragma unroll
            for (int mt = 0; mt < 2; mt++)
#pragma unroll
                for (int c = 0; c < 4; c++)
                    acc[mt][nt][c] += d0[mt][c] + d1[mt][c] * INV_LOSCALE;
        }
        buf ^= 1;
    }

#pragma unroll
    for (int mt = 0; mt < 2; mt++) {
        const int row = m0 + wm * 32 + mt * 16 + group;
#pragma unroll
        for (int nt = 0; nt < 8; nt++) {
            const int col = n0 + wn * 64 + nt * 8 + tig * 2;
            float b0 = bias[col], b1 = bias[col + 1];
            if (BF16OUT) {
                *(__nv_bfloat162*)&Cb[(size_t)row * N + col] =
                    __floats2bfloat162_rn(acc[mt][nt][0] + b0, acc[mt][nt][1] + b1);
                *(__nv_bfloat162*)&Cb[(size_t)(row + 8) * N + col] =
                    __floats2bfloat162_rn(acc[mt][nt][2] + b0, acc[mt][nt][3] + b1);
            } else {
                C[(size_t)row * N + col]           = acc[mt][nt][0] + b0;
                C[(size_t)row * N + col + 1]       = acc[mt][nt][1] + b1;
                C[(size_t)(row + 8) * N + col]     = acc[mt][nt][2] + b0;
                C[(size_t)(row + 8) * N + col + 1] = acc[mt][nt][3] + b1;
            }
        }
    }
}

// ---------------- bf16 2-term GEMM for Wo, cp.async + ldmatrix + chunk-fold ----------
#define SMW (2*128*40*2 + 2*2*16*132*4)     // 54272
__global__ void __launch_bounds__(256) gemm_wo(
    const __nv_bfloat16* __restrict__ A0,
    const unsigned* __restrict__ B0p, const unsigned* __restrict__ B1p,
    const float* __restrict__ bias, float* __restrict__ C, int M, int N, int K)
{
    extern __shared__ char sm[];
    typedef __nv_bfloat16 ATile[128][40];
    typedef unsigned BTile[2][16][132];
    ATile* As = (ATile*)sm;
    BTile* Bs = (BTile*)(sm + 2 * 128 * 40 * 2);

    const int tid = threadIdx.x;
    const int warp = tid >> 5, lane = tid & 31;
    const int wm = warp >> 1, wn = warp & 1;
    const int group = lane >> 2, tig = lane & 3;
    const int m0 = blockIdx.y * 128, n0 = blockIdx.x * 128;

    const int lrow = (lane & 7) + ((lane >> 3) & 1) * 8;
    const int lcol = (lane >> 4) * 8;

    const unsigned* Bp[2] = {B0p, B1p};
    const int rA = tid >> 2;
    const int cA = (tid & 3) * 8;
    const int kpB = tid >> 5;
    const int nqB = (tid & 31) * 4;

    auto issue = [&](int k0, int buf) {
#pragma unroll
        for (int i = 0; i < 2; i++) {
            int r = rA + i * 64;
            cp16(&As[buf][r][cA], &A0[(size_t)(m0 + r) * K + k0 + cA]);
        }
#pragma unroll
        for (int p = 0; p < 2; p++)
#pragma unroll
            for (int i = 0; i < 2; i++) {
                int kp = kpB + i * 8;
                cp16(&Bs[buf][p][kp][nqB], &Bp[p][(size_t)(k0 / 2 + kp) * N + n0 + nqB]);
            }
    };

    float acc[2][8][4] = {};
    issue(0, 0);
    CP_COMMIT();
    int buf = 0;

    for (int k0 = 0; k0 < K; k0 += 32) {
        CP_WAIT0();
        __syncthreads();
        if (k0 + 32 < K) {
            issue(k0 + 32, buf ^ 1);
            CP_COMMIT();
        }

        unsigned a[2][2][4];
#pragma unroll
        for (int mt = 0; mt < 2; mt++)
#pragma unroll
            for (int kk2 = 0; kk2 < 2; kk2++)
                ldsm_x4(a[mt][kk2], &As[buf][wm * 32 + mt * 16 + lrow][kk2 * 16 + lcol]);

#pragma unroll
        for (int nt = 0; nt < 8; nt++) {
            const int n = wn * 64 + nt * 8 + group;
            float d[2][4] = {};
#pragma unroll
            for (int kk2 = 0; kk2 < 2; kk2++) {
                unsigned b0[2], b1[2];
                b0[0] = Bs[buf][0][kk2 * 8 + tig][n];
                b0[1] = Bs[buf][0][kk2 * 8 + 4 + tig][n];
                b1[0] = Bs[buf][1][kk2 * 8 + tig][n];
                b1[1] = Bs[buf][1][kk2 * 8 + 4 + tig][n];
#pragma unroll
                for (int mt = 0; mt < 2; mt++) {
                    mma_bf16(d[mt], a[mt][kk2], b0);
                    mma_bf16(d[mt], a[mt][kk2], b1);
                }
            }
#pragma unroll
            for (int mt = 0; mt < 2; mt++)
#pragma unroll
                for (int c = 0; c < 4; c++)
                    acc[mt][nt][c] += d[mt][c];
        }
        buf ^= 1;
    }

#pragma unroll
    for (int mt = 0; mt < 2; mt++) {
        const int row = m0 + wm * 32 + mt * 16 + group;
#pragma unroll
        for (int nt = 0; nt < 8; nt++) {
            const int col = n0 + wn * 64 + nt * 8 + tig * 2;
            float b0 = bias[col], b1 = bias[col + 1];
            C[(size_t)row * N + col]           = acc[mt][nt][0] + b0;
            C[(size_t)row * N + col + 1]       = acc[mt][nt][1] + b1;
            C[(size_t)(row + 8) * N + col]     = acc[mt][nt][2] + b0;
            C[(size_t)(row + 8) * N + col + 1] = acc[mt][nt][3] + b1;
        }
    }
}

// ---------------- RMSNorm + 3D RoPE + bf16 pack (Q all rows, K kept rows) ----------
__global__ void rmsrope_kernel(const float* __restrict__ gq, const float* __restrict__ gk,
                               const float* __restrict__ freqs)
{
    const int l = blockIdx.x;
    const int tid = threadIdx.x;
    const int fi = l >> 6;
    const int rem = l & 63;
    const bool keep = (fi & 1) == 0;
    const int kc = (fi >> 1) * 64 + rem;

    const float* qr = g_qraw + (size_t)l * DIM;
    const float* kr = g_kraw + (size_t)kc * DIM;   // compact K rows

    float sq = 0.f, sk = 0.f;
    for (int i = tid; i < DIM; i += TPB) {
        float a = qr[i]; sq += a * a;
        if (keep) { float b = kr[i]; sk += b * b; }
    }
    __shared__ float rq[8], rk[8];
#pragma unroll
    for (int off = 16; off; off >>= 1) {
        sq += __shfl_xor_sync(0xffffffffu, sq, off);
        sk += __shfl_xor_sync(0xffffffffu, sk, off);
    }
    if ((tid & 31) == 0) { rq[tid >> 5] = sq; rk[tid >> 5] = sk; }
    __syncthreads();
    if (tid == 0) {
        float tq = 0.f, tk = 0.f;
        for (int i = 0; i < 8; i++) { tq += rq[i]; tk += rk[i]; }
        rq[0] = rsqrtf(tq / DIM + 1e-6f);
        rk[0] = rsqrtf(tk / DIM + 1e-6f);
    }
    __syncthreads();
    const float invq = rq[0], invk = rk[0];

    const int hi = rem >> 3, wi = rem & 7;

    for (int e = tid; e < NHD * 64; e += TPB) {
        const int n = e >> 6;
        const int p = e & 63;
        float ang;
        if (p < 22)      ang = freqs[fi * 64 + p];
        else if (p < 43) ang = freqs[hi * 64 + p];
        else             ang = freqs[wi * 64 + p];
        float s, c;
        sincosf(ang, &s, &c);
        const int j0 = n * HD + 2 * p;

        float q0 = qr[j0] * invq * gq[j0];
        float q1 = qr[j0 + 1] * invq * gq[j0 + 1];
        g_qb[(size_t)l * DIM + j0]     = __float2bfloat16(q0 * c - q1 * s);
        g_qb[(size_t)l * DIM + j0 + 1] = __float2bfloat16(q0 * s + q1 * c);

        if (keep) {
            float k0v = kr[j0] * invk * gk[j0];
            float k1v = kr[j0 + 1] * invk * gk[j0 + 1];
            g_kb[(size_t)kc * DIM + j0]     = __float2bfloat16(k0v * c - k1v * s);
            g_kb[(size_t)kc * DIM + j0 + 1] = __float2bfloat16(k0v * s + k1v * c);
        }
    }
}

// ---------------- scores via HMMA + fused per-block softmax stats ----------------
__global__ void __launch_bounds__(256) score_gemm_mma(void)
{
    __shared__ __nv_bfloat16 Qs[128][72];
    __shared__ __nv_bfloat16 Ks[128][72];
    __shared__ float sm_m[128][2], sm_s[128][2];
    const int h = blockIdx.z;
    const int mb0 = blockIdx.y * 128, n0 = blockIdx.x * 128;
    const int tid = threadIdx.x;
    const int warp = tid >> 5, lane = tid & 31;
    const int wm = warp >> 1, wn = warp & 1;
    const int group = lane >> 2, tig = lane & 3;

    const __nv_bfloat16* Q  = g_qb + h * HD;
    const __nv_bfloat16* Kb = g_kb + h * HD;

    float acc[2][8][4] = {};

    for (int k0 = 0; k0 < HD; k0 += 64) {
#pragma unroll
        for (int i = 0; i < 4; i++) {
            int idx = tid + i * 256;
            int r = idx >> 3, c = (idx & 7) * 8;
            *(uint4*)&Qs[r][c] = *(const uint4*)&Q [(size_t)(mb0 + r) * DIM + k0 + c];
            *(uint4*)&Ks[r][c] = *(const uint4*)&Kb[(size_t)(n0 + r) * DIM + k0 + c];
        }
        __syncthreads();
#pragma unroll
        for (int kk = 0; kk < 64; kk += 16) {
            unsigned a[2][4], b[8][2];
#pragma unroll
            for (int mt = 0; mt < 2; mt++) {
                const int r = wm * 32 + mt * 16 + group;
                a[mt][0] = *(const unsigned*)&Qs[r][kk + tig * 2];
                a[mt][1] = *(const unsigned*)&Qs[r + 8][kk + tig * 2];
                a[mt][2] = *(const unsigned*)&Qs[r][kk + 8 + tig * 2];
                a[mt][3] = *(const unsigned*)&Qs[r + 8][kk + 8 + tig * 2];
            }
#pragma unroll
            for (int nt = 0; nt < 8; nt++) {
                const int r = wn * 64 + nt * 8 + group;
                b[nt][0] = *(const unsigned*)&Ks[r][kk + tig * 2];
                b[nt][1] = *(const unsigned*)&Ks[r][kk + 8 + tig * 2];
            }
#pragma unroll
            for (int mt = 0; mt < 2; mt++)
#pragma unroll
                for (int nt = 0; nt < 8; nt++)
                    mma_bf16(acc[mt][nt], a[mt], b[nt]);
        }
        __syncthreads();
    }

    __nv_bfloat16* S = g_sc + (size_t)h * SL * LK;
#pragma unroll
    for (int mt = 0; mt < 2; mt++) {
#pragma unroll
        for (int hh = 0; hh < 2; hh++) {
            const int rr = wm * 32 + mt * 16 + group + hh * 8;
            const int row = mb0 + rr;
            float xv[16];
            float mx = -1e30f;
#pragma unroll
            for (int nt = 0; nt < 8; nt++) {
                const int col = n0 + wn * 64 + nt * 8 + tig * 2;
                __nv_bfloat162 b2 = __floats2bfloat162_rn(acc[mt][nt][hh * 2],
                                                          acc[mt][nt][hh * 2 + 1]);
                *(__nv_bfloat162*)&S[(size_t)row * LK + col] = b2;
                float2 f = __bfloat1622float2(b2);
                xv[2 * nt]     = f.x * SM_SCALE;
                xv[2 * nt + 1] = f.y * SM_SCALE;
                mx = fmaxf(mx, fmaxf(xv[2 * nt], xv[2 * nt + 1]));
            }
            mx = fmaxf(mx, __shfl_xor_sync(0xffffffffu, mx, 1));
            mx = fmaxf(mx, __shfl_xor_sync(0xffffffffu, mx, 2));
            float sum = 0.f;
#pragma unroll
            for (int c = 0; c < 16; c++) sum += expf(xv[c] - mx);
            sum += __shfl_xor_sync(0xffffffffu, sum, 1);
            sum += __shfl_xor_sync(0xffffffffu, sum, 2);
            if (tig == 0) { sm_m[rr][wn] = mx; sm_s[rr][wn] = sum; }
        }
    }
    __syncthreads();
    if (tid < 128) {
        float m0v = sm_m[tid][0], m1v = sm_m[tid][1];
        float M = fmaxf(m0v, m1v);
        float Sv = sm_s[tid][0] * expf(m0v - M) + sm_s[tid][1] * expf(m1v - M);
        size_t base = ((size_t)h * SL + mb0 + tid) * NKB + blockIdx.x;
        g_pm[base] = M;
        g_ps[base] = Sv;
    }
}

// ---------------- combine partial stats -> per-row M, 1/Z ----------------
__global__ void combine_kernel(void)
{
    int idx = blockIdx.x * blockDim.x + threadIdx.x;
    if (idx >= NHD * SL) return;
    const float* pm = g_pm + (size_t)idx * NKB;
    const float* ps = g_ps + (size_t)idx * NKB;
    float M = -1e30f;
#pragma unroll
    for (int b = 0; b < NKB; b++) M = fmaxf(M, pm[b]);
    float Z = 0.f;
#pragma unroll
    for (int b = 0; b < NKB; b++) Z += ps[b] * expf(pm[b] - M);
    g_M[idx] = M;
    g_iz[idx] = 1.f / Z;
}

// ---------------- PV via HMMA; probs computed on the fly from raw scores ----------
__global__ void __launch_bounds__(256) pv_gemm_mma(void)
{
    __shared__ __nv_bfloat16 Ps[128][72];
    __shared__ unsigned Vp[32][132];
    __shared__ float sMr[128], sZr[128];
    const int h = blockIdx.z;
    const int m0 = blockIdx.y * 128;
    const int tid = threadIdx.x;
    const int warp = tid >> 5, lane = tid & 31;
    const int wm = warp >> 1, wn = warp & 1;
    const int group = lane >> 2, tig = lane & 3;

    const __nv_bfloat16* P = g_sc + (size_t)h * SL * LK;
    const __nv_bfloat16* V = g_vb + h * HD;

    if (tid < 128) {
        int row = h * SL + m0 + tid;
        sMr[tid] = g_M[row];
        sZr[tid] = g_iz[row];
    }
    __syncthreads();

    float acc[2][8][4] = {};

    for (int k0 = 0; k0 < LK; k0 += 64) {
#pragma unroll
        for (int i = 0; i < 4; i++) {
            int idx = tid + i * 256;
            int r = idx >> 3, c = (idx & 7) * 8;
            uint4 raw = *(const uint4*)&P[(size_t)(m0 + r) * LK + k0 + c];
            float M = sMr[r], iz = sZr[r];
            unsigned* w = &raw.x;
            uint4 o;
            unsigned* ow = &o.x;
#pragma unroll
            for (int j = 0; j < 4; j++) {
                float2 f = __bfloat1622float2(*(__nv_bfloat162*)&w[j]);
                float p0 = expf(f.x * SM_SCALE - M) * iz;
                float p1 = expf(f.y * SM_SCALE - M) * iz;
                __nv_bfloat162 b2 = __floats2bfloat162_rn(p0, p1);
                ow[j] = *(unsigned*)&b2;
            }
            *(uint4*)&Ps[r][c] = o;
        }
#pragma unroll
        for (int i = 0; i < 2; i++) {
            int idx = tid + i * 256;
            int kp = idx >> 4, c = (idx & 15) * 8;
            uint4 a4 = *(const uint4*)&V[(size_t)(k0 + 2 * kp) * DIM + c];
            uint4 b4 = *(const uint4*)&V[(size_t)(k0 + 2 * kp + 1) * DIM + c];
            uint4 p0, p1;
            p0.x = __byte_perm(a4.x, b4.x, 0x5410); p0.y = __byte_perm(a4.x, b4.x, 0x7632);
            p0.z = __byte_perm(a4.y, b4.y, 0x5410); p0.w = __byte_perm(a4.y, b4.y, 0x7632);
            p1.x = __byte_perm(a4.z, b4.z, 0x5410); p1.y = __byte_perm(a4.z, b4.z, 0x7632);
            p1.z = __byte_perm(a4.w, b4.w, 0x5410); p1.w = __byte_perm(a4.w, b4.w, 0x7632);
            *(uint4*)&Vp[kp][c]     = p0;
            *(uint4*)&Vp[kp][c + 4] = p1;
        }
        __syncthreads();
#pragma unroll
        for (int kk = 0; kk < 64; kk += 16) {
            unsigned a[2][4], b[8][2];
#pragma unroll
            for (int mt = 0; mt < 2; mt++) {
                const int r = wm * 32 + mt * 16 + group;
                a[mt][0] = *(const unsigned*)&Ps[r][kk + tig * 2];
                a[mt][1] = *(const unsigned*)&Ps[r + 8][kk + tig * 2];
                a[mt][2] = *(const unsigned*)&Ps[r][kk + 8 + tig * 2];
                a[mt][3] = *(const unsigned*)&Ps[r + 8][kk + 8 + tig * 2];
            }
#pragma unroll
            for (int nt = 0; nt < 8; nt++) {
                const int n = wn * 64 + nt * 8 + group;
                b[nt][0] = Vp[kk / 2 + tig][n];
                b[nt][1] = Vp[kk / 2 + 4 + tig][n];
            }
#pragma unroll
            for (int mt = 0; mt < 2; mt++)
#pragma unroll
                for (int nt = 0; nt < 8; nt++)
                    mma_bf16(acc[mt][nt], a[mt], b[nt]);
        }
        __syncthreads();
    }

#pragma unroll
    for (int mt = 0; mt < 2; mt++) {
        const int row = m0 + wm * 32 + mt * 16 + group;
#pragma unroll
        for (int nt = 0; nt < 8; nt++) {
            const int col = h * HD + wn * 64 + nt * 8 + tig * 2;
            *(__nv_bfloat162*)&g_aob[(size_t)row * DIM + col] =
                __floats2bfloat162_rn(acc[mt][nt][0], acc[mt][nt][1]);
            *(__nv_bfloat162*)&g_aob[(size_t)(row + 8) * DIM + col] =
                __floats2bfloat162_rn(acc[mt][nt][2], acc[mt][nt][3]);
        }
    }
}

// ---------------- launch ----------------
extern "C" void kernel_launch(void* const* d_in, const int* in_sizes, int n_in,
                              void* d_out, int out_size)
{
    const float* x     = (const float*)d_in[0];
    const float* freqs = (const float*)d_in[1];
    const float* Wq    = (const float*)d_in[2];
    const float* bq    = (const float*)d_in[3];
    const float* Wk    = (const float*)d_in[4];
    const float* bk    = (const float*)d_in[5];
    const float* Wv    = (const float*)d_in[6];
    const float* bv    = (const float*)d_in[7];
    const float* Wo    = (const float*)d_in[8];
    const float* bo    = (const float*)d_in[9];
    const float* gq    = (const float*)d_in[10];
    const float* gk    = (const float*)d_in[11];
    float* out = (float*)d_out;

    float *qraw, *kraw;
    __half *xh;
    unsigned *whp, *wop;
    __nv_bfloat16 *aob, *vb;
    cudaGetSymbolAddress((void**)&qraw, g_qraw);
    cudaGetSymbolAddress((void**)&kraw, g_kraw);
    cudaGetSymbolAddress((void**)&xh,   g_xh);
    cudaGetSymbolAddress((void**)&whp,  g_whp);
    cudaGetSymbolAddress((void**)&wop,  g_wop);
    cudaGetSymbolAddress((void**)&aob,  g_aob);
    cudaGetSymbolAddress((void**)&vb,   g_vb);

    const size_t WPS = (size_t)(DIM / 2) * DIM;
    __half* xp[2];
    for (int i = 0; i < 2; i++) xp[i] = xh + (size_t)i * SL * DIM;
    unsigned* wp[6];
    for (int i = 0; i < 6; i++) wp[i] = whp + (size_t)i * WPS;
    unsigned* wo[2];
    for (int i = 0; i < 2; i++) wo[i] = wop + (size_t)i * WPS;

    cudaFuncSetAttribute(gemm_f16_split<false, false>,
                         cudaFuncAttributeMaxDynamicSharedMemorySize, SMF);
    cudaFuncSetAttribute(gemm_f16_split<true, false>,
                         cudaFuncAttributeMaxDynamicSharedMemorySize, SMF);
    cudaFuncSetAttribute(gemm_f16_split<true, true>,
                         cudaFuncAttributeMaxDynamicSharedMemorySize, SMF);
    cudaFuncSetAttribute(gemm_wo, cudaFuncAttributeMaxDynamicSharedMemorySize, SMW);

    dim3 blk(TPB);
    const int nw = (DIM / 2) * DIM;

    split2h_kernel<<<(SL * DIM + TPB - 1) / TPB, blk>>>(x, xp[0], xp[1], SL * DIM);
    splitpack_h_kernel<<<(nw + TPB - 1) / TPB, blk>>>(Wq, wp[0], wp[1], DIM, DIM);
    splitpack_h_kernel<<<(nw + TPB - 1) / TPB, blk>>>(Wk, wp[2], wp[3], DIM, DIM);
    splitpack_h_kernel<<<(nw + TPB - 1) / TPB, blk>>>(Wv, wp[4], wp[5], DIM, DIM);
    splitpack_b_kernel<<<(nw + TPB - 1) / TPB, blk>>>(Wo, wo[0], wo[1], DIM, DIM);

    dim3 gProjQ(DIM / 128, SL / 128);         // (12, 50)
    dim3 gProjKV(DIM / 128, LK / 128);        // (12, 25) — kept rows only
    gemm_f16_split<false, false><<<gProjQ, blk, SMF>>>(
        xp[0], xp[1], wp[0], wp[1], bq, qraw, nullptr, SL, DIM, DIM);
    gemm_f16_split<true, false><<<gProjKV, blk, SMF>>>(
        xp[0], xp[1], wp[2], wp[3], bk, kraw, nullptr, LK, DIM, DIM);
    gemm_f16_split<true, true><<<gProjKV, blk, SMF>>>(
        xp[0], xp[1], wp[4], wp[5], bv, nullptr, vb, LK, DIM, DIM);

    rmsrope_kernel<<<SL, blk>>>(gq, gk, freqs);

    dim3 gScore(LK / 128, SL / 128, NHD);     // (25, 50, 12)
    score_gemm_mma<<<gScore, blk>>>();

    combine_kernel<<<(NHD * SL + TPB - 1) / TPB, blk>>>();

    dim3 gPV(1, SL / 128, NHD);
    pv_gemm_mma<<<gPV, blk>>>();

    gemm_wo<<<gProjQ, blk, SMW>>>(aob, wo[0], wo[1], bo, out, SL, DIM, DIM);
}

// round 11
// speedup vs baseline: 4.5464x; 1.0491x over previous
#include <cuda_runtime.h>
#include <cuda_bf16.h>
#include <cuda_fp16.h>

#define DIM 1536
#define NHD 12
#define HD  128
#define SL  6400      // query length (100*8*8)
#define LK  3200      // kv length after even-frame subsample (50*64)
#define TPB 256
#define NKB (LK / 128)   // 25 score col-blocks per row

#define LOSCALE 2048.0f
#define INV_LOSCALE 4.8828125e-4f   // 1/2048
#define SM_SCALE 0.088388347648318447f  // 1/sqrt(128)

// ---------------- scratch (static device arrays; no allocs) ----------------
__device__ float g_qraw[SL * DIM];
__device__ float g_kraw[LK * DIM];                     // only kept rows
__device__ __half g_xh[2][SL * DIM];                   // x fp16 2-split (lo scaled)
__device__ unsigned g_whp[6][(DIM / 2) * DIM];         // Wq,Wk,Wv fp16 2-splits, k-pair packed
__device__ unsigned g_wop[2][(DIM / 2) * DIM];         // Wo bf16 2-split, k-pair packed
__device__ __nv_bfloat16 g_qb[SL * DIM];
__device__ __nv_bfloat16 g_kb[LK * DIM];
__device__ __nv_bfloat16 g_vb[LK * DIM];
__device__ unsigned g_vpk[(LK / 2) * DIM];             // V k-pair packed {V[2k],V[2k+1]}
__device__ __nv_bfloat16 g_sc[(size_t)NHD * SL * LK];  // 491.5 MB raw bf16 scores
__device__ float g_pm[NHD * SL * NKB];                 // per-block row max
__device__ float g_ps[NHD * SL * NKB];                 // per-block row sum-exp
__device__ float g_M[NHD * SL];                        // row max (global)
__device__ float g_iz[NHD * SL];                       // 1/Z per row
__device__ __nv_bfloat16 g_aob[SL * DIM];              // attention output, bf16 (per reference)

// ---------------- warp-level MMA helpers ----------------
__device__ __forceinline__ void mma_bf16(float* d, const unsigned* a, const unsigned* b)
{
    asm volatile(
        "mma.sync.aligned.m16n8k16.row.col.f32.bf16.bf16.f32 "
        "{%0,%1,%2,%3}, {%4,%5,%6,%7}, {%8,%9}, {%0,%1,%2,%3};\n"
        : "+f"(d[0]), "+f"(d[1]), "+f"(d[2]), "+f"(d[3])
        : "r"(a[0]), "r"(a[1]), "r"(a[2]), "r"(a[3]), "r"(b[0]), "r"(b[1]));
}

__device__ __forceinline__ void mma_f16(float* d, const unsigned* a, const unsigned* b)
{
    asm volatile(
        "mma.sync.aligned.m16n8k16.row.col.f32.f16.f16.f32 "
        "{%0,%1,%2,%3}, {%4,%5,%6,%7}, {%8,%9}, {%0,%1,%2,%3};\n"
        : "+f"(d[0]), "+f"(d[1]), "+f"(d[2]), "+f"(d[3])
        : "r"(a[0]), "r"(a[1]), "r"(a[2]), "r"(a[3]), "r"(b[0]), "r"(b[1]));
}

__device__ __forceinline__ void ldsm_x4(unsigned* a, const void* p)
{
    unsigned addr = (unsigned)__cvta_generic_to_shared(p);
    asm volatile("ldmatrix.sync.aligned.m8n8.x4.shared.b16 {%0,%1,%2,%3}, [%4];"
                 : "=r"(a[0]), "=r"(a[1]), "=r"(a[2]), "=r"(a[3]) : "r"(addr));
}

__device__ __forceinline__ void cp16(void* dst_smem, const void* src)
{
    unsigned d = (unsigned)__cvta_generic_to_shared(dst_smem);
    asm volatile("cp.async.cg.shared.global [%0], [%1], 16;\n" :: "r"(d), "l"(src));
}
#define CP_COMMIT() asm volatile("cp.async.commit_group;\n")
#define CP_WAIT0()  asm volatile("cp.async.wait_group 0;\n")

// expand compact kv row index -> original sequence row (even frames only)
__device__ __forceinline__ int kv_src_row(int kc) { return kc + ((kc >> 6) << 6); }

// raw bf16 score pair -> bf16 prob pair (exact reference path: expf(x*s - M)*iz)
__device__ __forceinline__ unsigned exp_cvt(unsigned raw, float M, float iz)
{
    float2 f = __bfloat1622float2(*(__nv_bfloat162*)&raw);
    float p0 = expf(f.x * SM_SCALE - M) * iz;
    float p1 = expf(f.y * SM_SCALE - M) * iz;
    __nv_bfloat162 b2 = __floats2bfloat162_rn(p0, p1);
    return *(unsigned*)&b2;
}

// ---------------- splits ----------------
__global__ void split2h_kernel(const float* __restrict__ src,
                               __half* __restrict__ h0,
                               __half* __restrict__ h1, int n)
{
    int i = blockIdx.x * blockDim.x + threadIdx.x;
    if (i < n) {
        float f = src[i];
        __half a = __float2half_rn(f);
        float r = f - __half2float(a);
        h0[i] = a;
        h1[i] = __float2half_rn(r * LOSCALE);
    }
}

__global__ void splitpack_h_kernel(const float* __restrict__ src,
                                   unsigned* __restrict__ p0,
                                   unsigned* __restrict__ p1, int K, int N)
{
    int i = blockIdx.x * blockDim.x + threadIdx.x;
    int total = (K / 2) * N;
    if (i < total) {
        int kp = i / N, n = i - kp * N;
        float f0 = src[(size_t)(2 * kp) * N + n];
        float f1 = src[(size_t)(2 * kp + 1) * N + n];
        __half h0 = __float2half_rn(f0), h1 = __float2half_rn(f1);
        __half l0 = __float2half_rn((f0 - __half2float(h0)) * LOSCALE);
        __half l1 = __float2half_rn((f1 - __half2float(h1)) * LOSCALE);
        __half2 ph = __halves2half2(h0, h1);
        __half2 pl = __halves2half2(l0, l1);
        p0[i] = *(unsigned*)&ph;
        p1[i] = *(unsigned*)&pl;
    }
}

__global__ void splitpack_b_kernel(const float* __restrict__ src,
                                   unsigned* __restrict__ p0,
                                   unsigned* __restrict__ p1, int K, int N)
{
    int i = blockIdx.x * blockDim.x + threadIdx.x;
    int total = (K / 2) * N;
    if (i < total) {
        int kp = i / N, n = i - kp * N;
        float f0 = src[(size_t)(2 * kp) * N + n];
        float f1 = src[(size_t)(2 * kp + 1) * N + n];
        __nv_bfloat16 h0 = __float2bfloat16(f0), h1 = __float2bfloat16(f1);
        __nv_bfloat16 l0 = __float2bfloat16(f0 - __bfloat162float(h0));
        __nv_bfloat16 l1 = __float2bfloat16(f1 - __bfloat162float(h1));
        __nv_bfloat162 ph = __halves2bfloat162(h0, h1);
        __nv_bfloat162 pl = __halves2bfloat162(l0, l1);
        p0[i] = *(unsigned*)&ph;
        p1[i] = *(unsigned*)&pl;
    }
}

// pack V k-pairs: g_vpk[kp*DIM + n] = {V[2kp][n], V[2kp+1][n]}
__global__ void vpack_kernel(void)
{
    int i = blockIdx.x * blockDim.x + threadIdx.x;
    if (i < (LK / 2) * DIM) {
        int kp = i / DIM, n = i - kp * DIM;
        __nv_bfloat162 b2 = __halves2bfloat162(g_vb[(size_t)(2 * kp) * DIM + n],
                                               g_vb[(size_t)(2 * kp + 1) * DIM + n]);
        g_vpk[i] = *(unsigned*)&b2;
    }
}

// ---------------- fp16 3-term split GEMM, cp.async + ldmatrix + chunk-fold ----------
#define SMF (2*2*128*40*2 + 2*2*16*132*4)   // 74752
template <bool REMAP, bool BF16OUT>
__global__ void __launch_bounds__(256) gemm_f16_split(
    const __half* __restrict__ A0, const __half* __restrict__ A1,
    const unsigned* __restrict__ B0p, const unsigned* __restrict__ B1p,
    const float* __restrict__ bias, float* __restrict__ C,
    __nv_bfloat16* __restrict__ Cb, int M, int N, int K)
{
    extern __shared__ char sm[];
    typedef __half ATile[2][128][40];
    typedef unsigned BTile[2][16][132];
    ATile* As = (ATile*)sm;
    BTile* Bs = (BTile*)(sm + 2 * 2 * 128 * 40 * 2);

    const int tid = threadIdx.x;
    const int warp = tid >> 5, lane = tid & 31;
    const int wm = warp >> 1, wn = warp & 1;
    const int group = lane >> 2, tig = lane & 3;
    const int m0 = blockIdx.y * 128, n0 = blockIdx.x * 128;

    const int lrow = (lane & 7) + ((lane >> 3) & 1) * 8;
    const int lcol = (lane >> 4) * 8;

    const __half* Ap[2] = {A0, A1};
    const unsigned* Bp[2] = {B0p, B1p};

    const int rA = tid >> 2;
    const int cA = (tid & 3) * 8;
    const int kpB = tid >> 5;
    const int nqB = (tid & 31) * 4;

    int srcRow[2];
#pragma unroll
    for (int i = 0; i < 2; i++) {
        int o = m0 + rA + i * 64;
        srcRow[i] = REMAP ? kv_src_row(o) : o;
    }

    auto issue = [&](int k0, int buf) {
#pragma unroll
        for (int p = 0; p < 2; p++) {
#pragma unroll
            for (int i = 0; i < 2; i++) {
                int r = rA + i * 64;
                cp16(&As[buf][p][r][cA], &Ap[p][(size_t)srcRow[i] * K + k0 + cA]);
            }
#pragma unroll
            for (int i = 0; i < 2; i++) {
                int kp = kpB + i * 8;
                cp16(&Bs[buf][p][kp][nqB], &Bp[p][(size_t)(k0 / 2 + kp) * N + n0 + nqB]);
            }
        }
    };

    float acc[2][8][4] = {};

    issue(0, 0);
    CP_COMMIT();
    int buf = 0;

    for (int k0 = 0; k0 < K; k0 += 32) {
        CP_WAIT0();
        __syncthreads();
        if (k0 + 32 < K) {
            issue(k0 + 32, buf ^ 1);
            CP_COMMIT();
        }

        unsigned a[2][2][2][4];   // [part][mt][kk2]
#pragma unroll
        for (int p = 0; p < 2; p++)
#pragma unroll
            for (int mt = 0; mt < 2; mt++)
#pragma unroll
                for (int kk2 = 0; kk2 < 2; kk2++)
                    ldsm_x4(a[p][mt][kk2],
                            &As[buf][p][wm * 32 + mt * 16 + lrow][kk2 * 16 + lcol]);

#pragma unroll
        for (int nt = 0; nt < 8; nt++) {
            const int n = wn * 64 + nt * 8 + group;
            float d0[2][4] = {};
            float d1[2][4] = {};
#pragma unroll
            for (int kk2 = 0; kk2 < 2; kk2++) {
                unsigned b0[2], b1[2];
                b0[0] = Bs[buf][0][kk2 * 8 + tig][n];
                b0[1] = Bs[buf][0][kk2 * 8 + 4 + tig][n];
                b1[0] = Bs[buf][1][kk2 * 8 + tig][n];
                b1[1] = Bs[buf][1][kk2 * 8 + 4 + tig][n];
#pragma unroll
                for (int mt = 0; mt < 2; mt++) {
                    mma_f16(d0[mt], a[0][mt][kk2], b0);
                    mma_f16(d1[mt], a[0][mt][kk2], b1);
                    mma_f16(d1[mt], a[1][mt][kk2], b0);
                }
            }
#pragma unroll
            for (int mt = 0; mt < 2; mt++)
#pragma unroll
                for (int c = 0; c < 4; c++)
                    acc[mt][nt][c] += d0[mt][c] + d1[mt][c] * INV_LOSCALE;
        }
        buf ^= 1;
    }

#pragma unroll
    for (int mt = 0; mt < 2; mt++) {
        const int row = m0 + wm * 32 + mt * 16 + group;
#pragma unroll
        for (int nt = 0; nt < 8; nt++) {
            const int col = n0 + wn * 64 + nt * 8 + tig * 2;
            float b0 = bias[col], b1 = bias[col + 1];
            if (BF16OUT) {
                *(__nv_bfloat162*)&Cb[(size_t)row * N + col] =
                    __floats2bfloat162_rn(acc[mt][nt][0] + b0, acc[mt][nt][1] + b1);
                *(__nv_bfloat162*)&Cb[(size_t)(row + 8) * N + col] =
                    __floats2bfloat162_rn(acc[mt][nt][2] + b0, acc[mt][nt][3] + b1);
            } else {
                C[(size_t)row * N + col]           = acc[mt][nt][0] + b0;
                C[(size_t)row * N + col + 1]       = acc[mt][nt][1] + b1;
                C[(size_t)(row + 8) * N + col]     = acc[mt][nt][2] + b0;
                C[(size_t)(row + 8) * N + col + 1] = acc[mt][nt][3] + b1;
            }
        }
    }
}

// ---------------- bf16 2-term GEMM for Wo, cp.async + ldmatrix + chunk-fold ----------
#define SMW (2*128*40*2 + 2*2*16*132*4)     // 54272
__global__ void __launch_bounds__(256) gemm_wo(
    const __nv_bfloat16* __restrict__ A0,
    const unsigned* __restrict__ B0p, const unsigned* __restrict__ B1p,
    const float* __restrict__ bias, float* __restrict__ C, int M, int N, int K)
{
    extern __shared__ char sm[];
    typedef __nv_bfloat16 ATile[128][40];
    typedef unsigned BTile[2][16][132];
    ATile* As = (ATile*)sm;
    BTile* Bs = (BTile*)(sm + 2 * 128 * 40 * 2);

    const int tid = threadIdx.x;
    const int warp = tid >> 5, lane = tid & 31;
    const int wm = warp >> 1, wn = warp & 1;
    const int group = lane >> 2, tig = lane & 3;
    const int m0 = blockIdx.y * 128, n0 = blockIdx.x * 128;

    const int lrow = (lane & 7) + ((lane >> 3) & 1) * 8;
    const int lcol = (lane >> 4) * 8;

    const unsigned* Bp[2] = {B0p, B1p};
    const int rA = tid >> 2;
    const int cA = (tid & 3) * 8;
    const int kpB = tid >> 5;
    const int nqB = (tid & 31) * 4;

    auto issue = [&](int k0, int buf) {
#pragma unroll
        for (int i = 0; i < 2; i++) {
            int r = rA + i * 64;
            cp16(&As[buf][r][cA], &A0[(size_t)(m0 + r) * K + k0 + cA]);
        }
#pragma unroll
        for (int p = 0; p < 2; p++)
#pragma unroll
            for (int i = 0; i < 2; i++) {
                int kp = kpB + i * 8;
                cp16(&Bs[buf][p][kp][nqB], &Bp[p][(size_t)(k0 / 2 + kp) * N + n0 + nqB]);
            }
    };

    float acc[2][8][4] = {};
    issue(0, 0);
    CP_COMMIT();
    int buf = 0;

    for (int k0 = 0; k0 < K; k0 += 32) {
        CP_WAIT0();
        __syncthreads();
        if (k0 + 32 < K) {
            issue(k0 + 32, buf ^ 1);
            CP_COMMIT();
        }

        unsigned a[2][2][4];
#pragma unroll
        for (int mt = 0; mt < 2; mt++)
#pragma unroll
            for (int kk2 = 0; kk2 < 2; kk2++)
                ldsm_x4(a[mt][kk2], &As[buf][wm * 32 + mt * 16 + lrow][kk2 * 16 + lcol]);

#pragma unroll
        for (int nt = 0; nt < 8; nt++) {
            const int n = wn * 64 + nt * 8 + group;
            float d[2][4] = {};
#pragma unroll
            for (int kk2 = 0; kk2 < 2; kk2++) {
                unsigned b0[2], b1[2];
                b0[0] = Bs[buf][0][kk2 * 8 + tig][n];
                b0[1] = Bs[buf][0][kk2 * 8 + 4 + tig][n];
                b1[0] = Bs[buf][1][kk2 * 8 + tig][n];
                b1[1] = Bs[buf][1][kk2 * 8 + 4 + tig][n];
#pragma unroll
                for (int mt = 0; mt < 2; mt++) {
                    mma_bf16(d[mt], a[mt][kk2], b0);
                    mma_bf16(d[mt], a[mt][kk2], b1);
                }
            }
#pragma unroll
            for (int mt = 0; mt < 2; mt++)
#pragma unroll
                for (int c = 0; c < 4; c++)
                    acc[mt][nt][c] += d[mt][c];
        }
        buf ^= 1;
    }

#pragma unroll
    for (int mt = 0; mt < 2; mt++) {
        const int row = m0 + wm * 32 + mt * 16 + group;
#pragma unroll
        for (int nt = 0; nt < 8; nt++) {
            const int col = n0 + wn * 64 + nt * 8 + tig * 2;
            float b0 = bias[col], b1 = bias[col + 1];
            C[(size_t)row * N + col]           = acc[mt][nt][0] + b0;
            C[(size_t)row * N + col + 1]       = acc[mt][nt][1] + b1;
            C[(size_t)(row + 8) * N + col]     = acc[mt][nt][2] + b0;
            C[(size_t)(row + 8) * N + col + 1] = acc[mt][nt][3] + b1;
        }
    }
}

// ---------------- RMSNorm + 3D RoPE + bf16 pack (Q all rows, K kept rows) ----------
__global__ void rmsrope_kernel(const float* __restrict__ gq, const float* __restrict__ gk,
                               const float* __restrict__ freqs)
{
    const int l = blockIdx.x;
    const int tid = threadIdx.x;
    const int fi = l >> 6;
    const int rem = l & 63;
    const bool keep = (fi & 1) == 0;
    const int kc = (fi >> 1) * 64 + rem;

    const float* qr = g_qraw + (size_t)l * DIM;
    const float* kr = g_kraw + (size_t)kc * DIM;

    float sq = 0.f, sk = 0.f;
    for (int i = tid; i < DIM; i += TPB) {
        float a = qr[i]; sq += a * a;
        if (keep) { float b = kr[i]; sk += b * b; }
    }
    __shared__ float rq[8], rk[8];
#pragma unroll
    for (int off = 16; off; off >>= 1) {
        sq += __shfl_xor_sync(0xffffffffu, sq, off);
        sk += __shfl_xor_sync(0xffffffffu, sk, off);
    }
    if ((tid & 31) == 0) { rq[tid >> 5] = sq; rk[tid >> 5] = sk; }
    __syncthreads();
    if (tid == 0) {
        float tq = 0.f, tk = 0.f;
        for (int i = 0; i < 8; i++) { tq += rq[i]; tk += rk[i]; }
        rq[0] = rsqrtf(tq / DIM + 1e-6f);
        rk[0] = rsqrtf(tk / DIM + 1e-6f);
    }
    __syncthreads();
    const float invq = rq[0], invk = rk[0];

    const int hi = rem >> 3, wi = rem & 7;

    for (int e = tid; e < NHD * 64; e += TPB) {
        const int n = e >> 6;
        const int p = e & 63;
        float ang;
        if (p < 22)      ang = freqs[fi * 64 + p];
        else if (p < 43) ang = freqs[hi * 64 + p];
        else             ang = freqs[wi * 64 + p];
        float s, c;
        sincosf(ang, &s, &c);
        const int j0 = n * HD + 2 * p;

        float q0 = qr[j0] * invq * gq[j0];
        float q1 = qr[j0 + 1] * invq * gq[j0 + 1];
        g_qb[(size_t)l * DIM + j0]     = __float2bfloat16(q0 * c - q1 * s);
        g_qb[(size_t)l * DIM + j0 + 1] = __float2bfloat16(q0 * s + q1 * c);

        if (keep) {
            float k0v = kr[j0] * invk * gk[j0];
            float k1v = kr[j0 + 1] * invk * gk[j0 + 1];
            g_kb[(size_t)kc * DIM + j0]     = __float2bfloat16(k0v * c - k1v * s);
            g_kb[(size_t)kc * DIM + j0 + 1] = __float2bfloat16(k0v * s + k1v * c);
        }
    }
}

// ---------------- scores via HMMA + fused per-block softmax stats ----------------
// Full K=128 tiles loaded via cp.async upfront, single sync, unrolled kk loop.
#define SMS (2 * 128 * 136 * 2)   // 69632
__global__ void __launch_bounds__(256) score_gemm_mma(void)
{
    extern __shared__ char sm[];
    typedef __nv_bfloat16 Row136[136];
    Row136* Qs = (Row136*)sm;
    Row136* Ks = (Row136*)(sm + 128 * 136 * 2);
    __shared__ float sm_m[128][2], sm_s[128][2];

    const int h = blockIdx.z;
    const int mb0 = blockIdx.y * 128, n0 = blockIdx.x * 128;
    const int tid = threadIdx.x;
    const int warp = tid >> 5, lane = tid & 31;
    const int wm = warp >> 1, wn = warp & 1;
    const int group = lane >> 2, tig = lane & 3;

    const __nv_bfloat16* Q  = g_qb + h * HD;
    const __nv_bfloat16* Kb = g_kb + h * HD;

#pragma unroll
    for (int i = 0; i < 8; i++) {
        int idx = tid + i * 256;
        int r = idx >> 4, c = (idx & 15) * 8;
        cp16(&Qs[r][c], &Q [(size_t)(mb0 + r) * DIM + c]);
        cp16(&Ks[r][c], &Kb[(size_t)(n0 + r) * DIM + c]);
    }
    CP_COMMIT();

    float acc[2][8][4] = {};

    CP_WAIT0();
    __syncthreads();

#pragma unroll
    for (int kk = 0; kk < HD; kk += 16) {
        unsigned a[2][4], b[8][2];
#pragma unroll
        for (int mt = 0; mt < 2; mt++) {
            const int r = wm * 32 + mt * 16 + group;
            a[mt][0] = *(const unsigned*)&Qs[r][kk + tig * 2];
            a[mt][1] = *(const unsigned*)&Qs[r + 8][kk + tig * 2];
            a[mt][2] = *(const unsigned*)&Qs[r][kk + 8 + tig * 2];
            a[mt][3] = *(const unsigned*)&Qs[r + 8][kk + 8 + tig * 2];
        }
#pragma unroll
        for (int nt = 0; nt < 8; nt++) {
            const int r = wn * 64 + nt * 8 + group;
            b[nt][0] = *(const unsigned*)&Ks[r][kk + tig * 2];
            b[nt][1] = *(const unsigned*)&Ks[r][kk + 8 + tig * 2];
        }
#pragma unroll
        for (int mt = 0; mt < 2; mt++)
#pragma unroll
            for (int nt = 0; nt < 8; nt++)
                mma_bf16(acc[mt][nt], a[mt], b[nt]);
    }

    __nv_bfloat16* S = g_sc + (size_t)h * SL * LK;
#pragma unroll
    for (int mt = 0; mt < 2; mt++) {
#pragma unroll
        for (int hh = 0; hh < 2; hh++) {
            const int rr = wm * 32 + mt * 16 + group + hh * 8;
            const int row = mb0 + rr;
            float xv[16];
            float mx = -1e30f;
#pragma unroll
            for (int nt = 0; nt < 8; nt++) {
                const int col = n0 + wn * 64 + nt * 8 + tig * 2;
                __nv_bfloat162 b2 = __floats2bfloat162_rn(acc[mt][nt][hh * 2],
                                                          acc[mt][nt][hh * 2 + 1]);
                *(__nv_bfloat162*)&S[(size_t)row * LK + col] = b2;
                float2 f = __bfloat1622float2(b2);
                xv[2 * nt]     = f.x * SM_SCALE;
                xv[2 * nt + 1] = f.y * SM_SCALE;
                mx = fmaxf(mx, fmaxf(xv[2 * nt], xv[2 * nt + 1]));
            }
            mx = fmaxf(mx, __shfl_xor_sync(0xffffffffu, mx, 1));
            mx = fmaxf(mx, __shfl_xor_sync(0xffffffffu, mx, 2));
            float sum = 0.f;
#pragma unroll
            for (int c = 0; c < 16; c++) sum += expf(xv[c] - mx);
            sum += __shfl_xor_sync(0xffffffffu, sum, 1);
            sum += __shfl_xor_sync(0xffffffffu, sum, 2);
            if (tig == 0) { sm_m[rr][wn] = mx; sm_s[rr][wn] = sum; }
        }
    }
    __syncthreads();
    if (tid < 128) {
        float m0v = sm_m[tid][0], m1v = sm_m[tid][1];
        float M = fmaxf(m0v, m1v);
        float Sv = sm_s[tid][0] * expf(m0v - M) + sm_s[tid][1] * expf(m1v - M);
        size_t base = ((size_t)h * SL + mb0 + tid) * NKB + blockIdx.x;
        g_pm[base] = M;
        g_ps[base] = Sv;
    }
}

// ---------------- combine partial stats -> per-row M, 1/Z ----------------
__global__ void combine_kernel(void)
{
    int idx = blockIdx.x * blockDim.x + threadIdx.x;
    if (idx >= NHD * SL) return;
    const float* pm = g_pm + (size_t)idx * NKB;
    const float* ps = g_ps + (size_t)idx * NKB;
    float M = -1e30f;
#pragma unroll
    for (int b = 0; b < NKB; b++) M = fmaxf(M, pm[b]);
    float Z = 0.f;
#pragma unroll
    for (int b = 0; b < NKB; b++) Z += ps[b] * expf(pm[b] - M);
    g_M[idx] = M;
    g_iz[idx] = 1.f / Z;
}

// ---------------- PV via HMMA; cp.async double-buffered; exp in frag build ----------
// 8 warps each own 16 m-rows x full 128 n. Probs converted once per element.
#define SMPV (2*128*72*2 + 2*32*132*4)   // 70656
__global__ void __launch_bounds__(256) pv_gemm_mma(void)
{
    extern __shared__ char sm[];
    typedef __nv_bfloat16 PRow[72];
    typedef unsigned VRow[132];
    PRow* Praw = (PRow*)sm;                       // [2 buf][128 rows]
    VRow* Vps  = (VRow*)(sm + 2 * 128 * 72 * 2);  // [2 buf][32 kp-rows]
    __shared__ float sMr[128], sZr[128];

    const int h = blockIdx.z;
    const int m0 = blockIdx.y * 128;
    const int tid = threadIdx.x;
    const int warp = tid >> 5, lane = tid & 31;
    const int group = lane >> 2, tig = lane & 3;

    const __nv_bfloat16* P = g_sc + (size_t)h * SL * LK;
    const unsigned* Vg = g_vpk + h * HD;

    if (tid < 128) {
        int row = h * SL + m0 + tid;
        sMr[tid] = g_M[row];
        sZr[tid] = g_iz[row];
    }

    auto issue = [&](int k0, int buf) {
#pragma unroll
        for (int i = 0; i < 4; i++) {
            int idx = tid + i * 256;
            int r = idx >> 3, c = (idx & 7) * 8;
            cp16(&Praw[buf * 128 + r][c], &P[(size_t)(m0 + r) * LK + k0 + c]);
        }
#pragma unroll
        for (int i = 0; i < 4; i++) {
            int idx = tid + i * 256;
            int kpr = idx >> 5, cq = (idx & 31) * 4;
            cp16(&Vps[buf * 32 + kpr][cq], &Vg[(size_t)(k0 / 2 + kpr) * DIM + cq]);
        }
    };

    issue(0, 0);
    CP_COMMIT();
    int buf = 0;

    __syncthreads();   // sMr/sZr visible
    const int rloc = warp * 16 + group;
    const float M0 = sMr[rloc], iz0 = sZr[rloc];
    const float M1 = sMr[rloc + 8], iz1 = sZr[rloc + 8];

    float acc[16][4] = {};

    for (int k0 = 0; k0 < LK; k0 += 64) {
        CP_WAIT0();
        __syncthreads();
        if (k0 + 64 < LK) {
            issue(k0 + 64, buf ^ 1);
            CP_COMMIT();
        }

#pragma unroll
        for (int kk = 0; kk < 64; kk += 16) {
            unsigned a[4];
            a[0] = exp_cvt(*(const unsigned*)&Praw[buf * 128 + rloc][kk + tig * 2], M0, iz0);
            a[1] = exp_cvt(*(const unsigned*)&Praw[buf * 128 + rloc + 8][kk + tig * 2], M1, iz1);
            a[2] = exp_cvt(*(const unsigned*)&Praw[buf * 128 + rloc][kk + 8 + tig * 2], M0, iz0);
            a[3] = exp_cvt(*(const unsigned*)&Praw[buf * 128 + rloc + 8][kk + 8 + tig * 2], M1, iz1);
#pragma unroll
            for (int nt = 0; nt < 16; nt++) {
                unsigned b[2];
                b[0] = Vps[buf * 32 + kk / 2 + tig][nt * 8 + group];
                b[1] = Vps[buf * 32 + kk / 2 + 4 + tig][nt * 8 + group];
                mma_bf16(acc[nt], a, b);
            }
        }
        buf ^= 1;
    }

    const int row = m0 + rloc;
#pragma unroll
    for (int nt = 0; nt < 16; nt++) {
        const int col = h * HD + nt * 8 + tig * 2;
        *(__nv_bfloat162*)&g_aob[(size_t)row * DIM + col] =
            __floats2bfloat162_rn(acc[nt][0], acc[nt][1]);
        *(__nv_bfloat162*)&g_aob[(size_t)(row + 8) * DIM + col] =
            __floats2bfloat162_rn(acc[nt][2], acc[nt][3]);
    }
}

// ---------------- launch ----------------
extern "C" void kernel_launch(void* const* d_in, const int* in_sizes, int n_in,
                              void* d_out, int out_size)
{
    const float* x     = (const float*)d_in[0];
    const float* freqs = (const float*)d_in[1];
    const float* Wq    = (const float*)d_in[2];
    const float* bq    = (const float*)d_in[3];
    const float* Wk    = (const float*)d_in[4];
    const float* bk    = (const float*)d_in[5];
    const float* Wv    = (const float*)d_in[6];
    const float* bv    = (const float*)d_in[7];
    const float* Wo    = (const float*)d_in[8];
    const float* bo    = (const float*)d_in[9];
    const float* gq    = (const float*)d_in[10];
    const float* gk    = (const float*)d_in[11];
    float* out = (float*)d_out;

    float *qraw, *kraw;
    __half *xh;
    unsigned *whp, *wop;
    __nv_bfloat16 *aob, *vb;
    cudaGetSymbolAddress((void**)&qraw, g_qraw);
    cudaGetSymbolAddress((void**)&kraw, g_kraw);
    cudaGetSymbolAddress((void**)&xh,   g_xh);
    cudaGetSymbolAddress((void**)&whp,  g_whp);
    cudaGetSymbolAddress((void**)&wop,  g_wop);
    cudaGetSymbolAddress((void**)&aob,  g_aob);
    cudaGetSymbolAddress((void**)&vb,   g_vb);

    const size_t WPS = (size_t)(DIM / 2) * DIM;
    __half* xp[2];
    for (int i = 0; i < 2; i++) xp[i] = xh + (size_t)i * SL * DIM;
    unsigned* wp[6];
    for (int i = 0; i < 6; i++) wp[i] = whp + (size_t)i * WPS;
    unsigned* wo[2];
    for (int i = 0; i < 2; i++) wo[i] = wop + (size_t)i * WPS;

    cudaFuncSetAttribute(gemm_f16_split<false, false>,
                         cudaFuncAttributeMaxDynamicSharedMemorySize, SMF);
    cudaFuncSetAttribute(gemm_f16_split<true, false>,
                         cudaFuncAttributeMaxDynamicSharedMemorySize, SMF);
    cudaFuncSetAttribute(gemm_f16_split<true, true>,
                         cudaFuncAttributeMaxDynamicSharedMemorySize, SMF);
    cudaFuncSetAttribute(gemm_wo, cudaFuncAttributeMaxDynamicSharedMemorySize, SMW);
    cudaFuncSetAttribute(score_gemm_mma, cudaFuncAttributeMaxDynamicSharedMemorySize, SMS);
    cudaFuncSetAttribute(pv_gemm_mma, cudaFuncAttributeMaxDynamicSharedMemorySize, SMPV);

    dim3 blk(TPB);
    const int nw = (DIM / 2) * DIM;

    split2h_kernel<<<(SL * DIM + TPB - 1) / TPB, blk>>>(x, xp[0], xp[1], SL * DIM);
    splitpack_h_kernel<<<(nw + TPB - 1) / TPB, blk>>>(Wq, wp[0], wp[1], DIM, DIM);
    splitpack_h_kernel<<<(nw + TPB - 1) / TPB, blk>>>(Wk, wp[2], wp[3], DIM, DIM);
    splitpack_h_kernel<<<(nw + TPB - 1) / TPB, blk>>>(Wv, wp[4], wp[5], DIM, DIM);
    splitpack_b_kernel<<<(nw + TPB - 1) / TPB, blk>>>(Wo, wo[0], wo[1], DIM, DIM);

    dim3 gProjQ(DIM / 128, SL / 128);         // (12, 50)
    dim3 gProjKV(DIM / 128, LK / 128);        // (12, 25)
    gemm_f16_split<false, false><<<gProjQ, blk, SMF>>>(
        xp[0], xp[1], wp[0], wp[1], bq, qraw, nullptr, SL, DIM, DIM);
    gemm_f16_split<true, false><<<gProjKV, blk, SMF>>>(
        xp[0], xp[1], wp[2], wp[3], bk, kraw, nullptr, LK, DIM, DIM);
    gemm_f16_split<true, true><<<gProjKV, blk, SMF>>>(
        xp[0], xp[1], wp[4], wp[5], bv, nullptr, vb, LK, DIM, DIM);

    rmsrope_kernel<<<SL, blk>>>(gq, gk, freqs);
    vpack_kernel<<<((LK / 2) * DIM + TPB - 1) / TPB, blk>>>();

    dim3 gScore(LK / 128, SL / 128, NHD);     // (25, 50, 12)
    score_gemm_mma<<<gScore, blk, SMS>>>();

    combine_kernel<<<(NHD * SL + TPB - 1) / TPB, blk>>>();

    dim3 gPV(1, SL / 128, NHD);
    pv_gemm_mma<<<gPV, blk, SMPV>>>();

    gemm_wo<<<gProjQ, blk, SMW>>>(aob, wo[0], wo[1], bo, out, SL, DIM, DIM);
}

// round 12
// speedup vs baseline: 4.9286x; 1.0841x over previous
#include <cuda_runtime.h>
#include <cuda_bf16.h>
#include <cuda_fp16.h>

#define DIM 1536
#define NHD 12
#define HD  128
#define SL  6400      // query length (100*8*8)
#define LK  3200      // kv length after even-frame subsample (50*64)
#define TPB 256
#define NKB (LK / 128)   // 25 score col-blocks per row

#define LOSCALE 2048.0f
#define INV_LOSCALE 4.8828125e-4f   // 1/2048
#define SM_SCALE 0.088388347648318447f  // 1/sqrt(128)

// ---------------- scratch (static device arrays; no allocs) ----------------
__device__ float g_qraw[SL * DIM];
__device__ float g_kraw[LK * DIM];                     // only kept rows
__device__ __half g_xh[2][SL * DIM];                   // x fp16 2-split (lo scaled)
__device__ uint2 g_whp[6][(DIM / 4) * DIM];            // W fp16 splits, {kp,kp+4} uint2 pairs
__device__ uint2 g_wop[2][(DIM / 4) * DIM];            // Wo bf16 split, paired
__device__ __nv_bfloat16 g_qb[SL * DIM];
__device__ __nv_bfloat16 g_kb[LK * DIM];
__device__ __nv_bfloat16 g_vb[LK * DIM];
__device__ uint2 g_vpk[(LK / 4) * DIM];                // V pairs {pair(kp),pair(kp+4)}
__device__ __nv_bfloat16 g_sc[(size_t)NHD * SL * LK];  // 491.5 MB raw bf16 scores
__device__ float g_pm[NHD * SL * NKB];
__device__ float g_ps[NHD * SL * NKB];
__device__ float g_M[NHD * SL];
__device__ float g_iz[NHD * SL];
__device__ __nv_bfloat16 g_aob[SL * DIM];

// ---------------- warp-level MMA helpers ----------------
__device__ __forceinline__ void mma_bf16(float* d, const unsigned* a, const unsigned* b)
{
    asm volatile(
        "mma.sync.aligned.m16n8k16.row.col.f32.bf16.bf16.f32 "
        "{%0,%1,%2,%3}, {%4,%5,%6,%7}, {%8,%9}, {%0,%1,%2,%3};\n"
        : "+f"(d[0]), "+f"(d[1]), "+f"(d[2]), "+f"(d[3])
        : "r"(a[0]), "r"(a[1]), "r"(a[2]), "r"(a[3]), "r"(b[0]), "r"(b[1]));
}

__device__ __forceinline__ void mma_f16(float* d, const unsigned* a, const unsigned* b)
{
    asm volatile(
        "mma.sync.aligned.m16n8k16.row.col.f32.f16.f16.f32 "
        "{%0,%1,%2,%3}, {%4,%5,%6,%7}, {%8,%9}, {%0,%1,%2,%3};\n"
        : "+f"(d[0]), "+f"(d[1]), "+f"(d[2]), "+f"(d[3])
        : "r"(a[0]), "r"(a[1]), "r"(a[2]), "r"(a[3]), "r"(b[0]), "r"(b[1]));
}

__device__ __forceinline__ void ldsm_x4(unsigned* a, const void* p)
{
    unsigned addr = (unsigned)__cvta_generic_to_shared(p);
    asm volatile("ldmatrix.sync.aligned.m8n8.x4.shared.b16 {%0,%1,%2,%3}, [%4];"
                 : "=r"(a[0]), "=r"(a[1]), "=r"(a[2]), "=r"(a[3]) : "r"(addr));
}

__device__ __forceinline__ void cp16(void* dst_smem, const void* src)
{
    unsigned d = (unsigned)__cvta_generic_to_shared(dst_smem);
    asm volatile("cp.async.cg.shared.global [%0], [%1], 16;\n" :: "r"(d), "l"(src));
}
#define CP_COMMIT() asm volatile("cp.async.commit_group;\n")
#define CP_WAIT0()  asm volatile("cp.async.wait_group 0;\n")

__device__ __forceinline__ int kv_src_row(int kc) { return kc + ((kc >> 6) << 6); }

__device__ __forceinline__ unsigned exp_cvt(unsigned raw, float M, float iz)
{
    float2 f = __bfloat1622float2(*(__nv_bfloat162*)&raw);
    float p0 = expf(f.x * SM_SCALE - M) * iz;
    float p1 = expf(f.y * SM_SCALE - M) * iz;
    __nv_bfloat162 b2 = __floats2bfloat162_rn(p0, p1);
    return *(unsigned*)&b2;
}

// ---------------- splits ----------------
__global__ void split2h_kernel(const float* __restrict__ src,
                               __half* __restrict__ h0,
                               __half* __restrict__ h1, int n)
{
    int i = blockIdx.x * blockDim.x + threadIdx.x;
    if (i < n) {
        float f = src[i];
        __half a = __float2half_rn(f);
        float r = f - __half2float(a);
        h0[i] = a;
        h1[i] = __float2half_rn(r * LOSCALE);
    }
}

// W fp16 2-split into paired layout:
// element i -> rowblk = i/N (= c*8 + kk2*4 + tig), n = i%N
// kp0 = c*16 + kk2*8 + tig, kp1 = kp0+4; each packed word = {W[2kp][n], W[2kp+1][n]}
__global__ void splitpack_h_kernel(const float* __restrict__ src,
                                   uint2* __restrict__ p0,
                                   uint2* __restrict__ p1, int K, int N)
{
    int i = blockIdx.x * blockDim.x + threadIdx.x;
    int total = (K / 4) * N;
    if (i >= total) return;
    int rowblk = i / N, n = i - rowblk * N;
    int c = rowblk >> 3, r8 = rowblk & 7;
    int kk2 = r8 >> 2, tig = r8 & 3;
    int kp0 = c * 16 + kk2 * 8 + tig;
    int kp1 = kp0 + 4;
    unsigned uh[2], ul[2];
    int kps[2] = {kp0, kp1};
#pragma unroll
    for (int j = 0; j < 2; j++) {
        float f0 = src[(size_t)(2 * kps[j]) * N + n];
        float f1 = src[(size_t)(2 * kps[j] + 1) * N + n];
        __half h0 = __float2half_rn(f0), h1 = __float2half_rn(f1);
        __half l0 = __float2half_rn((f0 - __half2float(h0)) * LOSCALE);
        __half l1 = __float2half_rn((f1 - __half2float(h1)) * LOSCALE);
        __half2 ph = __halves2half2(h0, h1);
        __half2 pl = __halves2half2(l0, l1);
        uh[j] = *(unsigned*)&ph;
        ul[j] = *(unsigned*)&pl;
    }
    p0[i] = make_uint2(uh[0], uh[1]);
    p1[i] = make_uint2(ul[0], ul[1]);
}

// Wo bf16 2-split, same paired layout
__global__ void splitpack_b_kernel(const float* __restrict__ src,
                                   uint2* __restrict__ p0,
                                   uint2* __restrict__ p1, int K, int N)
{
    int i = blockIdx.x * blockDim.x + threadIdx.x;
    int total = (K / 4) * N;
    if (i >= total) return;
    int rowblk = i / N, n = i - rowblk * N;
    int c = rowblk >> 3, r8 = rowblk & 7;
    int kk2 = r8 >> 2, tig = r8 & 3;
    int kp0 = c * 16 + kk2 * 8 + tig;
    int kp1 = kp0 + 4;
    unsigned uh[2], ul[2];
    int kps[2] = {kp0, kp1};
#pragma unroll
    for (int j = 0; j < 2; j++) {
        float f0 = src[(size_t)(2 * kps[j]) * N + n];
        float f1 = src[(size_t)(2 * kps[j] + 1) * N + n];
        __nv_bfloat16 h0 = __float2bfloat16(f0), h1 = __float2bfloat16(f1);
        __nv_bfloat16 l0 = __float2bfloat16(f0 - __bfloat162float(h0));
        __nv_bfloat16 l1 = __float2bfloat16(f1 - __bfloat162float(h1));
        __nv_bfloat162 ph = __halves2bfloat162(h0, h1);
        __nv_bfloat162 pl = __halves2bfloat162(l0, l1);
        uh[j] = *(unsigned*)&ph;
        ul[j] = *(unsigned*)&pl;
    }
    p0[i] = make_uint2(uh[0], uh[1]);
    p1[i] = make_uint2(ul[0], ul[1]);
}

// pack V pairs: rowblk = c64*16 + g*4 + tig; kp0 = c64*32 + g*8 + tig
__global__ void vpack_kernel(void)
{
    int i = blockIdx.x * blockDim.x + threadIdx.x;
    if (i >= (LK / 4) * DIM) return;
    int rowblk = i / DIM, n = i - rowblk * DIM;
    int c64 = rowblk >> 4, r = rowblk & 15;
    int g = r >> 2, tig = r & 3;
    int kp0 = c64 * 32 + g * 8 + tig;
    int kp1 = kp0 + 4;
    __nv_bfloat162 a2 = __halves2bfloat162(g_vb[(size_t)(2 * kp0) * DIM + n],
                                           g_vb[(size_t)(2 * kp0 + 1) * DIM + n]);
    __nv_bfloat162 b2 = __halves2bfloat162(g_vb[(size_t)(2 * kp1) * DIM + n],
                                           g_vb[(size_t)(2 * kp1 + 1) * DIM + n]);
    g_vpk[i] = make_uint2(*(unsigned*)&a2, *(unsigned*)&b2);
}

// ---------------- fp16 3-term split GEMM, paired-B + ldmatrix + chunk-fold ----------
#define SMF (2*2*128*40*2 + 2*2*8*132*8)   // 74752
template <bool REMAP, bool BF16OUT>
__global__ void __launch_bounds__(256) gemm_f16_split(
    const __half* __restrict__ A0, const __half* __restrict__ A1,
    const uint2* __restrict__ B0p, const uint2* __restrict__ B1p,
    const float* __restrict__ bias, float* __restrict__ C,
    __nv_bfloat16* __restrict__ Cb, int M, int N, int K)
{
    extern __shared__ char sm[];
    typedef __half ATile[2][128][40];
    typedef uint2 BTile[2][8][132];        // [part][kk2*4+tig][n]
    ATile* As = (ATile*)sm;
    BTile* Bs = (BTile*)(sm + 2 * 2 * 128 * 40 * 2);

    const int tid = threadIdx.x;
    const int warp = tid >> 5, lane = tid & 31;
    const int wm = warp >> 1, wn = warp & 1;
    const int group = lane >> 2, tig = lane & 3;
    const int m0 = blockIdx.y * 128, n0 = blockIdx.x * 128;

    const int lrow = (lane & 7) + ((lane >> 3) & 1) * 8;
    const int lcol = (lane >> 4) * 8;

    const __half* Ap[2] = {A0, A1};
    const uint2* Bp[2] = {B0p, B1p};

    const int rA = tid >> 2;
    const int cA = (tid & 3) * 8;
    const int r8B = tid >> 5;            // 0..7
    const int cqB = (lane) * 2;          // uint2 col pairs (2 per 16B copy)

    int srcRow[2];
#pragma unroll
    for (int i = 0; i < 2; i++) {
        int o = m0 + rA + i * 64;
        srcRow[i] = REMAP ? kv_src_row(o) : o;
    }

    auto issue = [&](int k0, int buf) {
        const int c = k0 >> 5;           // 32-k chunk index
#pragma unroll
        for (int p = 0; p < 2; p++) {
#pragma unroll
            for (int i = 0; i < 2; i++) {
                int r = rA + i * 64;
                cp16(&As[buf][p][r][cA], &Ap[p][(size_t)srcRow[i] * K + k0 + cA]);
            }
#pragma unroll
            for (int i = 0; i < 2; i++) {
                int cq = cqB + i * 64;   // 0..126
                cp16(&Bs[buf][p][r8B][cq],
                     &Bp[p][((size_t)c * 8 + r8B) * N + n0 + cq]);
            }
        }
    };

    float acc[2][8][4] = {};

    issue(0, 0);
    CP_COMMIT();
    int buf = 0;

    for (int k0 = 0; k0 < K; k0 += 32) {
        CP_WAIT0();
        __syncthreads();
        if (k0 + 32 < K) {
            issue(k0 + 32, buf ^ 1);
            CP_COMMIT();
        }

        unsigned a[2][2][2][4];   // [part][mt][kk2]
#pragma unroll
        for (int p = 0; p < 2; p++)
#pragma unroll
            for (int mt = 0; mt < 2; mt++)
#pragma unroll
                for (int kk2 = 0; kk2 < 2; kk2++)
                    ldsm_x4(a[p][mt][kk2],
                            &As[buf][p][wm * 32 + mt * 16 + lrow][kk2 * 16 + lcol]);

#pragma unroll
        for (int nt = 0; nt < 8; nt++) {
            const int n = wn * 64 + nt * 8 + group;
            float d0[2][4] = {};
            float d1[2][4] = {};
#pragma unroll
            for (int kk2 = 0; kk2 < 2; kk2++) {
                uint2 v0 = Bs[buf][0][kk2 * 4 + tig][n];
                uint2 v1 = Bs[buf][1][kk2 * 4 + tig][n];
#pragma unroll
                for (int mt = 0; mt < 2; mt++) {
                    mma_f16(d0[mt], a[0][mt][kk2], &v0.x);
                    mma_f16(d1[mt], a[0][mt][kk2], &v1.x);
                    mma_f16(d1[mt], a[1][mt][kk2], &v0.x);
                }
            }
#pragma unroll
            for (int mt = 0; mt < 2; mt++)
#pragma unroll
                for (int c = 0; c < 4; c++)
                    acc[mt][nt][c] += d0[mt][c] + d1[mt][c] * INV_LOSCALE;
        }
        buf ^= 1;
    }

#pragma unroll
    for (int mt = 0; mt < 2; mt++) {
        const int row = m0 + wm * 32 + mt * 16 + group;
#pragma unroll
        for (int nt = 0; nt < 8; nt++) {
            const int col = n0 + wn * 64 + nt * 8 + tig * 2;
            float b0 = bias[col], b1 = bias[col + 1];
            if (BF16OUT) {
                *(__nv_bfloat162*)&Cb[(size_t)row * N + col] =
                    __floats2bfloat162_rn(acc[mt][nt][0] + b0, acc[mt][nt][1] + b1);
                *(__nv_bfloat162*)&Cb[(size_t)(row + 8) * N + col] =
                    __floats2bfloat162_rn(acc[mt][nt][2] + b0, acc[mt][nt][3] + b1);
            } else {
                C[(size_t)row * N + col]           = acc[mt][nt][0] + b0;
                C[(size_t)row * N + col + 1]       = acc[mt][nt][1] + b1;
                C[(size_t)(row + 8) * N + col]     = acc[mt][nt][2] + b0;
                C[(size_t)(row + 8) * N + col + 1] = acc[mt][nt][3] + b1;
            }
        }
    }
}

// ---------------- bf16 2-term GEMM for Wo, paired-B ----------------
#define SMW (2*128*40*2 + 2*2*8*132*8)     // 54272
__global__ void __launch_bounds__(256) gemm_wo(
    const __nv_bfloat16* __restrict__ A0,
    const uint2* __restrict__ B0p, const uint2* __restrict__ B1p,
    const float* __restrict__ bias, float* __restrict__ C, int M, int N, int K)
{
    extern __shared__ char sm[];
    typedef __nv_bfloat16 ATile[128][40];
    typedef uint2 BTile[2][8][132];
    ATile* As = (ATile*)sm;
    BTile* Bs = (BTile*)(sm + 2 * 128 * 40 * 2);

    const int tid = threadIdx.x;
    const int warp = tid >> 5, lane = tid & 31;
    const int wm = warp >> 1, wn = warp & 1;
    const int group = lane >> 2, tig = lane & 3;
    const int m0 = blockIdx.y * 128, n0 = blockIdx.x * 128;

    const int lrow = (lane & 7) + ((lane >> 3) & 1) * 8;
    const int lcol = (lane >> 4) * 8;

    const uint2* Bp[2] = {B0p, B1p};
    const int rA = tid >> 2;
    const int cA = (tid & 3) * 8;
    const int r8B = tid >> 5;
    const int cqB = lane * 2;

    auto issue = [&](int k0, int buf) {
        const int c = k0 >> 5;
#pragma unroll
        for (int i = 0; i < 2; i++) {
            int r = rA + i * 64;
            cp16(&As[buf][r][cA], &A0[(size_t)(m0 + r) * K + k0 + cA]);
        }
#pragma unroll
        for (int p = 0; p < 2; p++)
#pragma unroll
            for (int i = 0; i < 2; i++) {
                int cq = cqB + i * 64;
                cp16(&Bs[buf][p][r8B][cq],
                     &Bp[p][((size_t)c * 8 + r8B) * N + n0 + cq]);
            }
    };

    float acc[2][8][4] = {};
    issue(0, 0);
    CP_COMMIT();
    int buf = 0;

    for (int k0 = 0; k0 < K; k0 += 32) {
        CP_WAIT0();
        __syncthreads();
        if (k0 + 32 < K) {
            issue(k0 + 32, buf ^ 1);
            CP_COMMIT();
        }

        unsigned a[2][2][4];
#pragma unroll
        for (int mt = 0; mt < 2; mt++)
#pragma unroll
            for (int kk2 = 0; kk2 < 2; kk2++)
                ldsm_x4(a[mt][kk2], &As[buf][wm * 32 + mt * 16 + lrow][kk2 * 16 + lcol]);

#pragma unroll
        for (int nt = 0; nt < 8; nt++) {
            const int n = wn * 64 + nt * 8 + group;
            float d[2][4] = {};
#pragma unroll
            for (int kk2 = 0; kk2 < 2; kk2++) {
                uint2 v0 = Bs[buf][0][kk2 * 4 + tig][n];
                uint2 v1 = Bs[buf][1][kk2 * 4 + tig][n];
#pragma unroll
                for (int mt = 0; mt < 2; mt++) {
                    mma_bf16(d[mt], a[mt][kk2], &v0.x);
                    mma_bf16(d[mt], a[mt][kk2], &v1.x);
                }
            }
#pragma unroll
            for (int mt = 0; mt < 2; mt++)
#pragma unroll
                for (int c = 0; c < 4; c++)
                    acc[mt][nt][c] += d[mt][c];
        }
        buf ^= 1;
    }

#pragma unroll
    for (int mt = 0; mt < 2; mt++) {
        const int row = m0 + wm * 32 + mt * 16 + group;
#pragma unroll
        for (int nt = 0; nt < 8; nt++) {
            const int col = n0 + wn * 64 + nt * 8 + tig * 2;
            float b0 = bias[col], b1 = bias[col + 1];
            C[(size_t)row * N + col]           = acc[mt][nt][0] + b0;
            C[(size_t)row * N + col + 1]       = acc[mt][nt][1] + b1;
            C[(size_t)(row + 8) * N + col]     = acc[mt][nt][2] + b0;
            C[(size_t)(row + 8) * N + col + 1] = acc[mt][nt][3] + b1;
        }
    }
}

// ---------------- RMSNorm + 3D RoPE + bf16 pack ----------------
__global__ void rmsrope_kernel(const float* __restrict__ gq, const float* __restrict__ gk,
                               const float* __restrict__ freqs)
{
    const int l = blockIdx.x;
    const int tid = threadIdx.x;
    const int fi = l >> 6;
    const int rem = l & 63;
    const bool keep = (fi & 1) == 0;
    const int kc = (fi >> 1) * 64 + rem;

    const float* qr = g_qraw + (size_t)l * DIM;
    const float* kr = g_kraw + (size_t)kc * DIM;

    float sq = 0.f, sk = 0.f;
    for (int i = tid; i < DIM; i += TPB) {
        float a = qr[i]; sq += a * a;
        if (keep) { float b = kr[i]; sk += b * b; }
    }
    __shared__ float rq[8], rk[8];
#pragma unroll
    for (int off = 16; off; off >>= 1) {
        sq += __shfl_xor_sync(0xffffffffu, sq, off);
        sk += __shfl_xor_sync(0xffffffffu, sk, off);
    }
    if ((tid & 31) == 0) { rq[tid >> 5] = sq; rk[tid >> 5] = sk; }
    __syncthreads();
    if (tid == 0) {
        float tq = 0.f, tk = 0.f;
        for (int i = 0; i < 8; i++) { tq += rq[i]; tk += rk[i]; }
        rq[0] = rsqrtf(tq / DIM + 1e-6f);
        rk[0] = rsqrtf(tk / DIM + 1e-6f);
    }
    __syncthreads();
    const float invq = rq[0], invk = rk[0];

    const int hi = rem >> 3, wi = rem & 7;

    for (int e = tid; e < NHD * 64; e += TPB) {
        const int n = e >> 6;
        const int p = e & 63;
        float ang;
        if (p < 22)      ang = freqs[fi * 64 + p];
        else if (p < 43) ang = freqs[hi * 64 + p];
        else             ang = freqs[wi * 64 + p];
        float s, c;
        sincosf(ang, &s, &c);
        const int j0 = n * HD + 2 * p;

        float q0 = qr[j0] * invq * gq[j0];
        float q1 = qr[j0 + 1] * invq * gq[j0 + 1];
        g_qb[(size_t)l * DIM + j0]     = __float2bfloat16(q0 * c - q1 * s);
        g_qb[(size_t)l * DIM + j0 + 1] = __float2bfloat16(q0 * s + q1 * c);

        if (keep) {
            float k0v = kr[j0] * invk * gk[j0];
            float k1v = kr[j0 + 1] * invk * gk[j0 + 1];
            g_kb[(size_t)kc * DIM + j0]     = __float2bfloat16(k0v * c - k1v * s);
            g_kb[(size_t)kc * DIM + j0 + 1] = __float2bfloat16(k0v * s + k1v * c);
        }
    }
}

// ---------------- scores via HMMA (ldmatrix frags) + fused softmax stats ----------
#define SMS (2 * 128 * 136 * 2)   // 69632
__global__ void __launch_bounds__(256) score_gemm_mma(void)
{
    extern __shared__ char sm[];
    typedef __nv_bfloat16 Row136[136];
    Row136* Qs = (Row136*)sm;
    Row136* Ks = (Row136*)(sm + 128 * 136 * 2);
    __shared__ float sm_m[128][2], sm_s[128][2];

    const int h = blockIdx.z;
    const int mb0 = blockIdx.y * 128, n0 = blockIdx.x * 128;
    const int tid = threadIdx.x;
    const int warp = tid >> 5, lane = tid & 31;
    const int wm = warp >> 1, wn = warp & 1;
    const int group = lane >> 2, tig = lane & 3;

    // ldmatrix per-lane offsets
    const int lrow = (lane & 7) + ((lane >> 3) & 1) * 8;   // A
    const int lcol = (lane >> 4) * 8;
    const int brow = ((lane >> 4) << 3) + (lane & 7);      // B
    const int bcol = ((lane >> 3) & 1) * 8;

    const __nv_bfloat16* Q  = g_qb + h * HD;
    const __nv_bfloat16* Kb = g_kb + h * HD;

#pragma unroll
    for (int i = 0; i < 8; i++) {
        int idx = tid + i * 256;
        int r = idx >> 4, c = (idx & 15) * 8;
        cp16(&Qs[r][c], &Q [(size_t)(mb0 + r) * DIM + c]);
        cp16(&Ks[r][c], &Kb[(size_t)(n0 + r) * DIM + c]);
    }
    CP_COMMIT();

    float acc[2][8][4] = {};

    CP_WAIT0();
    __syncthreads();

#pragma unroll
    for (int kk = 0; kk < HD; kk += 16) {
        unsigned a[2][4], b[8][2];
#pragma unroll
        for (int mt = 0; mt < 2; mt++)
            ldsm_x4(a[mt], &Qs[wm * 32 + mt * 16 + lrow][kk + lcol]);
#pragma unroll
        for (int ntp = 0; ntp < 4; ntp++) {
            unsigned r4[4];
            ldsm_x4(r4, &Ks[wn * 64 + ntp * 16 + brow][kk + bcol]);
            b[2 * ntp][0] = r4[0]; b[2 * ntp][1] = r4[1];
            b[2 * ntp + 1][0] = r4[2]; b[2 * ntp + 1][1] = r4[3];
        }
#pragma unroll
        for (int mt = 0; mt < 2; mt++)
#pragma unroll
            for (int nt = 0; nt < 8; nt++)
                mma_bf16(acc[mt][nt], a[mt], b[nt]);
    }

    __nv_bfloat16* S = g_sc + (size_t)h * SL * LK;
#pragma unroll
    for (int mt = 0; mt < 2; mt++) {
#pragma unroll
        for (int hh = 0; hh < 2; hh++) {
            const int rr = wm * 32 + mt * 16 + group + hh * 8;
            const int row = mb0 + rr;
            float xv[16];
            float mx = -1e30f;
#pragma unroll
            for (int nt = 0; nt < 8; nt++) {
                const int col = n0 + wn * 64 + nt * 8 + tig * 2;
                __nv_bfloat162 b2 = __floats2bfloat162_rn(acc[mt][nt][hh * 2],
                                                          acc[mt][nt][hh * 2 + 1]);
                *(__nv_bfloat162*)&S[(size_t)row * LK + col] = b2;
                float2 f = __bfloat1622float2(b2);
                xv[2 * nt]     = f.x * SM_SCALE;
                xv[2 * nt + 1] = f.y * SM_SCALE;
                mx = fmaxf(mx, fmaxf(xv[2 * nt], xv[2 * nt + 1]));
            }
            mx = fmaxf(mx, __shfl_xor_sync(0xffffffffu, mx, 1));
            mx = fmaxf(mx, __shfl_xor_sync(0xffffffffu, mx, 2));
            float sum = 0.f;
#pragma unroll
            for (int c = 0; c < 16; c++) sum += expf(xv[c] - mx);
            sum += __shfl_xor_sync(0xffffffffu, sum, 1);
            sum += __shfl_xor_sync(0xffffffffu, sum, 2);
            if (tig == 0) { sm_m[rr][wn] = mx; sm_s[rr][wn] = sum; }
        }
    }
    __syncthreads();
    if (tid < 128) {
        float m0v = sm_m[tid][0], m1v = sm_m[tid][1];
        float M = fmaxf(m0v, m1v);
        float Sv = sm_s[tid][0] * expf(m0v - M) + sm_s[tid][1] * expf(m1v - M);
        size_t base = ((size_t)h * SL + mb0 + tid) * NKB + blockIdx.x;
        g_pm[base] = M;
        g_ps[base] = Sv;
    }
}

// ---------------- combine partial stats -> per-row M, 1/Z ----------------
__global__ void combine_kernel(void)
{
    int idx = blockIdx.x * blockDim.x + threadIdx.x;
    if (idx >= NHD * SL) return;
    const float* pm = g_pm + (size_t)idx * NKB;
    const float* ps = g_ps + (size_t)idx * NKB;
    float M = -1e30f;
#pragma unroll
    for (int b = 0; b < NKB; b++) M = fmaxf(M, pm[b]);
    float Z = 0.f;
#pragma unroll
    for (int b = 0; b < NKB; b++) Z += ps[b] * expf(pm[b] - M);
    g_M[idx] = M;
    g_iz[idx] = 1.f / Z;
}

// ---------------- PV via HMMA; paired-V; exp in frag build; double-buffered ---------
#define SMPV (2*128*72*2 + 2*16*132*8)   // 70656
__global__ void __launch_bounds__(256) pv_gemm_mma(void)
{
    extern __shared__ char sm[];
    typedef __nv_bfloat16 PRow[72];
    typedef uint2 VRow[132];
    PRow* Praw = (PRow*)sm;                       // [2 buf][128 rows]
    VRow* Vps  = (VRow*)(sm + 2 * 128 * 72 * 2);  // [2 buf][16 rowblks]
    __shared__ float sMr[128], sZr[128];

    const int h = blockIdx.z;
    const int m0 = blockIdx.y * 128;
    const int tid = threadIdx.x;
    const int warp = tid >> 5, lane = tid & 31;
    const int group = lane >> 2, tig = lane & 3;

    const __nv_bfloat16* P = g_sc + (size_t)h * SL * LK;
    const uint2* Vg = g_vpk + h * HD;

    if (tid < 128) {
        int row = h * SL + m0 + tid;
        sMr[tid] = g_M[row];
        sZr[tid] = g_iz[row];
    }

    auto issue = [&](int k0, int buf) {
        const int c64 = k0 >> 6;
#pragma unroll
        for (int i = 0; i < 4; i++) {
            int idx = tid + i * 256;
            int r = idx >> 3, c = (idx & 7) * 8;
            cp16(&Praw[buf * 128 + r][c], &P[(size_t)(m0 + r) * LK + k0 + c]);
        }
#pragma unroll
        for (int i = 0; i < 4; i++) {
            int idx = tid + i * 256;
            int rb = idx >> 6, cq = (idx & 63) * 2;
            cp16(&Vps[buf * 16 + rb][cq], &Vg[((size_t)c64 * 16 + rb) * DIM + cq]);
        }
    };

    issue(0, 0);
    CP_COMMIT();
    int buf = 0;

    __syncthreads();
    const int rloc = warp * 16 + group;
    const float M0 = sMr[rloc], iz0 = sZr[rloc];
    const float M1 = sMr[rloc + 8], iz1 = sZr[rloc + 8];

    float acc[16][4] = {};

    for (int k0 = 0; k0 < LK; k0 += 64) {
        CP_WAIT0();
        __syncthreads();
        if (k0 + 64 < LK) {
            issue(k0 + 64, buf ^ 1);
            CP_COMMIT();
        }

#pragma unroll
        for (int kk = 0; kk < 64; kk += 16) {
            const int g = kk >> 4;
            unsigned a[4];
            a[0] = exp_cvt(*(const unsigned*)&Praw[buf * 128 + rloc][kk + tig * 2], M0, iz0);
            a[1] = exp_cvt(*(const unsigned*)&Praw[buf * 128 + rloc + 8][kk + tig * 2], M1, iz1);
            a[2] = exp_cvt(*(const unsigned*)&Praw[buf * 128 + rloc][kk + 8 + tig * 2], M0, iz0);
            a[3] = exp_cvt(*(const unsigned*)&Praw[buf * 128 + rloc + 8][kk + 8 + tig * 2], M1, iz1);
#pragma unroll
            for (int nt = 0; nt < 16; nt++) {
                uint2 v = Vps[buf * 16 + g * 4 + tig][nt * 8 + group];
                mma_bf16(acc[nt], a, &v.x);
            }
        }
        buf ^= 1;
    }

    const int row = m0 + rloc;
#pragma unroll
    for (int nt = 0; nt < 16; nt++) {
        const int col = h * HD + nt * 8 + tig * 2;
        *(__nv_bfloat162*)&g_aob[(size_t)row * DIM + col] =
            __floats2bfloat162_rn(acc[nt][0], acc[nt][1]);
        *(__nv_bfloat162*)&g_aob[(size_t)(row + 8) * DIM + col] =
            __floats2bfloat162_rn(acc[nt][2], acc[nt][3]);
    }
}

// ---------------- launch ----------------
extern "C" void kernel_launch(void* const* d_in, const int* in_sizes, int n_in,
                              void* d_out, int out_size)
{
    const float* x     = (const float*)d_in[0];
    const float* freqs = (const float*)d_in[1];
    const float* Wq    = (const float*)d_in[2];
    const float* bq    = (const float*)d_in[3];
    const float* Wk    = (const float*)d_in[4];
    const float* bk    = (const float*)d_in[5];
    const float* Wv    = (const float*)d_in[6];
    const float* bv    = (const float*)d_in[7];
    const float* Wo    = (const float*)d_in[8];
    const float* bo    = (const float*)d_in[9];
    const float* gq    = (const float*)d_in[10];
    const float* gk    = (const float*)d_in[11];
    float* out = (float*)d_out;

    float *qraw, *kraw;
    __half *xh;
    uint2 *whp, *wop;
    __nv_bfloat16 *aob, *vb;
    cudaGetSymbolAddress((void**)&qraw, g_qraw);
    cudaGetSymbolAddress((void**)&kraw, g_kraw);
    cudaGetSymbolAddress((void**)&xh,   g_xh);
    cudaGetSymbolAddress((void**)&whp,  g_whp);
    cudaGetSymbolAddress((void**)&wop,  g_wop);
    cudaGetSymbolAddress((void**)&aob,  g_aob);
    cudaGetSymbolAddress((void**)&vb,   g_vb);

    const size_t WPS = (size_t)(DIM / 4) * DIM;   // uint2 elements per split part
    __half* xp[2];
    for (int i = 0; i < 2; i++) xp[i] = xh + (size_t)i * SL * DIM;
    uint2* wp[6];
    for (int i = 0; i < 6; i++) wp[i] = whp + (size_t)i * WPS;
    uint2* wo[2];
    for (int i = 0; i < 2; i++) wo[i] = wop + (size_t)i * WPS;

    cudaFuncSetAttribute(gemm_f16_split<false, false>,
                         cudaFuncAttributeMaxDynamicSharedMemorySize, SMF);
    cudaFuncSetAttribute(gemm_f16_split<true, false>,
                         cudaFuncAttributeMaxDynamicSharedMemorySize, SMF);
    cudaFuncSetAttribute(gemm_f16_split<true, true>,
                         cudaFuncAttributeMaxDynamicSharedMemorySize, SMF);
    cudaFuncSetAttribute(gemm_wo, cudaFuncAttributeMaxDynamicSharedMemorySize, SMW);
    cudaFuncSetAttribute(score_gemm_mma, cudaFuncAttributeMaxDynamicSharedMemorySize, SMS);
    cudaFuncSetAttribute(pv_gemm_mma, cudaFuncAttributeMaxDynamicSharedMemorySize, SMPV);

    dim3 blk(TPB);
    const int nw = (DIM / 4) * DIM;               // uint2 per W

    split2h_kernel<<<(SL * DIM + TPB - 1) / TPB, blk>>>(x, xp[0], xp[1], SL * DIM);
    splitpack_h_kernel<<<(nw + TPB - 1) / TPB, blk>>>(Wq, wp[0], wp[1], DIM, DIM);
    splitpack_h_kernel<<<(nw + TPB - 1) / TPB, blk>>>(Wk, wp[2], wp[3], DIM, DIM);
    splitpack_h_kernel<<<(nw + TPB - 1) / TPB, blk>>>(Wv, wp[4], wp[5], DIM, DIM);
    splitpack_b_kernel<<<(nw + TPB - 1) / TPB, blk>>>(Wo, wo[0], wo[1], DIM, DIM);

    dim3 gProjQ(DIM / 128, SL / 128);         // (12, 50)
    dim3 gProjKV(DIM / 128, LK / 128);        // (12, 25)
    gemm_f16_split<false, false><<<gProjQ, blk, SMF>>>(
        xp[0], xp[1], wp[0], wp[1], bq, qraw, nullptr, SL, DIM, DIM);
    gemm_f16_split<true, false><<<gProjKV, blk, SMF>>>(
        xp[0], xp[1], wp[2], wp[3], bk, kraw, nullptr, LK, DIM, DIM);
    gemm_f16_split<true, true><<<gProjKV, blk, SMF>>>(
        xp[0], xp[1], wp[4], wp[5], bv, nullptr, vb, LK, DIM, DIM);

    rmsrope_kernel<<<SL, blk>>>(gq, gk, freqs);
    vpack_kernel<<<((LK / 4) * DIM + TPB - 1) / TPB, blk>>>();

    dim3 gScore(LK / 128, SL / 128, NHD);     // (25, 50, 12)
    score_gemm_mma<<<gScore, blk, SMS>>>();

    combine_kernel<<<(NHD * SL + TPB - 1) / TPB, blk>>>();

    dim3 gPV(1, SL / 128, NHD);
    pv_gemm_mma<<<gPV, blk, SMPV>>>();

    gemm_wo<<<gProjQ, blk, SMW>>>(aob, wo[0], wo[1], bo, out, SL, DIM, DIM);
}

// round 13
// speedup vs baseline: 5.1181x; 1.0385x over previous
#include <cuda_runtime.h>
#include <cuda_bf16.h>
#include <cuda_fp16.h>

#define DIM 1536
#define NHD 12
#define HD  128
#define SL  6400      // query length (100*8*8)
#define LK  3200      // kv length after even-frame subsample (50*64)
#define TPB 256
#define NKB (LK / 128)   // 25 score col-blocks per row

#define LOSCALE 2048.0f
#define INV_LOSCALE 4.8828125e-4f             // 1/2048
#define INV2_BITS 0x3A0000003A000000ULL       // packed {1/2048, 1/2048}
#define SM_SCALE 0.088388347648318447f        // 1/sqrt(128)
#define LOG2E 1.4426950408889634f
#define SC2 (SM_SCALE * LOG2E)                // scale straight to log2 domain

// ---------------- scratch (static device arrays; no allocs) ----------------
__device__ float g_qraw[SL * DIM];
__device__ float g_kraw[LK * DIM];                     // only kept rows
__device__ __half g_xh[2][SL * DIM];                   // x fp16 2-split (lo scaled)
__device__ uint2 g_whp[6][(DIM / 4) * DIM];            // W fp16 splits, {kp,kp+4} uint2 pairs
__device__ uint2 g_wop[2][(DIM / 4) * DIM];            // Wo bf16 split, paired
__device__ __nv_bfloat16 g_qb[SL * DIM];
__device__ __nv_bfloat16 g_kb[LK * DIM];
__device__ __nv_bfloat16 g_vb[LK * DIM];
__device__ uint2 g_vpk[(LK / 4) * DIM];                // V pairs {pair(kp),pair(kp+4)}
__device__ __nv_bfloat16 g_sc[(size_t)NHD * SL * LK];  // 491.5 MB raw bf16 scores
__device__ float g_pm[NHD * SL * NKB];
__device__ float g_ps[NHD * SL * NKB];
__device__ float g_M2[NHD * SL];                       // row max * log2e
__device__ float g_iz[NHD * SL];
__device__ __nv_bfloat16 g_aob[SL * DIM];

// ---------------- warp-level MMA helpers ----------------
__device__ __forceinline__ void mma_bf16(float* d, const unsigned* a, const unsigned* b)
{
    asm volatile(
        "mma.sync.aligned.m16n8k16.row.col.f32.bf16.bf16.f32 "
        "{%0,%1,%2,%3}, {%4,%5,%6,%7}, {%8,%9}, {%0,%1,%2,%3};\n"
        : "+f"(d[0]), "+f"(d[1]), "+f"(d[2]), "+f"(d[3])
        : "r"(a[0]), "r"(a[1]), "r"(a[2]), "r"(a[3]), "r"(b[0]), "r"(b[1]));
}

__device__ __forceinline__ void mma_f16(float* d, const unsigned* a, const unsigned* b)
{
    asm volatile(
        "mma.sync.aligned.m16n8k16.row.col.f32.f16.f16.f32 "
        "{%0,%1,%2,%3}, {%4,%5,%6,%7}, {%8,%9}, {%0,%1,%2,%3};\n"
        : "+f"(d[0]), "+f"(d[1]), "+f"(d[2]), "+f"(d[3])
        : "r"(a[0]), "r"(a[1]), "r"(a[2]), "r"(a[3]), "r"(b[0]), "r"(b[1]));
}

__device__ __forceinline__ void ldsm_x4(unsigned* a, const void* p)
{
    unsigned addr = (unsigned)__cvta_generic_to_shared(p);
    asm volatile("ldmatrix.sync.aligned.m8n8.x4.shared.b16 {%0,%1,%2,%3}, [%4];"
                 : "=r"(a[0]), "=r"(a[1]), "=r"(a[2]), "=r"(a[3]) : "r"(addr));
}

__device__ __forceinline__ void cp16(void* dst_smem, const void* src)
{
    unsigned d = (unsigned)__cvta_generic_to_shared(dst_smem);
    asm volatile("cp.async.cg.shared.global [%0], [%1], 16;\n" :: "r"(d), "l"(src));
}
#define CP_COMMIT() asm volatile("cp.async.commit_group;\n")
#define CP_WAIT0()  asm volatile("cp.async.wait_group 0;\n")

__device__ __forceinline__ int kv_src_row(int kc) { return kc + ((kc >> 6) << 6); }

__device__ __forceinline__ float ex2f(float x)
{
    float y;
    asm("ex2.approx.f32 %0, %1;" : "=f"(y) : "f"(x));
    return y;
}

// packed f32x2: a += x + y * (1/2048)   (per-lane IEEE fp32, half the issue slots)
__device__ __forceinline__ void ffma2add(float& a0, float& a1,
                                         float x0, float x1, float y0, float y1)
{
    asm("{\n\t.reg .b64 ra, rx, ry, rt;\n\t"
        "mov.b64 rx, {%2,%3};\n\t"
        "mov.b64 ry, {%4,%5};\n\t"
        "fma.rn.f32x2 rt, ry, %6, rx;\n\t"
        "mov.b64 ra, {%0,%1};\n\t"
        "add.rn.f32x2 ra, ra, rt;\n\t"
        "mov.b64 {%0,%1}, ra;\n\t}"
        : "+f"(a0), "+f"(a1)
        : "f"(x0), "f"(x1), "f"(y0), "f"(y1), "l"(INV2_BITS));
}

__device__ __forceinline__ void fadd2(float& a0, float& a1, float d0, float d1)
{
    asm("{\n\t.reg .b64 ra, rd;\n\t"
        "mov.b64 ra, {%0,%1};\n\t"
        "mov.b64 rd, {%2,%3};\n\t"
        "add.rn.f32x2 ra, ra, rd;\n\t"
        "mov.b64 {%0,%1}, ra;\n\t}"
        : "+f"(a0), "+f"(a1) : "f"(d0), "f"(d1));
}

// raw bf16 score pair -> bf16 prob pair: p = ex2(x*SC2 - M2) * iz
__device__ __forceinline__ unsigned exp_cvt(unsigned raw, float M2, float iz)
{
    float2 f = __bfloat1622float2(*(__nv_bfloat162*)&raw);
    float p0 = ex2f(__fmaf_rn(f.x, SC2, -M2)) * iz;
    float p1 = ex2f(__fmaf_rn(f.y, SC2, -M2)) * iz;
    __nv_bfloat162 b2 = __floats2bfloat162_rn(p0, p1);
    return *(unsigned*)&b2;
}

// ---------------- splits ----------------
__global__ void split2h_kernel(const float* __restrict__ src,
                               __half* __restrict__ h0,
                               __half* __restrict__ h1, int n)
{
    int i = blockIdx.x * blockDim.x + threadIdx.x;
    if (i < n) {
        float f = src[i];
        __half a = __float2half_rn(f);
        float r = f - __half2float(a);
        h0[i] = a;
        h1[i] = __float2half_rn(r * LOSCALE);
    }
}

__global__ void splitpack_h_kernel(const float* __restrict__ src,
                                   uint2* __restrict__ p0,
                                   uint2* __restrict__ p1, int K, int N)
{
    int i = blockIdx.x * blockDim.x + threadIdx.x;
    int total = (K / 4) * N;
    if (i >= total) return;
    int rowblk = i / N, n = i - rowblk * N;
    int c = rowblk >> 3, r8 = rowblk & 7;
    int kk2 = r8 >> 2, tig = r8 & 3;
    int kp0 = c * 16 + kk2 * 8 + tig;
    int kp1 = kp0 + 4;
    unsigned uh[2], ul[2];
    int kps[2] = {kp0, kp1};
#pragma unroll
    for (int j = 0; j < 2; j++) {
        float f0 = src[(size_t)(2 * kps[j]) * N + n];
        float f1 = src[(size_t)(2 * kps[j] + 1) * N + n];
        __half h0 = __float2half_rn(f0), h1 = __float2half_rn(f1);
        __half l0 = __float2half_rn((f0 - __half2float(h0)) * LOSCALE);
        __half l1 = __float2half_rn((f1 - __half2float(h1)) * LOSCALE);
        __half2 ph = __halves2half2(h0, h1);
        __half2 pl = __halves2half2(l0, l1);
        uh[j] = *(unsigned*)&ph;
        ul[j] = *(unsigned*)&pl;
    }
    p0[i] = make_uint2(uh[0], uh[1]);
    p1[i] = make_uint2(ul[0], ul[1]);
}

__global__ void splitpack_b_kernel(const float* __restrict__ src,
                                   uint2* __restrict__ p0,
                                   uint2* __restrict__ p1, int K, int N)
{
    int i = blockIdx.x * blockDim.x + threadIdx.x;
    int total = (K / 4) * N;
    if (i >= total) return;
    int rowblk = i / N, n = i - rowblk * N;
    int c = rowblk >> 3, r8 = rowblk & 7;
    int kk2 = r8 >> 2, tig = r8 & 3;
    int kp0 = c * 16 + kk2 * 8 + tig;
    int kp1 = kp0 + 4;
    unsigned uh[2], ul[2];
    int kps[2] = {kp0, kp1};
#pragma unroll
    for (int j = 0; j < 2; j++) {
        float f0 = src[(size_t)(2 * kps[j]) * N + n];
        float f1 = src[(size_t)(2 * kps[j] + 1) * N + n];
        __nv_bfloat16 h0 = __float2bfloat16(f0), h1 = __float2bfloat16(f1);
        __nv_bfloat16 l0 = __float2bfloat16(f0 - __bfloat162float(h0));
        __nv_bfloat16 l1 = __float2bfloat16(f1 - __bfloat162float(h1));
        __nv_bfloat162 ph = __halves2bfloat162(h0, h1);
        __nv_bfloat162 pl = __halves2bfloat162(l0, l1);
        uh[j] = *(unsigned*)&ph;
        ul[j] = *(unsigned*)&pl;
    }
    p0[i] = make_uint2(uh[0], uh[1]);
    p1[i] = make_uint2(ul[0], ul[1]);
}

__global__ void vpack_kernel(void)
{
    int i = blockIdx.x * blockDim.x + threadIdx.x;
    if (i >= (LK / 4) * DIM) return;
    int rowblk = i / DIM, n = i - rowblk * DIM;
    int c64 = rowblk >> 4, r = rowblk & 15;
    int g = r >> 2, tig = r & 3;
    int kp0 = c64 * 32 + g * 8 + tig;
    int kp1 = kp0 + 4;
    __nv_bfloat162 a2 = __halves2bfloat162(g_vb[(size_t)(2 * kp0) * DIM + n],
                                           g_vb[(size_t)(2 * kp0 + 1) * DIM + n]);
    __nv_bfloat162 b2 = __halves2bfloat162(g_vb[(size_t)(2 * kp1) * DIM + n],
                                           g_vb[(size_t)(2 * kp1 + 1) * DIM + n]);
    g_vpk[i] = make_uint2(*(unsigned*)&a2, *(unsigned*)&b2);
}

// ---------------- fp16 3-term split GEMM, paired-B + ldmatrix + f32x2 fold ----------
#define SMF (2*2*128*40*2 + 2*2*8*132*8)   // 74752
template <bool REMAP, bool BF16OUT>
__global__ void __launch_bounds__(256) gemm_f16_split(
    const __half* __restrict__ A0, const __half* __restrict__ A1,
    const uint2* __restrict__ B0p, const uint2* __restrict__ B1p,
    const float* __restrict__ bias, float* __restrict__ C,
    __nv_bfloat16* __restrict__ Cb, int M, int N, int K)
{
    extern __shared__ char sm[];
    typedef __half ATile[2][128][40];
    typedef uint2 BTile[2][8][132];
    ATile* As = (ATile*)sm;
    BTile* Bs = (BTile*)(sm + 2 * 2 * 128 * 40 * 2);

    const int tid = threadIdx.x;
    const int warp = tid >> 5, lane = tid & 31;
    const int wm = warp >> 1, wn = warp & 1;
    const int group = lane >> 2, tig = lane & 3;
    const int m0 = blockIdx.y * 128, n0 = blockIdx.x * 128;

    const int lrow = (lane & 7) + ((lane >> 3) & 1) * 8;
    const int lcol = (lane >> 4) * 8;

    const __half* Ap[2] = {A0, A1};
    const uint2* Bp[2] = {B0p, B1p};

    const int rA = tid >> 2;
    const int cA = (tid & 3) * 8;
    const int r8B = tid >> 5;
    const int cqB = lane * 2;

    int srcRow[2];
#pragma unroll
    for (int i = 0; i < 2; i++) {
        int o = m0 + rA + i * 64;
        srcRow[i] = REMAP ? kv_src_row(o) : o;
    }

    auto issue = [&](int k0, int buf) {
        const int c = k0 >> 5;
#pragma unroll
        for (int p = 0; p < 2; p++) {
#pragma unroll
            for (int i = 0; i < 2; i++) {
                int r = rA + i * 64;
                cp16(&As[buf][p][r][cA], &Ap[p][(size_t)srcRow[i] * K + k0 + cA]);
            }
#pragma unroll
            for (int i = 0; i < 2; i++) {
                int cq = cqB + i * 64;
                cp16(&Bs[buf][p][r8B][cq],
                     &Bp[p][((size_t)c * 8 + r8B) * N + n0 + cq]);
            }
        }
    };

    float acc[2][8][4] = {};

    issue(0, 0);
    CP_COMMIT();
    int buf = 0;

    for (int k0 = 0; k0 < K; k0 += 32) {
        CP_WAIT0();
        __syncthreads();
        if (k0 + 32 < K) {
            issue(k0 + 32, buf ^ 1);
            CP_COMMIT();
        }

        unsigned a[2][2][2][4];
#pragma unroll
        for (int p = 0; p < 2; p++)
#pragma unroll
            for (int mt = 0; mt < 2; mt++)
#pragma unroll
                for (int kk2 = 0; kk2 < 2; kk2++)
                    ldsm_x4(a[p][mt][kk2],
                            &As[buf][p][wm * 32 + mt * 16 + lrow][kk2 * 16 + lcol]);

#pragma unroll
        for (int nt = 0; nt < 8; nt++) {
            const int n = wn * 64 + nt * 8 + group;
            float d0[2][4] = {};
            float d1[2][4] = {};
#pragma unroll
            for (int kk2 = 0; kk2 < 2; kk2++) {
                uint2 v0 = Bs[buf][0][kk2 * 4 + tig][n];
                uint2 v1 = Bs[buf][1][kk2 * 4 + tig][n];
#pragma unroll
                for (int mt = 0; mt < 2; mt++) {
                    mma_f16(d0[mt], a[0][mt][kk2], &v0.x);
                    mma_f16(d1[mt], a[0][mt][kk2], &v1.x);
                    mma_f16(d1[mt], a[1][mt][kk2], &v0.x);
                }
            }
#pragma unroll
            for (int mt = 0; mt < 2; mt++) {
                ffma2add(acc[mt][nt][0], acc[mt][nt][1],
                         d0[mt][0], d0[mt][1], d1[mt][0], d1[mt][1]);
                ffma2add(acc[mt][nt][2], acc[mt][nt][3],
                         d0[mt][2], d0[mt][3], d1[mt][2], d1[mt][3]);
            }
        }
        buf ^= 1;
    }

#pragma unroll
    for (int mt = 0; mt < 2; mt++) {
        const int row = m0 + wm * 32 + mt * 16 + group;
#pragma unroll
        for (int nt = 0; nt < 8; nt++) {
            const int col = n0 + wn * 64 + nt * 8 + tig * 2;
            float b0 = bias[col], b1 = bias[col + 1];
            if (BF16OUT) {
                *(__nv_bfloat162*)&Cb[(size_t)row * N + col] =
                    __floats2bfloat162_rn(acc[mt][nt][0] + b0, acc[mt][nt][1] + b1);
                *(__nv_bfloat162*)&Cb[(size_t)(row + 8) * N + col] =
                    __floats2bfloat162_rn(acc[mt][nt][2] + b0, acc[mt][nt][3] + b1);
            } else {
                C[(size_t)row * N + col]           = acc[mt][nt][0] + b0;
                C[(size_t)row * N + col + 1]       = acc[mt][nt][1] + b1;
                C[(size_t)(row + 8) * N + col]     = acc[mt][nt][2] + b0;
                C[(size_t)(row + 8) * N + col + 1] = acc[mt][nt][3] + b1;
            }
        }
    }
}

// ---------------- bf16 2-term GEMM for Wo, paired-B + f32x2 fold ----------------
#define SMW (2*128*40*2 + 2*2*8*132*8)     // 54272
__global__ void __launch_bounds__(256) gemm_wo(
    const __nv_bfloat16* __restrict__ A0,
    const uint2* __restrict__ B0p, const uint2* __restrict__ B1p,
    const float* __restrict__ bias, float* __restrict__ C, int M, int N, int K)
{
    extern __shared__ char sm[];
    typedef __nv_bfloat16 ATile[128][40];
    typedef uint2 BTile[2][8][132];
    ATile* As = (ATile*)sm;
    BTile* Bs = (BTile*)(sm + 2 * 128 * 40 * 2);

    const int tid = threadIdx.x;
    const int warp = tid >> 5, lane = tid & 31;
    const int wm = warp >> 1, wn = warp & 1;
    const int group = lane >> 2, tig = lane & 3;
    const int m0 = blockIdx.y * 128, n0 = blockIdx.x * 128;

    const int lrow = (lane & 7) + ((lane >> 3) & 1) * 8;
    const int lcol = (lane >> 4) * 8;

    const uint2* Bp[2] = {B0p, B1p};
    const int rA = tid >> 2;
    const int cA = (tid & 3) * 8;
    const int r8B = tid >> 5;
    const int cqB = lane * 2;

    auto issue = [&](int k0, int buf) {
        const int c = k0 >> 5;
#pragma unroll
        for (int i = 0; i < 2; i++) {
            int r = rA + i * 64;
            cp16(&As[buf][r][cA], &A0[(size_t)(m0 + r) * K + k0 + cA]);
        }
#pragma unroll
        for (int p = 0; p < 2; p++)
#pragma unroll
            for (int i = 0; i < 2; i++) {
                int cq = cqB + i * 64;
                cp16(&Bs[buf][p][r8B][cq],
                     &Bp[p][((size_t)c * 8 + r8B) * N + n0 + cq]);
            }
    };

    float acc[2][8][4] = {};
    issue(0, 0);
    CP_COMMIT();
    int buf = 0;

    for (int k0 = 0; k0 < K; k0 += 32) {
        CP_WAIT0();
        __syncthreads();
        if (k0 + 32 < K) {
            issue(k0 + 32, buf ^ 1);
            CP_COMMIT();
        }

        unsigned a[2][2][4];
#pragma unroll
        for (int mt = 0; mt < 2; mt++)
#pragma unroll
            for (int kk2 = 0; kk2 < 2; kk2++)
                ldsm_x4(a[mt][kk2], &As[buf][wm * 32 + mt * 16 + lrow][kk2 * 16 + lcol]);

#pragma unroll
        for (int nt = 0; nt < 8; nt++) {
            const int n = wn * 64 + nt * 8 + group;
            float d[2][4] = {};
#pragma unroll
            for (int kk2 = 0; kk2 < 2; kk2++) {
                uint2 v0 = Bs[buf][0][kk2 * 4 + tig][n];
                uint2 v1 = Bs[buf][1][kk2 * 4 + tig][n];
#pragma unroll
                for (int mt = 0; mt < 2; mt++) {
                    mma_bf16(d[mt], a[mt][kk2], &v0.x);
                    mma_bf16(d[mt], a[mt][kk2], &v1.x);
                }
            }
#pragma unroll
            for (int mt = 0; mt < 2; mt++) {
                fadd2(acc[mt][nt][0], acc[mt][nt][1], d[mt][0], d[mt][1]);
                fadd2(acc[mt][nt][2], acc[mt][nt][3], d[mt][2], d[mt][3]);
            }
        }
        buf ^= 1;
    }

#pragma unroll
    for (int mt = 0; mt < 2; mt++) {
        const int row = m0 + wm * 32 + mt * 16 + group;
#pragma unroll
        for (int nt = 0; nt < 8; nt++) {
            const int col = n0 + wn * 64 + nt * 8 + tig * 2;
            float b0 = bias[col], b1 = bias[col + 1];
            C[(size_t)row * N + col]           = acc[mt][nt][0] + b0;
            C[(size_t)row * N + col + 1]       = acc[mt][nt][1] + b1;
            C[(size_t)(row + 8) * N + col]     = acc[mt][nt][2] + b0;
            C[(size_t)(row + 8) * N + col + 1] = acc[mt][nt][3] + b1;
        }
    }
}

// ---------------- RMSNorm + 3D RoPE + bf16 pack ----------------
__global__ void rmsrope_kernel(const float* __restrict__ gq, const float* __restrict__ gk,
                               const float* __restrict__ freqs)
{
    const int l = blockIdx.x;
    const int tid = threadIdx.x;
    const int fi = l >> 6;
    const int rem = l & 63;
    const bool keep = (fi & 1) == 0;
    const int kc = (fi >> 1) * 64 + rem;

    const float* qr = g_qraw + (size_t)l * DIM;
    const float* kr = g_kraw + (size_t)kc * DIM;

    float sq = 0.f, sk = 0.f;
    for (int i = tid; i < DIM; i += TPB) {
        float a = qr[i]; sq += a * a;
        if (keep) { float b = kr[i]; sk += b * b; }
    }
    __shared__ float rq[8], rk[8];
#pragma unroll
    for (int off = 16; off; off >>= 1) {
        sq += __shfl_xor_sync(0xffffffffu, sq, off);
        sk += __shfl_xor_sync(0xffffffffu, sk, off);
    }
    if ((tid & 31) == 0) { rq[tid >> 5] = sq; rk[tid >> 5] = sk; }
    __syncthreads();
    if (tid == 0) {
        float tq = 0.f, tk = 0.f;
        for (int i = 0; i < 8; i++) { tq += rq[i]; tk += rk[i]; }
        rq[0] = rsqrtf(tq / DIM + 1e-6f);
        rk[0] = rsqrtf(tk / DIM + 1e-6f);
    }
    __syncthreads();
    const float invq = rq[0], invk = rk[0];

    const int hi = rem >> 3, wi = rem & 7;

    for (int e = tid; e < NHD * 64; e += TPB) {
        const int n = e >> 6;
        const int p = e & 63;
        float ang;
        if (p < 22)      ang = freqs[fi * 64 + p];
        else if (p < 43) ang = freqs[hi * 64 + p];
        else             ang = freqs[wi * 64 + p];
        float s, c;
        sincosf(ang, &s, &c);
        const int j0 = n * HD + 2 * p;

        float q0 = qr[j0] * invq * gq[j0];
        float q1 = qr[j0 + 1] * invq * gq[j0 + 1];
        g_qb[(size_t)l * DIM + j0]     = __float2bfloat16(q0 * c - q1 * s);
        g_qb[(size_t)l * DIM + j0 + 1] = __float2bfloat16(q0 * s + q1 * c);

        if (keep) {
            float k0v = kr[j0] * invk * gk[j0];
            float k1v = kr[j0 + 1] * invk * gk[j0 + 1];
            g_kb[(size_t)kc * DIM + j0]     = __float2bfloat16(k0v * c - k1v * s);
            g_kb[(size_t)kc * DIM + j0 + 1] = __float2bfloat16(k0v * s + k1v * c);
        }
    }
}

// ---------------- scores via HMMA (ldmatrix frags) + fused softmax stats ----------
#define SMS (2 * 128 * 136 * 2)   // 69632
__global__ void __launch_bounds__(256) score_gemm_mma(void)
{
    extern __shared__ char sm[];
    typedef __nv_bfloat16 Row136[136];
    Row136* Qs = (Row136*)sm;
    Row136* Ks = (Row136*)(sm + 128 * 136 * 2);
    __shared__ float sm_m[128][2], sm_s[128][2];

    const int h = blockIdx.z;
    const int mb0 = blockIdx.y * 128, n0 = blockIdx.x * 128;
    const int tid = threadIdx.x;
    const int warp = tid >> 5, lane = tid & 31;
    const int wm = warp >> 1, wn = warp & 1;
    const int group = lane >> 2, tig = lane & 3;

    const int lrow = (lane & 7) + ((lane >> 3) & 1) * 8;
    const int lcol = (lane >> 4) * 8;
    const int brow = ((lane >> 4) << 3) + (lane & 7);
    const int bcol = ((lane >> 3) & 1) * 8;

    const __nv_bfloat16* Q  = g_qb + h * HD;
    const __nv_bfloat16* Kb = g_kb + h * HD;

#pragma unroll
    for (int i = 0; i < 8; i++) {
        int idx = tid + i * 256;
        int r = idx >> 4, c = (idx & 15) * 8;
        cp16(&Qs[r][c], &Q [(size_t)(mb0 + r) * DIM + c]);
        cp16(&Ks[r][c], &Kb[(size_t)(n0 + r) * DIM + c]);
    }
    CP_COMMIT();

    float acc[2][8][4] = {};

    CP_WAIT0();
    __syncthreads();

#pragma unroll
    for (int kk = 0; kk < HD; kk += 16) {
        unsigned a[2][4], b[8][2];
#pragma unroll
        for (int mt = 0; mt < 2; mt++)
            ldsm_x4(a[mt], &Qs[wm * 32 + mt * 16 + lrow][kk + lcol]);
#pragma unroll
        for (int ntp = 0; ntp < 4; ntp++) {
            unsigned r4[4];
            ldsm_x4(r4, &Ks[wn * 64 + ntp * 16 + brow][kk + bcol]);
            b[2 * ntp][0] = r4[0]; b[2 * ntp][1] = r4[1];
            b[2 * ntp + 1][0] = r4[2]; b[2 * ntp + 1][1] = r4[3];
        }
#pragma unroll
        for (int mt = 0; mt < 2; mt++)
#pragma unroll
            for (int nt = 0; nt < 8; nt++)
                mma_bf16(acc[mt][nt], a[mt], b[nt]);
    }

    __nv_bfloat16* S = g_sc + (size_t)h * SL * LK;
#pragma unroll
    for (int mt = 0; mt < 2; mt++) {
#pragma unroll
        for (int hh = 0; hh < 2; hh++) {
            const int rr = wm * 32 + mt * 16 + group + hh * 8;
            const int row = mb0 + rr;
            float xv[16];
            float mx = -1e30f;
#pragma unroll
            for (int nt = 0; nt < 8; nt++) {
                const int col = n0 + wn * 64 + nt * 8 + tig * 2;
                __nv_bfloat162 b2 = __floats2bfloat162_rn(acc[mt][nt][hh * 2],
                                                          acc[mt][nt][hh * 2 + 1]);
                *(__nv_bfloat162*)&S[(size_t)row * LK + col] = b2;
                float2 f = __bfloat1622float2(b2);
                xv[2 * nt]     = f.x * SM_SCALE;
                xv[2 * nt + 1] = f.y * SM_SCALE;
                mx = fmaxf(mx, fmaxf(xv[2 * nt], xv[2 * nt + 1]));
            }
            mx = fmaxf(mx, __shfl_xor_sync(0xffffffffu, mx, 1));
            mx = fmaxf(mx, __shfl_xor_sync(0xffffffffu, mx, 2));
            const float mxl = mx * LOG2E;
            float sum = 0.f;
#pragma unroll
            for (int c = 0; c < 16; c++)
                sum += ex2f(__fmaf_rn(xv[c], LOG2E, -mxl));
            sum += __shfl_xor_sync(0xffffffffu, sum, 1);
            sum += __shfl_xor_sync(0xffffffffu, sum, 2);
            if (tig == 0) { sm_m[rr][wn] = mx; sm_s[rr][wn] = sum; }
        }
    }
    __syncthreads();
    if (tid < 128) {
        float m0v = sm_m[tid][0], m1v = sm_m[tid][1];
        float M = fmaxf(m0v, m1v);
        float Sv = sm_s[tid][0] * ex2f((m0v - M) * LOG2E)
                 + sm_s[tid][1] * ex2f((m1v - M) * LOG2E);
        size_t base = ((size_t)h * SL + mb0 + tid) * NKB + blockIdx.x;
        g_pm[base] = M;
        g_ps[base] = Sv;
    }
}

// ---------------- combine partial stats -> per-row M*log2e, 1/Z ----------------
__global__ void combine_kernel(void)
{
    int idx = blockIdx.x * blockDim.x + threadIdx.x;
    if (idx >= NHD * SL) return;
    const float* pm = g_pm + (size_t)idx * NKB;
    const float* ps = g_ps + (size_t)idx * NKB;
    float M = -1e30f;
#pragma unroll
    for (int b = 0; b < NKB; b++) M = fmaxf(M, pm[b]);
    float Z = 0.f;
#pragma unroll
    for (int b = 0; b < NKB; b++) Z += ps[b] * ex2f((pm[b] - M) * LOG2E);
    g_M2[idx] = M * LOG2E;
    g_iz[idx] = 1.f / Z;
}

// ---------------- PV via HMMA; paired-V; ex2 probs; double-buffered ----------------
#define SMPV (2*128*72*2 + 2*16*132*8)   // 70656
__global__ void __launch_bounds__(256) pv_gemm_mma(void)
{
    extern __shared__ char sm[];
    typedef __nv_bfloat16 PRow[72];
    typedef uint2 VRow[132];
    PRow* Praw = (PRow*)sm;
    VRow* Vps  = (VRow*)(sm + 2 * 128 * 72 * 2);
    __shared__ float sMr[128], sZr[128];

    const int h = blockIdx.z;
    const int m0 = blockIdx.y * 128;
    const int tid = threadIdx.x;
    const int warp = tid >> 5, lane = tid & 31;
    const int group = lane >> 2, tig = lane & 3;

    const __nv_bfloat16* P = g_sc + (size_t)h * SL * LK;
    const uint2* Vg = g_vpk + h * HD;

    if (tid < 128) {
        int row = h * SL + m0 + tid;
        sMr[tid] = g_M2[row];
        sZr[tid] = g_iz[row];
    }

    auto issue = [&](int k0, int buf) {
        const int c64 = k0 >> 6;
#pragma unroll
        for (int i = 0; i < 4; i++) {
            int idx = tid + i * 256;
            int r = idx >> 3, c = (idx & 7) * 8;
            cp16(&Praw[buf * 128 + r][c], &P[(size_t)(m0 + r) * LK + k0 + c]);
        }
#pragma unroll
        for (int i = 0; i < 4; i++) {
            int idx = tid + i * 256;
            int rb = idx >> 6, cq = (idx & 63) * 2;
            cp16(&Vps[buf * 16 + rb][cq], &Vg[((size_t)c64 * 16 + rb) * DIM + cq]);
        }
    };

    issue(0, 0);
    CP_COMMIT();
    int buf = 0;

    __syncthreads();
    const int rloc = warp * 16 + group;
    const float M0 = sMr[rloc], iz0 = sZr[rloc];
    const float M1 = sMr[rloc + 8], iz1 = sZr[rloc + 8];

    float acc[16][4] = {};

    for (int k0 = 0; k0 < LK; k0 += 64) {
        CP_WAIT0();
        __syncthreads();
        if (k0 + 64 < LK) {
            issue(k0 + 64, buf ^ 1);
            CP_COMMIT();
        }

#pragma unroll
        for (int kk = 0; kk < 64; kk += 16) {
            const int g = kk >> 4;
            unsigned a[4];
            a[0] = exp_cvt(*(const unsigned*)&Praw[buf * 128 + rloc][kk + tig * 2], M0, iz0);
            a[1] = exp_cvt(*(const unsigned*)&Praw[buf * 128 + rloc + 8][kk + tig * 2], M1, iz1);
            a[2] = exp_cvt(*(const unsigned*)&Praw[buf * 128 + rloc][kk + 8 + tig * 2], M0, iz0);
            a[3] = exp_cvt(*(const unsigned*)&Praw[buf * 128 + rloc + 8][kk + 8 + tig * 2], M1, iz1);
#pragma unroll
            for (int nt = 0; nt < 16; nt++) {
                uint2 v = Vps[buf * 16 + g * 4 + tig][nt * 8 + group];
                mma_bf16(acc[nt], a, &v.x);
            }
        }
        buf ^= 1;
    }

    const int row = m0 + rloc;
#pragma unroll
    for (int nt = 0; nt < 16; nt++) {
        const int col = h * HD + nt * 8 + tig * 2;
        *(__nv_bfloat162*)&g_aob[(size_t)row * DIM + col] =
            __floats2bfloat162_rn(acc[nt][0], acc[nt][1]);
        *(__nv_bfloat162*)&g_aob[(size_t)(row + 8) * DIM + col] =
            __floats2bfloat162_rn(acc[nt][2], acc[nt][3]);
    }
}

// ---------------- launch ----------------
extern "C" void kernel_launch(void* const* d_in, const int* in_sizes, int n_in,
                              void* d_out, int out_size)
{
    const float* x     = (const float*)d_in[0];
    const float* freqs = (const float*)d_in[1];
    const float* Wq    = (const float*)d_in[2];
    const float* bq    = (const float*)d_in[3];
    const float* Wk    = (const float*)d_in[4];
    const float* bk    = (const float*)d_in[5];
    const float* Wv    = (const float*)d_in[6];
    const float* bv    = (const float*)d_in[7];
    const float* Wo    = (const float*)d_in[8];
    const float* bo    = (const float*)d_in[9];
    const float* gq    = (const float*)d_in[10];
    const float* gk    = (const float*)d_in[11];
    float* out = (float*)d_out;

    float *qraw, *kraw;
    __half *xh;
    uint2 *whp, *wop;
    __nv_bfloat16 *aob, *vb;
    cudaGetSymbolAddress((void**)&qraw, g_qraw);
    cudaGetSymbolAddress((void**)&kraw, g_kraw);
    cudaGetSymbolAddress((void**)&xh,   g_xh);
    cudaGetSymbolAddress((void**)&whp,  g_whp);
    cudaGetSymbolAddress((void**)&wop,  g_wop);
    cudaGetSymbolAddress((void**)&aob,  g_aob);
    cudaGetSymbolAddress((void**)&vb,   g_vb);

    const size_t WPS = (size_t)(DIM / 4) * DIM;
    __half* xp[2];
    for (int i = 0; i < 2; i++) xp[i] = xh + (size_t)i * SL * DIM;
    uint2* wp[6];
    for (int i = 0; i < 6; i++) wp[i] = whp + (size_t)i * WPS;
    uint2* wo[2];
    for (int i = 0; i < 2; i++) wo[i] = wop + (size_t)i * WPS;

    cudaFuncSetAttribute(gemm_f16_split<false, false>,
                         cudaFuncAttributeMaxDynamicSharedMemorySize, SMF);
    cudaFuncSetAttribute(gemm_f16_split<true, false>,
                         cudaFuncAttributeMaxDynamicSharedMemorySize, SMF);
    cudaFuncSetAttribute(gemm_f16_split<true, true>,
                         cudaFuncAttributeMaxDynamicSharedMemorySize, SMF);
    cudaFuncSetAttribute(gemm_wo, cudaFuncAttributeMaxDynamicSharedMemorySize, SMW);
    cudaFuncSetAttribute(score_gemm_mma, cudaFuncAttributeMaxDynamicSharedMemorySize, SMS);
    cudaFuncSetAttribute(pv_gemm_mma, cudaFuncAttributeMaxDynamicSharedMemorySize, SMPV);

    dim3 blk(TPB);
    const int nw = (DIM / 4) * DIM;

    split2h_kernel<<<(SL * DIM + TPB - 1) / TPB, blk>>>(x, xp[0], xp[1], SL * DIM);
    splitpack_h_kernel<<<(nw + TPB - 1) / TPB, blk>>>(Wq, wp[0], wp[1], DIM, DIM);
    splitpack_h_kernel<<<(nw + TPB - 1) / TPB, blk>>>(Wk, wp[2], wp[3], DIM, DIM);
    splitpack_h_kernel<<<(nw + TPB - 1) / TPB, blk>>>(Wv, wp[4], wp[5], DIM, DIM);
    splitpack_b_kernel<<<(nw + TPB - 1) / TPB, blk>>>(Wo, wo[0], wo[1], DIM, DIM);

    dim3 gProjQ(DIM / 128, SL / 128);         // (12, 50)
    dim3 gProjKV(DIM / 128, LK / 128);        // (12, 25)
    gemm_f16_split<false, false><<<gProjQ, blk, SMF>>>(
        xp[0], xp[1], wp[0], wp[1], bq, qraw, nullptr, SL, DIM, DIM);
    gemm_f16_split<true, false><<<gProjKV, blk, SMF>>>(
        xp[0], xp[1], wp[2], wp[3], bk, kraw, nullptr, LK, DIM, DIM);
    gemm_f16_split<true, true><<<gProjKV, blk, SMF>>>(
        xp[0], xp[1], wp[4], wp[5], bv, nullptr, vb, LK, DIM, DIM);

    rmsrope_kernel<<<SL, blk>>>(gq, gk, freqs);
    vpack_kernel<<<((LK / 4) * DIM + TPB - 1) / TPB, blk>>>();

    dim3 gScore(LK / 128, SL / 128, NHD);     // (25, 50, 12)
    score_gemm_mma<<<gScore, blk, SMS>>>();

    combine_kernel<<<(NHD * SL + TPB - 1) / TPB, blk>>>();

    dim3 gPV(1, SL / 128, NHD);
    pv_gemm_mma<<<gPV, blk, SMPV>>>();

    gemm_wo<<<gProjQ, blk, SMW>>>(aob, wo[0], wo[1], bo, out, SL, DIM, DIM);
}

// round 14
// speedup vs baseline: 5.2592x; 1.0276x over previous
#include <cuda_runtime.h>
#include <cuda_bf16.h>
#include <cuda_fp16.h>

#define DIM 1536
#define NHD 12
#define HD  128
#define SL  6400      // query length (100*8*8)
#define LK  3200      // kv length after even-frame subsample (50*64)
#define TPB 256
#define NKB (LK / 128)   // 25 score col-blocks per row

#define LOSCALE 2048.0f
#define INV_LOSCALE 4.8828125e-4f             // 1/2048
#define INV2_BITS 0x3A0000003A000000ULL       // packed {1/2048, 1/2048}
#define SM_SCALE 0.088388347648318447f        // 1/sqrt(128)
#define LOG2E 1.4426950408889634f
#define SC2 (SM_SCALE * LOG2E)

// ---------------- scratch (static device arrays; no allocs) ----------------
__device__ float g_qraw[SL * DIM];
__device__ float g_kraw[LK * DIM];
__device__ __half g_xh[2][SL * DIM];
__device__ uint2 g_whp[6][(DIM / 4) * DIM];
__device__ uint2 g_wop[2][(DIM / 4) * DIM];
__device__ __nv_bfloat16 g_qb[SL * DIM];
__device__ __nv_bfloat16 g_kb[LK * DIM];
__device__ __nv_bfloat16 g_vb[LK * DIM];
__device__ uint2 g_vpk[(LK / 4) * DIM];
__device__ __nv_bfloat16 g_sc[(size_t)NHD * SL * LK];
__device__ float g_pm[NHD * SL * NKB];
__device__ float g_ps[NHD * SL * NKB];
__device__ float g_M2[NHD * SL];
__device__ float g_iz[NHD * SL];
__device__ __nv_bfloat16 g_aob[SL * DIM];

// ---------------- warp-level MMA helpers ----------------
__device__ __forceinline__ void mma_bf16(float* d, const unsigned* a, const unsigned* b)
{
    asm volatile(
        "mma.sync.aligned.m16n8k16.row.col.f32.bf16.bf16.f32 "
        "{%0,%1,%2,%3}, {%4,%5,%6,%7}, {%8,%9}, {%0,%1,%2,%3};\n"
        : "+f"(d[0]), "+f"(d[1]), "+f"(d[2]), "+f"(d[3])
        : "r"(a[0]), "r"(a[1]), "r"(a[2]), "r"(a[3]), "r"(b[0]), "r"(b[1]));
}

__device__ __forceinline__ void mma_f16(float* d, const unsigned* a, const unsigned* b)
{
    asm volatile(
        "mma.sync.aligned.m16n8k16.row.col.f32.f16.f16.f32 "
        "{%0,%1,%2,%3}, {%4,%5,%6,%7}, {%8,%9}, {%0,%1,%2,%3};\n"
        : "+f"(d[0]), "+f"(d[1]), "+f"(d[2]), "+f"(d[3])
        : "r"(a[0]), "r"(a[1]), "r"(a[2]), "r"(a[3]), "r"(b[0]), "r"(b[1]));
}

__device__ __forceinline__ void ldsm_x4(unsigned* a, const void* p)
{
    unsigned addr = (unsigned)__cvta_generic_to_shared(p);
    asm volatile("ldmatrix.sync.aligned.m8n8.x4.shared.b16 {%0,%1,%2,%3}, [%4];"
                 : "=r"(a[0]), "=r"(a[1]), "=r"(a[2]), "=r"(a[3]) : "r"(addr));
}

__device__ __forceinline__ void cp16(void* dst_smem, const void* src)
{
    unsigned d = (unsigned)__cvta_generic_to_shared(dst_smem);
    asm volatile("cp.async.cg.shared.global [%0], [%1], 16;\n" :: "r"(d), "l"(src));
}
#define CP_COMMIT() asm volatile("cp.async.commit_group;\n")
#define CP_WAIT0()  asm volatile("cp.async.wait_group 0;\n")

__device__ __forceinline__ int kv_src_row(int kc) { return kc + ((kc >> 6) << 6); }

__device__ __forceinline__ float ex2f(float x)
{
    float y;
    asm("ex2.approx.f32 %0, %1;" : "=f"(y) : "f"(x));
    return y;
}

__device__ __forceinline__ void ffma2add(float& a0, float& a1,
                                         float x0, float x1, float y0, float y1)
{
    asm("{\n\t.reg .b64 ra, rx, ry, rt;\n\t"
        "mov.b64 rx, {%2,%3};\n\t"
        "mov.b64 ry, {%4,%5};\n\t"
        "fma.rn.f32x2 rt, ry, %6, rx;\n\t"
        "mov.b64 ra, {%0,%1};\n\t"
        "add.rn.f32x2 ra, ra, rt;\n\t"
        "mov.b64 {%0,%1}, ra;\n\t}"
        : "+f"(a0), "+f"(a1)
        : "f"(x0), "f"(x1), "f"(y0), "f"(y1), "l"(INV2_BITS));
}

__device__ __forceinline__ void fadd2(float& a0, float& a1, float d0, float d1)
{
    asm("{\n\t.reg .b64 ra, rd;\n\t"
        "mov.b64 ra, {%0,%1};\n\t"
        "mov.b64 rd, {%2,%3};\n\t"
        "add.rn.f32x2 ra, ra, rd;\n\t"
        "mov.b64 {%0,%1}, ra;\n\t}"
        : "+f"(a0), "+f"(a1) : "f"(d0), "f"(d1));
}

__device__ __forceinline__ unsigned exp_cvt(unsigned raw, float M2, float iz)
{
    float2 f = __bfloat1622float2(*(__nv_bfloat162*)&raw);
    float p0 = ex2f(__fmaf_rn(f.x, SC2, -M2)) * iz;
    float p1 = ex2f(__fmaf_rn(f.y, SC2, -M2)) * iz;
    __nv_bfloat162 b2 = __floats2bfloat162_rn(p0, p1);
    return *(unsigned*)&b2;
}

// ---------------- merged prep: x split + W splits (paired layout) ----------------
#define NX (SL * DIM)
#define NW ((DIM / 4) * DIM)

__device__ __forceinline__ void do_splitpack_h(const float* src, uint2* p0, uint2* p1, int i)
{
    const int N = DIM;
    int rowblk = i / N, n = i - rowblk * N;
    int c = rowblk >> 3, r8 = rowblk & 7;
    int kk2 = r8 >> 2, tig = r8 & 3;
    int kp0 = c * 16 + kk2 * 8 + tig;
    int kps[2] = {kp0, kp0 + 4};
    unsigned uh[2], ul[2];
#pragma unroll
    for (int j = 0; j < 2; j++) {
        float f0 = src[(size_t)(2 * kps[j]) * N + n];
        float f1 = src[(size_t)(2 * kps[j] + 1) * N + n];
        __half h0 = __float2half_rn(f0), h1 = __float2half_rn(f1);
        __half l0 = __float2half_rn((f0 - __half2float(h0)) * LOSCALE);
        __half l1 = __float2half_rn((f1 - __half2float(h1)) * LOSCALE);
        __half2 ph = __halves2half2(h0, h1);
        __half2 pl = __halves2half2(l0, l1);
        uh[j] = *(unsigned*)&ph;
        ul[j] = *(unsigned*)&pl;
    }
    p0[i] = make_uint2(uh[0], uh[1]);
    p1[i] = make_uint2(ul[0], ul[1]);
}

__device__ __forceinline__ void do_splitpack_b(const float* src, uint2* p0, uint2* p1, int i)
{
    const int N = DIM;
    int rowblk = i / N, n = i - rowblk * N;
    int c = rowblk >> 3, r8 = rowblk & 7;
    int kk2 = r8 >> 2, tig = r8 & 3;
    int kp0 = c * 16 + kk2 * 8 + tig;
    int kps[2] = {kp0, kp0 + 4};
    unsigned uh[2], ul[2];
#pragma unroll
    for (int j = 0; j < 2; j++) {
        float f0 = src[(size_t)(2 * kps[j]) * N + n];
        float f1 = src[(size_t)(2 * kps[j] + 1) * N + n];
        __nv_bfloat16 h0 = __float2bfloat16(f0), h1 = __float2bfloat16(f1);
        __nv_bfloat16 l0 = __float2bfloat16(f0 - __bfloat162float(h0));
        __nv_bfloat16 l1 = __float2bfloat16(f1 - __bfloat162float(h1));
        __nv_bfloat162 ph = __halves2bfloat162(h0, h1);
        __nv_bfloat162 pl = __halves2bfloat162(l0, l1);
        uh[j] = *(unsigned*)&ph;
        ul[j] = *(unsigned*)&pl;
    }
    p0[i] = make_uint2(uh[0], uh[1]);
    p1[i] = make_uint2(ul[0], ul[1]);
}

__global__ void prep_kernel(const float* __restrict__ x,
                            const float* __restrict__ Wq, const float* __restrict__ Wk,
                            const float* __restrict__ Wv, const float* __restrict__ Wo)
{
    int i = blockIdx.x * blockDim.x + threadIdx.x;
    if (i < NX) {
        float f = x[i];
        __half a = __float2half_rn(f);
        float r = f - __half2float(a);
        g_xh[0][i] = a;
        g_xh[1][i] = __float2half_rn(r * LOSCALE);
        return;
    }
    i -= NX;
    if (i < NW) { do_splitpack_h(Wq, g_whp[0], g_whp[1], i); return; }
    i -= NW;
    if (i < NW) { do_splitpack_h(Wk, g_whp[2], g_whp[3], i); return; }
    i -= NW;
    if (i < NW) { do_splitpack_h(Wv, g_whp[4], g_whp[5], i); return; }
    i -= NW;
    if (i < NW) { do_splitpack_b(Wo, g_wop[0], g_wop[1], i); }
}

// ---------------- merged QKV: fp16 3-term split GEMM (one launch, 3 ops) ----------
// grid (12, 100): y<50 -> Q(m0=y), 50..74 -> K(m0=y-50, remap), 75..99 -> V(remap, bf16 out)
#define SMF (2*2*128*40*2 + 2*2*8*132*8)   // 74752
__global__ void __launch_bounds__(256) gemm_qkv(
    const float* __restrict__ bq, const float* __restrict__ bk,
    const float* __restrict__ bv)
{
    extern __shared__ char sm[];
    typedef __half ATile[2][128][40];
    typedef uint2 BTile[2][8][132];
    ATile* As = (ATile*)sm;
    BTile* Bs = (BTile*)(sm + 2 * 2 * 128 * 40 * 2);

    const int tid = threadIdx.x;
    const int warp = tid >> 5, lane = tid & 31;
    const int wm = warp >> 1, wn = warp & 1;
    const int group = lane >> 2, tig = lane & 3;

    const int by = blockIdx.y;
    const int op = (by < 50) ? 0 : ((by < 75) ? 1 : 2);
    const int myi = (op == 0) ? by : ((op == 1) ? by - 50 : by - 75);
    const int m0 = myi * 128, n0 = blockIdx.x * 128;

    const uint2* Bp[2];
    const float* bias;
    if (op == 0)      { Bp[0] = g_whp[0]; Bp[1] = g_whp[1]; bias = bq; }
    else if (op == 1) { Bp[0] = g_whp[2]; Bp[1] = g_whp[3]; bias = bk; }
    else              { Bp[0] = g_whp[4]; Bp[1] = g_whp[5]; bias = bv; }

    const int lrow = (lane & 7) + ((lane >> 3) & 1) * 8;
    const int lcol = (lane >> 4) * 8;

    const __half* Ap[2] = {g_xh[0], g_xh[1]};
    const int rA = tid >> 2;
    const int cA = (tid & 3) * 8;
    const int r8B = tid >> 5;
    const int cqB = lane * 2;

    int srcRow[2];
#pragma unroll
    for (int i = 0; i < 2; i++) {
        int o = m0 + rA + i * 64;
        srcRow[i] = (op == 0) ? o : kv_src_row(o);
    }

    auto issue = [&](int k0, int buf) {
        const int c = k0 >> 5;
#pragma unroll
        for (int p = 0; p < 2; p++) {
#pragma unroll
            for (int i = 0; i < 2; i++) {
                int r = rA + i * 64;
                cp16(&As[buf][p][r][cA], &Ap[p][(size_t)srcRow[i] * DIM + k0 + cA]);
            }
#pragma unroll
            for (int i = 0; i < 2; i++) {
                int cq = cqB + i * 64;
                cp16(&Bs[buf][p][r8B][cq],
                     &Bp[p][((size_t)c * 8 + r8B) * DIM + n0 + cq]);
            }
        }
    };

    float acc[2][8][4] = {};

    issue(0, 0);
    CP_COMMIT();
    int buf = 0;

    for (int k0 = 0; k0 < DIM; k0 += 32) {
        CP_WAIT0();
        __syncthreads();
        if (k0 + 32 < DIM) {
            issue(k0 + 32, buf ^ 1);
            CP_COMMIT();
        }

        unsigned a[2][2][2][4];
#pragma unroll
        for (int p = 0; p < 2; p++)
#pragma unroll
            for (int mt = 0; mt < 2; mt++)
#pragma unroll
                for (int kk2 = 0; kk2 < 2; kk2++)
                    ldsm_x4(a[p][mt][kk2],
                            &As[buf][p][wm * 32 + mt * 16 + lrow][kk2 * 16 + lcol]);

#pragma unroll
        for (int nt = 0; nt < 8; nt++) {
            const int n = wn * 64 + nt * 8 + group;
            float d0[2][4] = {};
            float d1[2][4] = {};
#pragma unroll
            for (int kk2 = 0; kk2 < 2; kk2++) {
                uint2 v0 = Bs[buf][0][kk2 * 4 + tig][n];
                uint2 v1 = Bs[buf][1][kk2 * 4 + tig][n];
#pragma unroll
                for (int mt = 0; mt < 2; mt++) {
                    mma_f16(d0[mt], a[0][mt][kk2], &v0.x);
                    mma_f16(d1[mt], a[0][mt][kk2], &v1.x);
                    mma_f16(d1[mt], a[1][mt][kk2], &v0.x);
                }
            }
#pragma unroll
            for (int mt = 0; mt < 2; mt++) {
                ffma2add(acc[mt][nt][0], acc[mt][nt][1],
                         d0[mt][0], d0[mt][1], d1[mt][0], d1[mt][1]);
                ffma2add(acc[mt][nt][2], acc[mt][nt][3],
                         d0[mt][2], d0[mt][3], d1[mt][2], d1[mt][3]);
            }
        }
        buf ^= 1;
    }

    float* C = (op == 0) ? g_qraw : g_kraw;
#pragma unroll
    for (int mt = 0; mt < 2; mt++) {
        const int row = m0 + wm * 32 + mt * 16 + group;
#pragma unroll
        for (int nt = 0; nt < 8; nt++) {
            const int col = n0 + wn * 64 + nt * 8 + tig * 2;
            float b0 = bias[col], b1 = bias[col + 1];
            if (op == 2) {
                *(__nv_bfloat162*)&g_vb[(size_t)row * DIM + col] =
                    __floats2bfloat162_rn(acc[mt][nt][0] + b0, acc[mt][nt][1] + b1);
                *(__nv_bfloat162*)&g_vb[(size_t)(row + 8) * DIM + col] =
                    __floats2bfloat162_rn(acc[mt][nt][2] + b0, acc[mt][nt][3] + b1);
            } else {
                C[(size_t)row * DIM + col]           = acc[mt][nt][0] + b0;
                C[(size_t)row * DIM + col + 1]       = acc[mt][nt][1] + b1;
                C[(size_t)(row + 8) * DIM + col]     = acc[mt][nt][2] + b0;
                C[(size_t)(row + 8) * DIM + col + 1] = acc[mt][nt][3] + b1;
            }
        }
    }
}

// ---------------- bf16 2-term GEMM for Wo ----------------
#define SMW (2*128*40*2 + 2*2*8*132*8)     // 54272
__global__ void __launch_bounds__(256) gemm_wo(
    const float* __restrict__ bias, float* __restrict__ C)
{
    extern __shared__ char sm[];
    typedef __nv_bfloat16 ATile[128][40];
    typedef uint2 BTile[2][8][132];
    ATile* As = (ATile*)sm;
    BTile* Bs = (BTile*)(sm + 2 * 128 * 40 * 2);

    const int tid = threadIdx.x;
    const int warp = tid >> 5, lane = tid & 31;
    const int wm = warp >> 1, wn = warp & 1;
    const int group = lane >> 2, tig = lane & 3;
    const int m0 = blockIdx.y * 128, n0 = blockIdx.x * 128;

    const int lrow = (lane & 7) + ((lane >> 3) & 1) * 8;
    const int lcol = (lane >> 4) * 8;

    const uint2* Bp[2] = {g_wop[0], g_wop[1]};
    const int rA = tid >> 2;
    const int cA = (tid & 3) * 8;
    const int r8B = tid >> 5;
    const int cqB = lane * 2;

    auto issue = [&](int k0, int buf) {
        const int c = k0 >> 5;
#pragma unroll
        for (int i = 0; i < 2; i++) {
            int r = rA + i * 64;
            cp16(&As[buf][r][cA], &g_aob[(size_t)(m0 + r) * DIM + k0 + cA]);
        }
#pragma unroll
        for (int p = 0; p < 2; p++)
#pragma unroll
            for (int i = 0; i < 2; i++) {
                int cq = cqB + i * 64;
                cp16(&Bs[buf][p][r8B][cq],
                     &Bp[p][((size_t)c * 8 + r8B) * DIM + n0 + cq]);
            }
    };

    float acc[2][8][4] = {};
    issue(0, 0);
    CP_COMMIT();
    int buf = 0;

    for (int k0 = 0; k0 < DIM; k0 += 32) {
        CP_WAIT0();
        __syncthreads();
        if (k0 + 32 < DIM) {
            issue(k0 + 32, buf ^ 1);
            CP_COMMIT();
        }

        unsigned a[2][2][4];
#pragma unroll
        for (int mt = 0; mt < 2; mt++)
#pragma unroll
            for (int kk2 = 0; kk2 < 2; kk2++)
                ldsm_x4(a[mt][kk2], &As[buf][wm * 32 + mt * 16 + lrow][kk2 * 16 + lcol]);

#pragma unroll
        for (int nt = 0; nt < 8; nt++) {
            const int n = wn * 64 + nt * 8 + group;
            float d[2][4] = {};
#pragma unroll
            for (int kk2 = 0; kk2 < 2; kk2++) {
                uint2 v0 = Bs[buf][0][kk2 * 4 + tig][n];
                uint2 v1 = Bs[buf][1][kk2 * 4 + tig][n];
#pragma unroll
                for (int mt = 0; mt < 2; mt++) {
                    mma_bf16(d[mt], a[mt][kk2], &v0.x);
                    mma_bf16(d[mt], a[mt][kk2], &v1.x);
                }
            }
#pragma unroll
            for (int mt = 0; mt < 2; mt++) {
                fadd2(acc[mt][nt][0], acc[mt][nt][1], d[mt][0], d[mt][1]);
                fadd2(acc[mt][nt][2], acc[mt][nt][3], d[mt][2], d[mt][3]);
            }
        }
        buf ^= 1;
    }

#pragma unroll
    for (int mt = 0; mt < 2; mt++) {
        const int row = m0 + wm * 32 + mt * 16 + group;
#pragma unroll
        for (int nt = 0; nt < 8; nt++) {
            const int col = n0 + wn * 64 + nt * 8 + tig * 2;
            float b0 = bias[col], b1 = bias[col + 1];
            C[(size_t)row * DIM + col]           = acc[mt][nt][0] + b0;
            C[(size_t)row * DIM + col + 1]       = acc[mt][nt][1] + b1;
            C[(size_t)(row + 8) * DIM + col]     = acc[mt][nt][2] + b0;
            C[(size_t)(row + 8) * DIM + col + 1] = acc[mt][nt][3] + b1;
        }
    }
}

// ---------------- merged RMSNorm/RoPE + V pack ----------------
__global__ void rmsvp_kernel(const float* __restrict__ gq, const float* __restrict__ gk,
                             const float* __restrict__ freqs)
{
    const int bx = blockIdx.x;
    const int tid = threadIdx.x;

    if (bx >= SL) {
        // V pack region
        int i = (bx - SL) * TPB + tid;
        if (i < (LK / 4) * DIM) {
            int rowblk = i / DIM, n = i - rowblk * DIM;
            int c64 = rowblk >> 4, r = rowblk & 15;
            int g = r >> 2, tig = r & 3;
            int kp0 = c64 * 32 + g * 8 + tig;
            int kp1 = kp0 + 4;
            __nv_bfloat162 a2 = __halves2bfloat162(g_vb[(size_t)(2 * kp0) * DIM + n],
                                                   g_vb[(size_t)(2 * kp0 + 1) * DIM + n]);
            __nv_bfloat162 b2 = __halves2bfloat162(g_vb[(size_t)(2 * kp1) * DIM + n],
                                                   g_vb[(size_t)(2 * kp1 + 1) * DIM + n]);
            g_vpk[i] = make_uint2(*(unsigned*)&a2, *(unsigned*)&b2);
        }
        return;
    }

    const int l = bx;
    const int fi = l >> 6;
    const int rem = l & 63;
    const bool keep = (fi & 1) == 0;
    const int kc = (fi >> 1) * 64 + rem;

    const float* qr = g_qraw + (size_t)l * DIM;
    const float* kr = g_kraw + (size_t)kc * DIM;

    float sq = 0.f, sk = 0.f;
    for (int i = tid; i < DIM; i += TPB) {
        float a = qr[i]; sq += a * a;
        if (keep) { float b = kr[i]; sk += b * b; }
    }
    __shared__ float rq[8], rk[8];
#pragma unroll
    for (int off = 16; off; off >>= 1) {
        sq += __shfl_xor_sync(0xffffffffu, sq, off);
        sk += __shfl_xor_sync(0xffffffffu, sk, off);
    }
    if ((tid & 31) == 0) { rq[tid >> 5] = sq; rk[tid >> 5] = sk; }
    __syncthreads();
    if (tid == 0) {
        float tq = 0.f, tk = 0.f;
        for (int i = 0; i < 8; i++) { tq += rq[i]; tk += rk[i]; }
        rq[0] = rsqrtf(tq / DIM + 1e-6f);
        rk[0] = rsqrtf(tk / DIM + 1e-6f);
    }
    __syncthreads();
    const float invq = rq[0], invk = rk[0];

    const int hi = rem >> 3, wi = rem & 7;

    for (int e = tid; e < NHD * 64; e += TPB) {
        const int n = e >> 6;
        const int p = e & 63;
        float ang;
        if (p < 22)      ang = freqs[fi * 64 + p];
        else if (p < 43) ang = freqs[hi * 64 + p];
        else             ang = freqs[wi * 64 + p];
        float s, c;
        sincosf(ang, &s, &c);
        const int j0 = n * HD + 2 * p;

        float q0 = qr[j0] * invq * gq[j0];
        float q1 = qr[j0 + 1] * invq * gq[j0 + 1];
        g_qb[(size_t)l * DIM + j0]     = __float2bfloat16(q0 * c - q1 * s);
        g_qb[(size_t)l * DIM + j0 + 1] = __float2bfloat16(q0 * s + q1 * c);

        if (keep) {
            float k0v = kr[j0] * invk * gk[j0];
            float k1v = kr[j0 + 1] * invk * gk[j0 + 1];
            g_kb[(size_t)kc * DIM + j0]     = __float2bfloat16(k0v * c - k1v * s);
            g_kb[(size_t)kc * DIM + j0 + 1] = __float2bfloat16(k0v * s + k1v * c);
        }
    }
}

// ---------------- scores via HMMA (ldmatrix frags) + fused softmax stats ----------
#define SMS (2 * 128 * 136 * 2)   // 69632
__global__ void __launch_bounds__(256) score_gemm_mma(void)
{
    extern __shared__ char sm[];
    typedef __nv_bfloat16 Row136[136];
    Row136* Qs = (Row136*)sm;
    Row136* Ks = (Row136*)(sm + 128 * 136 * 2);
    __shared__ float sm_m[128][2], sm_s[128][2];

    const int h = blockIdx.z;
    const int mb0 = blockIdx.y * 128, n0 = blockIdx.x * 128;
    const int tid = threadIdx.x;
    const int warp = tid >> 5, lane = tid & 31;
    const int wm = warp >> 1, wn = warp & 1;
    const int group = lane >> 2, tig = lane & 3;

    const int lrow = (lane & 7) + ((lane >> 3) & 1) * 8;
    const int lcol = (lane >> 4) * 8;
    const int brow = ((lane >> 4) << 3) + (lane & 7);
    const int bcol = ((lane >> 3) & 1) * 8;

    const __nv_bfloat16* Q  = g_qb + h * HD;
    const __nv_bfloat16* Kb = g_kb + h * HD;

#pragma unroll
    for (int i = 0; i < 8; i++) {
        int idx = tid + i * 256;
        int r = idx >> 4, c = (idx & 15) * 8;
        cp16(&Qs[r][c], &Q [(size_t)(mb0 + r) * DIM + c]);
        cp16(&Ks[r][c], &Kb[(size_t)(n0 + r) * DIM + c]);
    }
    CP_COMMIT();

    float acc[2][8][4] = {};

    CP_WAIT0();
    __syncthreads();

#pragma unroll
    for (int kk = 0; kk < HD; kk += 16) {
        unsigned a[2][4], b[8][2];
#pragma unroll
        for (int mt = 0; mt < 2; mt++)
            ldsm_x4(a[mt], &Qs[wm * 32 + mt * 16 + lrow][kk + lcol]);
#pragma unroll
        for (int ntp = 0; ntp < 4; ntp++) {
            unsigned r4[4];
            ldsm_x4(r4, &Ks[wn * 64 + ntp * 16 + brow][kk + bcol]);
            b[2 * ntp][0] = r4[0]; b[2 * ntp][1] = r4[1];
            b[2 * ntp + 1][0] = r4[2]; b[2 * ntp + 1][1] = r4[3];
        }
#pragma unroll
        for (int mt = 0; mt < 2; mt++)
#pragma unroll
            for (int nt = 0; nt < 8; nt++)
                mma_bf16(acc[mt][nt], a[mt], b[nt]);
    }

    __nv_bfloat16* S = g_sc + (size_t)h * SL * LK;
#pragma unroll
    for (int mt = 0; mt < 2; mt++) {
#pragma unroll
        for (int hh = 0; hh < 2; hh++) {
            const int rr = wm * 32 + mt * 16 + group + hh * 8;
            const int row = mb0 + rr;
            float xv[16];
            float mx = -1e30f;
#pragma unroll
            for (int nt = 0; nt < 8; nt++) {
                const int col = n0 + wn * 64 + nt * 8 + tig * 2;
                __nv_bfloat162 b2 = __floats2bfloat162_rn(acc[mt][nt][hh * 2],
                                                          acc[mt][nt][hh * 2 + 1]);
                *(__nv_bfloat162*)&S[(size_t)row * LK + col] = b2;
                float2 f = __bfloat1622float2(b2);
                xv[2 * nt]     = f.x * SM_SCALE;
                xv[2 * nt + 1] = f.y * SM_SCALE;
                mx = fmaxf(mx, fmaxf(xv[2 * nt], xv[2 * nt + 1]));
            }
            mx = fmaxf(mx, __shfl_xor_sync(0xffffffffu, mx, 1));
            mx = fmaxf(mx, __shfl_xor_sync(0xffffffffu, mx, 2));
            const float mxl = mx * LOG2E;
            float sum = 0.f;
#pragma unroll
            for (int c = 0; c < 16; c++)
                sum += ex2f(__fmaf_rn(xv[c], LOG2E, -mxl));
            sum += __shfl_xor_sync(0xffffffffu, sum, 1);
            sum += __shfl_xor_sync(0xffffffffu, sum, 2);
            if (tig == 0) { sm_m[rr][wn] = mx; sm_s[rr][wn] = sum; }
        }
    }
    __syncthreads();
    if (tid < 128) {
        float m0v = sm_m[tid][0], m1v = sm_m[tid][1];
        float M = fmaxf(m0v, m1v);
        float Sv = sm_s[tid][0] * ex2f((m0v - M) * LOG2E)
                 + sm_s[tid][1] * ex2f((m1v - M) * LOG2E);
        size_t base = ((size_t)h * SL + mb0 + tid) * NKB + blockIdx.x;
        g_pm[base] = M;
        g_ps[base] = Sv;
    }
}

// ---------------- combine partial stats -> per-row M*log2e, 1/Z ----------------
__global__ void combine_kernel(void)
{
    int idx = blockIdx.x * blockDim.x + threadIdx.x;
    if (idx >= NHD * SL) return;
    const float* pm = g_pm + (size_t)idx * NKB;
    const float* ps = g_ps + (size_t)idx * NKB;
    float M = -1e30f;
#pragma unroll
    for (int b = 0; b < NKB; b++) M = fmaxf(M, pm[b]);
    float Z = 0.f;
#pragma unroll
    for (int b = 0; b < NKB; b++) Z += ps[b] * ex2f((pm[b] - M) * LOG2E);
    g_M2[idx] = M * LOG2E;
    g_iz[idx] = 1.f / Z;
}

// ---------------- PV via HMMA; paired-V; ex2 probs; double-buffered ----------------
#define SMPV (2*128*72*2 + 2*16*132*8)   // 70656
__global__ void __launch_bounds__(256) pv_gemm_mma(void)
{
    extern __shared__ char sm[];
    typedef __nv_bfloat16 PRow[72];
    typedef uint2 VRow[132];
    PRow* Praw = (PRow*)sm;
    VRow* Vps  = (VRow*)(sm + 2 * 128 * 72 * 2);
    __shared__ float sMr[128], sZr[128];

    const int h = blockIdx.z;
    const int m0 = blockIdx.y * 128;
    const int tid = threadIdx.x;
    const int warp = tid >> 5, lane = tid & 31;
    const int group = lane >> 2, tig = lane & 3;

    const __nv_bfloat16* P = g_sc + (size_t)h * SL * LK;
    const uint2* Vg = g_vpk + h * HD;

    if (tid < 128) {
        int row = h * SL + m0 + tid;
        sMr[tid] = g_M2[row];
        sZr[tid] = g_iz[row];
    }

    auto issue = [&](int k0, int buf) {
        const int c64 = k0 >> 6;
#pragma unroll
        for (int i = 0; i < 4; i++) {
            int idx = tid + i * 256;
            int r = idx >> 3, c = (idx & 7) * 8;
            cp16(&Praw[buf * 128 + r][c], &P[(size_t)(m0 + r) * LK + k0 + c]);
        }
#pragma unroll
        for (int i = 0; i < 4; i++) {
            int idx = tid + i * 256;
            int rb = idx >> 6, cq = (idx & 63) * 2;
            cp16(&Vps[buf * 16 + rb][cq], &Vg[((size_t)c64 * 16 + rb) * DIM + cq]);
        }
    };

    issue(0, 0);
    CP_COMMIT();
    int buf = 0;

    __syncthreads();
    const int rloc = warp * 16 + group;
    const float M0 = sMr[rloc], iz0 = sZr[rloc];
    const float M1 = sMr[rloc + 8], iz1 = sZr[rloc + 8];

    float acc[16][4] = {};

    for (int k0 = 0; k0 < LK; k0 += 64) {
        CP_WAIT0();
        __syncthreads();
        if (k0 + 64 < LK) {
            issue(k0 + 64, buf ^ 1);
            CP_COMMIT();
        }

#pragma unroll
        for (int kk = 0; kk < 64; kk += 16) {
            const int g = kk >> 4;
            unsigned a[4];
            a[0] = exp_cvt(*(const unsigned*)&Praw[buf * 128 + rloc][kk + tig * 2], M0, iz0);
            a[1] = exp_cvt(*(const unsigned*)&Praw[buf * 128 + rloc + 8][kk + tig * 2], M1, iz1);
            a[2] = exp_cvt(*(const unsigned*)&Praw[buf * 128 + rloc][kk + 8 + tig * 2], M0, iz0);
            a[3] = exp_cvt(*(const unsigned*)&Praw[buf * 128 + rloc + 8][kk + 8 + tig * 2], M1, iz1);
#pragma unroll
            for (int nt = 0; nt < 16; nt++) {
                uint2 v = Vps[buf * 16 + g * 4 + tig][nt * 8 + group];
                mma_bf16(acc[nt], a, &v.x);
            }
        }
        buf ^= 1;
    }

    const int row = m0 + rloc;
#pragma unroll
    for (int nt = 0; nt < 16; nt++) {
        const int col = h * HD + nt * 8 + tig * 2;
        *(__nv_bfloat162*)&g_aob[(size_t)row * DIM + col] =
            __floats2bfloat162_rn(acc[nt][0], acc[nt][1]);
        *(__nv_bfloat162*)&g_aob[(size_t)(row + 8) * DIM + col] =
            __floats2bfloat162_rn(acc[nt][2], acc[nt][3]);
    }
}

// ---------------- launch ----------------
extern "C" void kernel_launch(void* const* d_in, const int* in_sizes, int n_in,
                              void* d_out, int out_size)
{
    const float* x     = (const float*)d_in[0];
    const float* freqs = (const float*)d_in[1];
    const float* Wq    = (const float*)d_in[2];
    const float* bq    = (const float*)d_in[3];
    const float* Wk    = (const float*)d_in[4];
    const float* bk    = (const float*)d_in[5];
    const float* Wv    = (const float*)d_in[6];
    const float* bv    = (const float*)d_in[7];
    const float* Wo    = (const float*)d_in[8];
    const float* bo    = (const float*)d_in[9];
    const float* gq    = (const float*)d_in[10];
    const float* gk    = (const float*)d_in[11];
    float* out = (float*)d_out;

    cudaFuncSetAttribute(gemm_qkv, cudaFuncAttributeMaxDynamicSharedMemorySize, SMF);
    cudaFuncSetAttribute(gemm_wo, cudaFuncAttributeMaxDynamicSharedMemorySize, SMW);
    cudaFuncSetAttribute(score_gemm_mma, cudaFuncAttributeMaxDynamicSharedMemorySize, SMS);
    cudaFuncSetAttribute(pv_gemm_mma, cudaFuncAttributeMaxDynamicSharedMemorySize, SMPV);

    dim3 blk(TPB);

    // prep: x split + 4 weight splits in one launch
    const int prep_total = NX + 4 * NW;
    prep_kernel<<<(prep_total + TPB - 1) / TPB, blk>>>(x, Wq, Wk, Wv, Wo);

    // merged QKV projections (one launch, 1200 CTAs)
    dim3 gQKV(DIM / 128, 100);
    gemm_qkv<<<gQKV, blk, SMF>>>(bq, bk, bv);

    // rmsrope + vpack merged
    const int vpk_blocks = ((LK / 4) * DIM + TPB - 1) / TPB;
    rmsvp_kernel<<<SL + vpk_blocks, blk>>>(gq, gk, freqs);

    dim3 gScore(LK / 128, SL / 128, NHD);     // (25, 50, 12)
    score_gemm_mma<<<gScore, blk, SMS>>>();

    combine_kernel<<<(NHD * SL + TPB - 1) / TPB, blk>>>();

    dim3 gPV(1, SL / 128, NHD);
    pv_gemm_mma<<<gPV, blk, SMPV>>>();

    dim3 gWo(DIM / 128, SL / 128);
    gemm_wo<<<gWo, blk, SMW>>>(bo, out);
}